// round 1
// baseline (speedup 1.0000x reference)
#include <cuda_runtime.h>

#define NMAX 100000
#define EMAX 800000

// -------- scratch (static __device__, no allocation) --------
__device__ float g_Q[NMAX * 128];
__device__ float g_K[NMAX * 128];
__device__ float g_V[NMAX * 128];
__device__ float g_O[NMAX * 128];   // unnormalized message accum
__device__ float g_Z[NMAX * 8];     // softmax denominators per head
__device__ int   g_perm[NMAX];
__device__ int   g_cnt[3];
__device__ int   g_cur[3];

// ---------------- init: zero accumulators ----------------
__global__ void k_init(int N) {
    int i = blockIdx.x * blockDim.x + threadIdx.x;
    int stride = gridDim.x * blockDim.x;
    int tot = N * 128;
    for (int j = i; j < tot; j += stride) g_O[j] = 0.f;
    for (int j = i; j < N * 8; j += stride) g_Z[j] = 0.f;
    if (i < 3) { g_cnt[i] = 0; g_cur[i] = 0; }
}

// ---------------- bin nodes by type ----------------
__global__ void k_count(const int* __restrict__ ntype, int N) {
    int n = blockIdx.x * blockDim.x + threadIdx.x;
    if (n < N) atomicAdd(&g_cnt[ntype[n]], 1);
}

__global__ void k_base() {
    int c0 = g_cnt[0], c1 = g_cnt[1];
    g_cur[0] = 0; g_cur[1] = c0; g_cur[2] = c0 + c1;
}

__global__ void k_scatter(const int* __restrict__ ntype, int N) {
    int n = blockIdx.x * blockDim.x + threadIdx.x;
    if (n < N) {
        int t = ntype[n];
        int pos = atomicAdd(&g_cur[t], 1);
        g_perm[pos] = n;
    }
}

// ---------------- per-type Q/K/V projection ----------------
// Block: 128 nodes (type-sorted via perm), 256 threads.
// smem: x tile [128][128] (64KB) + W tile [128][128] (64KB) + perm/type (1KB)
// Thread (ni=tid/32, oi=tid%32) computes 16 nodes x 4 outputs.
#define QKV_SMEM (128 * 128 * 2 * 4 + 128 * 8)

__global__ void __launch_bounds__(256) k_qkv(
    const float* __restrict__ x, const int* __restrict__ ntype,
    const float* __restrict__ Wq, const float* __restrict__ bq,
    const float* __restrict__ Wk, const float* __restrict__ bk,
    const float* __restrict__ Wv, const float* __restrict__ bv,
    int N)
{
    extern __shared__ float sh[];
    float* xs = sh;                 // 128*128
    float* Ws = sh + 16384;         // 128*128
    int*   sp = (int*)(sh + 32768); // 128 perm values
    int*   st = sp + 128;           // 128 types

    int tid = threadIdx.x;
    int start = blockIdx.x * 128;
    int count = N - start; if (count > 128) count = 128;

    if (tid < count) {
        int pn = g_perm[start + tid];
        sp[tid] = pn;
        st[tid] = ntype[pn];
    }
    __syncthreads();

    // load x tile (coalesced per row, float4)
    for (int i = tid; i < count * 32; i += 256) {
        int row = i >> 5, c = i & 31;
        float4 v = *(const float4*)(x + (size_t)sp[row] * 128 + c * 4);
        *(float4*)(xs + row * 128 + c * 4) = v;
    }

    int tmin = st[0];
    int tmax = st[count - 1];

    const float* Wm[3] = {Wq, Wk, Wv};
    const float* bm[3] = {bq, bk, bv};
    float*       Om[3] = {g_Q, g_K, g_V};

    int oi = tid & 31;
    int ni = tid >> 5;

    for (int t = tmin; t <= tmax; ++t) {
        for (int m = 0; m < 3; ++m) {
            __syncthreads();
            const float* W = Wm[m] + (size_t)t * 16384;
            for (int i = tid; i < 4096; i += 256)
                *(float4*)(Ws + i * 4) = *(const float4*)(W + i * 4);
            __syncthreads();

            float4 bias = *(const float4*)(bm[m] + t * 128 + oi * 4);
            float4 acc[16];
            #pragma unroll
            for (int j = 0; j < 16; ++j) acc[j] = bias;

            #pragma unroll 2
            for (int d = 0; d < 128; ++d) {
                float4 w4 = *(float4*)(Ws + d * 128 + oi * 4);
                #pragma unroll
                for (int j = 0; j < 16; ++j) {
                    float xv = xs[(ni * 16 + j) * 128 + d];
                    acc[j].x += xv * w4.x;
                    acc[j].y += xv * w4.y;
                    acc[j].z += xv * w4.z;
                    acc[j].w += xv * w4.w;
                }
            }

            #pragma unroll
            for (int j = 0; j < 16; ++j) {
                int n = ni * 16 + j;
                if (n < count && st[n] == t)
                    *(float4*)(Om[m] + (size_t)sp[n] * 128 + oi * 4) = acc[j];
            }
        }
    }
}

// ---------------- fused edge pass ----------------
// One warp per edge. score -> exp -> RED Z + RED.v4 message accumulation.
__global__ void __launch_bounds__(256) k_edge(
    const int* __restrict__ ei, const int* __restrict__ etype,
    const int* __restrict__ esign, const float* __restrict__ edist,
    const float* __restrict__ rq, const float* __restrict__ rk,
    const float* __restrict__ rv, const float* __restrict__ rb,
    const float* __restrict__ skf, const float* __restrict__ svf,
    const float* __restrict__ skn, const float* __restrict__ svn,
    const float* __restrict__ alphap, const float* __restrict__ taup,
    int E)
{
    __shared__ float s_rq[1024], s_rk[1024], s_rv[1024], s_rb[64];
    __shared__ float s_sk[384], s_sv[384];
    __shared__ float s_at[2];

    int tid = threadIdx.x;
    for (int i = tid; i < 1024; i += 256) {
        s_rq[i] = rq[i]; s_rk[i] = rk[i]; s_rv[i] = rv[i];
    }
    if (tid < 64) s_rb[tid] = rb[tid];
    if (tid < 256) { s_sk[tid] = skf[tid]; s_sv[tid] = svf[tid]; }
    if (tid < 128) { s_sk[256 + tid] = skn[tid]; s_sv[256 + tid] = svn[tid]; }
    if (tid == 0) { s_at[0] = alphap[0]; s_at[1] = taup[0]; }
    __syncthreads();

    float alpha = s_at[0];
    float itau  = 1.f / (s_at[1] + 1e-9f);

    int lane = tid & 31;
    int h = lane >> 2;
    int gw = (blockIdx.x * 256 + tid) >> 5;
    int nw = (gridDim.x * 256) >> 5;

    for (int e = gw; e < E; e += nw) {
        int src = 0, dst = 0, et = 0, sg = 0;
        float dist = 0.f;
        if (lane == 0) {
            src = ei[e]; dst = ei[E + e];
            et = etype[e]; sg = esign[e]; dist = edist[e];
        }
        src  = __shfl_sync(0xffffffffu, src, 0);
        dst  = __shfl_sync(0xffffffffu, dst, 0);
        et   = __shfl_sync(0xffffffffu, et, 0);
        sg   = __shfl_sync(0xffffffffu, sg, 0);
        dist = __shfl_sync(0xffffffffu, dist, 0);

        int sidx = (sg == -1) ? 0 : ((sg == 1) ? 1 : 2);

        float4 q = *(const float4*)(g_Q + (size_t)dst * 128 + lane * 4);
        float4 k = *(const float4*)(g_K + (size_t)src * 128 + lane * 4);
        float4 v = *(const float4*)(g_V + (size_t)src * 128 + lane * 4);

        float4 a4 = *(float4*)(s_rq + et * 128 + lane * 4);
        float4 b4 = *(float4*)(s_rk + et * 128 + lane * 4);
        float4 c4 = *(float4*)(s_rv + et * 128 + lane * 4);
        float4 sk = *(float4*)(s_sk + sidx * 128 + lane * 4);
        float4 sv = *(float4*)(s_sv + sidx * 128 + lane * 4);

        float p = (q.x * a4.x) * (k.x * b4.x * sk.x)
                + (q.y * a4.y) * (k.y * b4.y * sk.y)
                + (q.z * a4.z) * (k.z * b4.z * sk.z)
                + (q.w * a4.w) * (k.w * b4.w * sk.w);
        p += __shfl_xor_sync(0xffffffffu, p, 1);
        p += __shfl_xor_sync(0xffffffffu, p, 2);

        float phi = alpha * __expf(-dist * itau);
        float es = __expf(p * 0.25f + s_rb[et * 8 + h] + phi);

        if ((lane & 3) == 0) atomicAdd(g_Z + (size_t)dst * 8 + h, es);

        float mx = v.x * c4.x * sv.x * es;
        float my = v.y * c4.y * sv.y * es;
        float mz = v.z * c4.z * sv.z * es;
        float mw = v.w * c4.w * sv.w * es;

        float* op = g_O + (size_t)dst * 128 + lane * 4;
        asm volatile("red.global.add.v4.f32 [%0], {%1,%2,%3,%4};"
                     :: "l"(op), "f"(mx), "f"(my), "f"(mz), "f"(mw)
                     : "memory");
    }
}

// ---------------- normalize + gated residual + LayerNorm ----------------
// One warp per node.
__global__ void __launch_bounds__(256) k_node(
    const float* __restrict__ x, const int* __restrict__ ntype,
    const float* __restrict__ skip, const float* __restrict__ gamma,
    const float* __restrict__ beta, float* __restrict__ out, int N)
{
    int w = (blockIdx.x * blockDim.x + threadIdx.x) >> 5;
    int lane = threadIdx.x & 31;
    if (w >= N) return;

    int t = ntype[w];
    float a = 1.f / (1.f + __expf(-skip[t]));
    float b = 1.f - a;

    int h = lane >> 2;
    float z = g_Z[(size_t)w * 8 + h] + 1e-9f;
    float r = a / z;

    float4 o4 = *(float4*)(g_O + (size_t)w * 128 + lane * 4);
    float4 xi = *(const float4*)(x + (size_t)w * 128 + lane * 4);

    float4 xv;
    xv.x = o4.x * r + b * xi.x;
    xv.y = o4.y * r + b * xi.y;
    xv.z = o4.z * r + b * xi.z;
    xv.w = o4.w * r + b * xi.w;

    float s = xv.x + xv.y + xv.z + xv.w;
    #pragma unroll
    for (int o = 16; o; o >>= 1) s += __shfl_xor_sync(0xffffffffu, s, o);
    float mu = s * (1.f / 128.f);

    float dx0 = xv.x - mu, dx1 = xv.y - mu, dx2 = xv.z - mu, dx3 = xv.w - mu;
    float vs = dx0 * dx0 + dx1 * dx1 + dx2 * dx2 + dx3 * dx3;
    #pragma unroll
    for (int o = 16; o; o >>= 1) vs += __shfl_xor_sync(0xffffffffu, vs, o);
    float rs = rsqrtf(vs * (1.f / 128.f) + 1e-5f);

    float4 g4 = *(const float4*)(gamma + t * 128 + lane * 4);
    float4 be4 = *(const float4*)(beta + t * 128 + lane * 4);

    float4 y;
    y.x = dx0 * rs * g4.x + be4.x;
    y.y = dx1 * rs * g4.y + be4.y;
    y.z = dx2 * rs * g4.z + be4.z;
    y.w = dx3 * rs * g4.w + be4.w;

    *(float4*)(out + (size_t)w * 128 + lane * 4) = y;
}

// ---------------- launch ----------------
extern "C" void kernel_launch(void* const* d_in, const int* in_sizes, int n_in,
                              void* d_out, int out_size)
{
    const float* node_inp   = (const float*)d_in[0];
    const int*   node_type  = (const int*)d_in[1];
    const int*   edge_index = (const int*)d_in[2];
    const int*   edge_type  = (const int*)d_in[3];
    const int*   edge_sign  = (const int*)d_in[4];
    const float* edge_dist  = (const float*)d_in[5];
    const float* Wq = (const float*)d_in[6];
    const float* bq = (const float*)d_in[7];
    const float* Wk = (const float*)d_in[8];
    const float* bk = (const float*)d_in[9];
    const float* Wv = (const float*)d_in[10];
    const float* bv = (const float*)d_in[11];
    const float* rel_q   = (const float*)d_in[12];
    const float* rel_k   = (const float*)d_in[13];
    const float* rel_v   = (const float*)d_in[14];
    const float* rel_b   = (const float*)d_in[15];
    const float* skf     = (const float*)d_in[16];
    const float* svf     = (const float*)d_in[17];
    const float* skn     = (const float*)d_in[18];
    const float* svn     = (const float*)d_in[19];
    const float* d_alpha = (const float*)d_in[20];
    const float* d_tau   = (const float*)d_in[21];
    const float* skip    = (const float*)d_in[22];
    const float* ln_g    = (const float*)d_in[23];
    const float* ln_b    = (const float*)d_in[24];

    int N = in_sizes[1];
    int E = in_sizes[3];

    float* out = (float*)d_out;

    cudaFuncSetAttribute(k_qkv, cudaFuncAttributeMaxDynamicSharedMemorySize, QKV_SMEM);

    k_init<<<4096, 256>>>(N);

    int nb = (N + 255) / 256;
    k_count<<<nb, 256>>>(node_type, N);
    k_base<<<1, 1>>>();
    k_scatter<<<nb, 256>>>(node_type, N);

    int qb = (N + 127) / 128;
    k_qkv<<<qb, 256, QKV_SMEM>>>(node_inp, node_type, Wq, bq, Wk, bk, Wv, bv, N);

    k_edge<<<2368, 256>>>(edge_index, edge_type, edge_sign, edge_dist,
                          rel_q, rel_k, rel_v, rel_b,
                          skf, svf, skn, svn, d_alpha, d_tau, E);

    int ob = (N * 32 + 255) / 256;
    k_node<<<ob, 256>>>(node_inp, node_type, skip, ln_g, ln_b, out, N);
}

// round 3
// speedup vs baseline: 1.4550x; 1.4550x over previous
#include <cuda_runtime.h>
#include <cuda_bf16.h>
#include <cstdint>

#define NMAX 100000

// -------- scratch (static __device__, no allocation) --------
__device__ float g_Q[NMAX * 128];
__device__ float g_K[NMAX * 128];
__device__ float g_V[NMAX * 128];
__device__ float g_O[NMAX * 128];   // unnormalized message accum
__device__ float g_Z[NMAX * 8];     // softmax denominators per head
__device__ int   g_perm[NMAX];
__device__ int   g_cnt[3];
__device__ int   g_cur[3];
// pre-packed weights in mma.sync B-fragment order:
// [type][mat][hi/lo] -> uint4[(ktile*8+npair)*32+lane]  (32KB each)
__device__ __align__(16) uint4 g_Bpk[3][3][2][2048];

// ---------------- helpers ----------------
__device__ __forceinline__ uint32_t pack_bf16(float a, float b) {
    __nv_bfloat162 t = __floats2bfloat162_rn(a, b);
    return *(uint32_t*)&t;
}

__device__ __forceinline__ void mma16816(float* c,
    uint32_t a0, uint32_t a1, uint32_t a2, uint32_t a3,
    uint32_t b0, uint32_t b1)
{
    asm volatile(
        "mma.sync.aligned.m16n8k16.row.col.f32.bf16.bf16.f32 "
        "{%0,%1,%2,%3}, {%4,%5,%6,%7}, {%8,%9}, {%0,%1,%2,%3};"
        : "+f"(c[0]), "+f"(c[1]), "+f"(c[2]), "+f"(c[3])
        : "r"(a0), "r"(a1), "r"(a2), "r"(a3), "r"(b0), "r"(b1));
}

// ---------------- init: zero accumulators ----------------
__global__ void k_init(int N) {
    int i = blockIdx.x * blockDim.x + threadIdx.x;
    int stride = gridDim.x * blockDim.x;
    float4 z4 = make_float4(0.f, 0.f, 0.f, 0.f);
    int tot = N * 32;
    float4* O4 = (float4*)g_O;
    for (int j = i; j < tot; j += stride) O4[j] = z4;
    float4* Z4 = (float4*)g_Z;
    for (int j = i; j < N * 2; j += stride) Z4[j] = z4;
    if (i < 3) { g_cnt[i] = 0; g_cur[i] = 0; }
}

// ---------------- binning (block-aggregated atomics) ----------------
__global__ void k_count(const int* __restrict__ ntype, int N) {
    __shared__ int h[3];
    if (threadIdx.x < 3) h[threadIdx.x] = 0;
    __syncthreads();
    int n = blockIdx.x * blockDim.x + threadIdx.x;
    if (n < N) atomicAdd(&h[ntype[n]], 1);
    __syncthreads();
    if (threadIdx.x < 3 && h[threadIdx.x]) atomicAdd(&g_cnt[threadIdx.x], h[threadIdx.x]);
}

__global__ void k_base() {
    int c0 = g_cnt[0], c1 = g_cnt[1];
    g_cur[0] = 0; g_cur[1] = c0; g_cur[2] = c0 + c1;
}

__global__ void k_scatter(const int* __restrict__ ntype, int N) {
    __shared__ int h[3], base[3];
    if (threadIdx.x < 3) h[threadIdx.x] = 0;
    __syncthreads();
    int n = blockIdx.x * blockDim.x + threadIdx.x;
    int t = 0, r = 0;
    if (n < N) { t = ntype[n]; r = atomicAdd(&h[t], 1); }
    __syncthreads();
    if (threadIdx.x < 3 && h[threadIdx.x]) base[threadIdx.x] = atomicAdd(&g_cur[threadIdx.x], h[threadIdx.x]);
    __syncthreads();
    if (n < N) g_perm[base[t] + r] = n;
}

// ---------------- weight pre-pack into B-fragment order ----------------
// B frag for mma.m16n8k16 (k x n = W[d][o]):
//   b0,b1 = W[k0+{0,1}][n],  b2,b3 = W[k0+8+{0,1}][n]
//   k0 = ktile*16 + (lane%4)*2, n = ntile*8 + lane/4
// uint4 per (ktile, npair, lane): {nt0.b01, nt0.b23, nt1.b01, nt1.b23}
__global__ void k_wpack(const float* __restrict__ Wq, const float* __restrict__ Wk,
                        const float* __restrict__ Wv) {
    int gid = blockIdx.x * blockDim.x + threadIdx.x;
    if (gid >= 3 * 3 * 2048) return;
    int t = gid / 6144;
    int m = (gid % 6144) / 2048;
    int w = gid % 2048;
    int kt = w >> 8;
    int np = (w >> 5) & 7;
    int lane = w & 31;

    const float* W = (m == 0 ? Wq : (m == 1 ? Wk : Wv)) + (size_t)t * 16384;
    int k0 = kt * 16 + (lane & 3) * 2;
    int n0 = (2 * np) * 8 + (lane >> 2);

    uint4 hi, lo;
    uint32_t* hp = (uint32_t*)&hi;
    uint32_t* lp = (uint32_t*)&lo;
    #pragma unroll
    for (int j = 0; j < 2; ++j) {
        int n = n0 + j * 8;
        #pragma unroll
        for (int g = 0; g < 2; ++g) {
            float v0 = W[(k0 + g * 8) * 128 + n];
            float v1 = W[(k0 + g * 8 + 1) * 128 + n];
            float h0 = __bfloat162float(__float2bfloat16(v0));
            float h1 = __bfloat162float(__float2bfloat16(v1));
            hp[j * 2 + g] = pack_bf16(h0, h1);
            lp[j * 2 + g] = pack_bf16(v0 - h0, v1 - h1);
        }
    }
    g_Bpk[t][m][0][w] = hi;
    g_Bpk[t][m][1][w] = lo;
}

// ---------------- tensor-core QKV via mma.sync, bf16x3 emulated fp32 ----------------
// smem: A frags hi/lo (32KB each), B frags hi/lo (32KB each), meta.
// A frag layout: uint4[(ktile*8+mtile)*32+lane] = {a0,a1,a2,a3} regs.
#define SM_AHI 0
#define SM_ALO 32768
#define SM_BHI 65536
#define SM_BLO 98304
#define SM_META 131072
#define SM_TOTAL (131072 + 1024)

__global__ void __launch_bounds__(256) k_qkv_mma(
    const float* __restrict__ x, const int* __restrict__ ntype,
    const float* __restrict__ bq, const float* __restrict__ bk,
    const float* __restrict__ bv, int N)
{
    extern __shared__ __align__(16) unsigned char sm[];
    uint32_t* Ahi = (uint32_t*)(sm + SM_AHI);
    uint32_t* Alo = (uint32_t*)(sm + SM_ALO);
    uint4*    Bhi = (uint4*)(sm + SM_BHI);
    uint4*    Blo = (uint4*)(sm + SM_BLO);
    int* sp = (int*)(sm + SM_META);
    int* st = sp + 128;

    int tid = threadIdx.x;
    int wid = tid >> 5;
    int lane = tid & 31;

    int start = blockIdx.x * 128;
    int count = N - start; if (count > 128) count = 128;

    if (tid < count) {
        int pn = g_perm[start + tid];
        sp[tid] = pn;
        st[tid] = ntype[pn];
    }
    __syncthreads();

    // phase 1: gather x rows coalesced into scratch (B area, 64KB fp32)
    float* raw = (float*)(sm + SM_BHI);
    for (int i = tid; i < count * 32; i += 256) {
        int r = i >> 5, c = i & 31;
        *(float4*)(raw + r * 128 + c * 4) = *(const float4*)(x + (size_t)sp[r] * 128 + c * 4);
    }
    __syncthreads();

    // phase 2: split to bf16 hi/lo in A-fragment order
    // thread handles row r = tid/2, pair range [half*32, half*32+32)
    {
        int r = tid >> 1;
        int half = tid & 1;
        int mt = r >> 4, rr = r & 15;
        #pragma unroll 8
        for (int c = half * 32; c < half * 32 + 32; ++c) {
            float v0 = 0.f, v1 = 0.f;
            if (r < count) {
                v0 = raw[r * 128 + 2 * c];
                v1 = raw[r * 128 + 2 * c + 1];
            }
            float h0 = __bfloat162float(__float2bfloat16(v0));
            float h1 = __bfloat162float(__float2bfloat16(v1));
            int kt = c >> 3, cc = c & 7;
            int wl = (rr & 7) * 4 + (cc & 3);
            int slot = (rr >> 3) | ((cc >> 2) << 1);
            int idx = (((kt * 8 + mt) * 32 + wl) << 2) + slot;
            Ahi[idx] = pack_bf16(h0, h1);
            Alo[idx] = pack_bf16(v0 - h0, v1 - h1);
        }
    }
    // NOTE: raw (B area) gets overwritten below only after this sync
    __syncthreads();

    int tmin = st[0], tmax = st[count - 1];

    for (int t = tmin; t <= tmax; ++t) {
        for (int m = 0; m < 3; ++m) {
            __syncthreads();   // everyone done with previous B
            // copy pre-packed B frags (hi+lo, 32KB each), L2-resident
            {
                const uint4* srch = g_Bpk[t][m][0];
                const uint4* srcl = g_Bpk[t][m][1];
                #pragma unroll 4
                for (int i = tid; i < 2048; i += 256) {
                    Bhi[i] = srch[i];
                    Blo[i] = srcl[i];
                }
            }
            __syncthreads();

            float acc[16][4];
            #pragma unroll
            for (int i = 0; i < 16; ++i)
                #pragma unroll
                for (int j = 0; j < 4; ++j) acc[i][j] = 0.f;

            #pragma unroll
            for (int kt = 0; kt < 8; ++kt) {
                uint4 ah = *(uint4*)(Ahi + (((kt * 8 + wid) * 32 + lane) << 2));
                uint4 al = *(uint4*)(Alo + (((kt * 8 + wid) * 32 + lane) << 2));
                #pragma unroll
                for (int np = 0; np < 8; ++np) {
                    uint4 bh = Bhi[(kt * 8 + np) * 32 + lane];
                    uint4 bl = Blo[(kt * 8 + np) * 32 + lane];
                    mma16816(acc[2 * np],     ah.x, ah.y, ah.z, ah.w, bh.x, bh.y);
                    mma16816(acc[2 * np + 1], ah.x, ah.y, ah.z, ah.w, bh.z, bh.w);
                    mma16816(acc[2 * np],     al.x, al.y, al.z, al.w, bh.x, bh.y);
                    mma16816(acc[2 * np + 1], al.x, al.y, al.z, al.w, bh.z, bh.w);
                    mma16816(acc[2 * np],     ah.x, ah.y, ah.z, ah.w, bl.x, bl.y);
                    mma16816(acc[2 * np + 1], ah.x, ah.y, ah.z, ah.w, bl.z, bl.w);
                }
            }

            // epilogue: D frag -> gmem with bias
            const float* bias = (m == 0 ? bq : (m == 1 ? bk : bv)) + t * 128;
            float* dst = (m == 0 ? g_Q : (m == 1 ? g_K : g_V));
            int row0 = wid * 16 + (lane >> 2);
            int row1 = row0 + 8;
            bool v0ok = (row0 < count) && (st[row0] == t);
            bool v1ok = (row1 < count) && (st[row1] == t);
            float* d0 = v0ok ? (dst + (size_t)sp[row0] * 128) : nullptr;
            float* d1 = v1ok ? (dst + (size_t)sp[row1] * 128) : nullptr;
            int cbase = (lane & 3) * 2;
            #pragma unroll
            for (int nt = 0; nt < 16; ++nt) {
                int c = nt * 8 + cbase;
                float2 b2 = __ldg((const float2*)(bias + c));
                if (v0ok) {
                    float2 o; o.x = acc[nt][0] + b2.x; o.y = acc[nt][1] + b2.y;
                    *(float2*)(d0 + c) = o;
                }
                if (v1ok) {
                    float2 o; o.x = acc[nt][2] + b2.x; o.y = acc[nt][3] + b2.y;
                    *(float2*)(d1 + c) = o;
                }
            }
        }
    }
}

// ---------------- fused edge pass ----------------
__global__ void __launch_bounds__(256) k_edge(
    const int* __restrict__ ei, const int* __restrict__ etype,
    const int* __restrict__ esign, const float* __restrict__ edist,
    const float* __restrict__ rq, const float* __restrict__ rk,
    const float* __restrict__ rv, const float* __restrict__ rb,
    const float* __restrict__ skf, const float* __restrict__ svf,
    const float* __restrict__ skn, const float* __restrict__ svn,
    const float* __restrict__ alphap, const float* __restrict__ taup,
    int E)
{
    __shared__ float s_rq[1024], s_rk[1024], s_rv[1024], s_rb[64];
    __shared__ float s_sk[384], s_sv[384];
    __shared__ float s_at[2];

    int tid = threadIdx.x;
    for (int i = tid; i < 1024; i += 256) {
        s_rq[i] = rq[i]; s_rk[i] = rk[i]; s_rv[i] = rv[i];
    }
    if (tid < 64) s_rb[tid] = rb[tid];
    if (tid < 256) { s_sk[tid] = skf[tid]; s_sv[tid] = svf[tid]; }
    if (tid < 128) { s_sk[256 + tid] = skn[tid]; s_sv[256 + tid] = svn[tid]; }
    if (tid == 0) { s_at[0] = alphap[0]; s_at[1] = taup[0]; }
    __syncthreads();

    float alpha = s_at[0];
    float itau  = 1.f / (s_at[1] + 1e-9f);

    int lane = tid & 31;
    int h = lane >> 2;
    int gw = (blockIdx.x * 256 + tid) >> 5;
    int nw = (gridDim.x * 256) >> 5;

    for (int e = gw; e < E; e += nw) {
        int src = 0, dst = 0, et = 0, sg = 0;
        float dist = 0.f;
        if (lane == 0) {
            src = ei[e]; dst = ei[E + e];
            et = etype[e]; sg = esign[e]; dist = edist[e];
        }
        src  = __shfl_sync(0xffffffffu, src, 0);
        dst  = __shfl_sync(0xffffffffu, dst, 0);
        et   = __shfl_sync(0xffffffffu, et, 0);
        sg   = __shfl_sync(0xffffffffu, sg, 0);
        dist = __shfl_sync(0xffffffffu, dist, 0);

        int sidx = (sg == -1) ? 0 : ((sg == 1) ? 1 : 2);

        float4 q = *(const float4*)(g_Q + (size_t)dst * 128 + lane * 4);
        float4 k = *(const float4*)(g_K + (size_t)src * 128 + lane * 4);
        float4 v = *(const float4*)(g_V + (size_t)src * 128 + lane * 4);

        float4 a4 = *(float4*)(s_rq + et * 128 + lane * 4);
        float4 b4 = *(float4*)(s_rk + et * 128 + lane * 4);
        float4 c4 = *(float4*)(s_rv + et * 128 + lane * 4);
        float4 sk = *(float4*)(s_sk + sidx * 128 + lane * 4);
        float4 sv = *(float4*)(s_sv + sidx * 128 + lane * 4);

        float p = (q.x * a4.x) * (k.x * b4.x * sk.x)
                + (q.y * a4.y) * (k.y * b4.y * sk.y)
                + (q.z * a4.z) * (k.z * b4.z * sk.z)
                + (q.w * a4.w) * (k.w * b4.w * sk.w);
        p += __shfl_xor_sync(0xffffffffu, p, 1);
        p += __shfl_xor_sync(0xffffffffu, p, 2);

        float phi = alpha * __expf(-dist * itau);
        float es = __expf(p * 0.25f + s_rb[et * 8 + h] + phi);

        if ((lane & 3) == 0) atomicAdd(g_Z + (size_t)dst * 8 + h, es);

        float mx = v.x * c4.x * sv.x * es;
        float my = v.y * c4.y * sv.y * es;
        float mz = v.z * c4.z * sv.z * es;
        float mw = v.w * c4.w * sv.w * es;

        float* op = g_O + (size_t)dst * 128 + lane * 4;
        asm volatile("red.global.add.v4.f32 [%0], {%1,%2,%3,%4};"
                     :: "l"(op), "f"(mx), "f"(my), "f"(mz), "f"(mw)
                     : "memory");
    }
}

// ---------------- normalize + gated residual + LayerNorm ----------------
__global__ void __launch_bounds__(256) k_node(
    const float* __restrict__ x, const int* __restrict__ ntype,
    const float* __restrict__ skip, const float* __restrict__ gamma,
    const float* __restrict__ beta, float* __restrict__ out, int N)
{
    int w = (blockIdx.x * blockDim.x + threadIdx.x) >> 5;
    int lane = threadIdx.x & 31;
    if (w >= N) return;

    int t = ntype[w];
    float a = 1.f / (1.f + __expf(-skip[t]));
    float b = 1.f - a;

    int h = lane >> 2;
    float z = g_Z[(size_t)w * 8 + h] + 1e-9f;
    float r = a / z;

    float4 o4 = *(float4*)(g_O + (size_t)w * 128 + lane * 4);
    float4 xi = *(const float4*)(x + (size_t)w * 128 + lane * 4);

    float4 xv;
    xv.x = o4.x * r + b * xi.x;
    xv.y = o4.y * r + b * xi.y;
    xv.z = o4.z * r + b * xi.z;
    xv.w = o4.w * r + b * xi.w;

    float s = xv.x + xv.y + xv.z + xv.w;
    #pragma unroll
    for (int o = 16; o; o >>= 1) s += __shfl_xor_sync(0xffffffffu, s, o);
    float mu = s * (1.f / 128.f);

    float dx0 = xv.x - mu, dx1 = xv.y - mu, dx2 = xv.z - mu, dx3 = xv.w - mu;
    float vs = dx0 * dx0 + dx1 * dx1 + dx2 * dx2 + dx3 * dx3;
    #pragma unroll
    for (int o = 16; o; o >>= 1) vs += __shfl_xor_sync(0xffffffffu, vs, o);
    float rs = rsqrtf(vs * (1.f / 128.f) + 1e-5f);

    float4 g4 = *(const float4*)(gamma + t * 128 + lane * 4);
    float4 be4 = *(const float4*)(beta + t * 128 + lane * 4);

    float4 y;
    y.x = dx0 * rs * g4.x + be4.x;
    y.y = dx1 * rs * g4.y + be4.y;
    y.z = dx2 * rs * g4.z + be4.z;
    y.w = dx3 * rs * g4.w + be4.w;

    *(float4*)(out + (size_t)w * 128 + lane * 4) = y;
}

// ---------------- launch ----------------
extern "C" void kernel_launch(void* const* d_in, const int* in_sizes, int n_in,
                              void* d_out, int out_size)
{
    const float* node_inp   = (const float*)d_in[0];
    const int*   node_type  = (const int*)d_in[1];
    const int*   edge_index = (const int*)d_in[2];
    const int*   edge_type  = (const int*)d_in[3];
    const int*   edge_sign  = (const int*)d_in[4];
    const float* edge_dist  = (const float*)d_in[5];
    const float* Wq = (const float*)d_in[6];
    const float* bq = (const float*)d_in[7];
    const float* Wk = (const float*)d_in[8];
    const float* bk = (const float*)d_in[9];
    const float* Wv = (const float*)d_in[10];
    const float* bv = (const float*)d_in[11];
    const float* rel_q   = (const float*)d_in[12];
    const float* rel_k   = (const float*)d_in[13];
    const float* rel_v   = (const float*)d_in[14];
    const float* rel_b   = (const float*)d_in[15];
    const float* skf     = (const float*)d_in[16];
    const float* svf     = (const float*)d_in[17];
    const float* skn     = (const float*)d_in[18];
    const float* svn     = (const float*)d_in[19];
    const float* d_alpha = (const float*)d_in[20];
    const float* d_tau   = (const float*)d_in[21];
    const float* skip    = (const float*)d_in[22];
    const float* ln_g    = (const float*)d_in[23];
    const float* ln_b    = (const float*)d_in[24];

    int N = in_sizes[1];
    int E = in_sizes[3];

    float* out = (float*)d_out;

    cudaFuncSetAttribute(k_qkv_mma, cudaFuncAttributeMaxDynamicSharedMemorySize, SM_TOTAL);

    k_init<<<2048, 256>>>(N);

    int nb = (N + 255) / 256;
    k_count<<<nb, 256>>>(node_type, N);
    k_base<<<1, 1>>>();
    k_scatter<<<nb, 256>>>(node_type, N);

    k_wpack<<<72, 256>>>(Wq, Wk, Wv);

    int qb = (N + 127) / 128;
    k_qkv_mma<<<qb, 256, SM_TOTAL>>>(node_inp, node_type, bq, bk, bv, N);

    k_edge<<<2368, 256>>>(edge_index, edge_type, edge_sign, edge_dist,
                          rel_q, rel_k, rel_v, rel_b,
                          skf, svf, skn, svn, d_alpha, d_tau, E);

    int ob = (N * 32 + 255) / 256;
    k_node<<<ob, 256>>>(node_inp, node_type, skip, ln_g, ln_b, out, N);
}

// round 4
// speedup vs baseline: 1.4624x; 1.0051x over previous
#include <cuda_runtime.h>
#include <cuda_bf16.h>
#include <cstdint>

#define NMAX 100000
#define EMAX 800000

// -------- scratch (static __device__, no allocation) --------
__device__ float g_Q[NMAX * 128];
__device__ float g_K[NMAX * 128];
__device__ float g_V[NMAX * 128];
__device__ int   g_perm[NMAX];
__device__ int   g_cnt[3];
__device__ int   g_cur[3];
// CSR by destination
__device__ int   g_deg[NMAX];
__device__ int   g_off[NMAX];
__device__ int   g_cur2[NMAX];
__device__ int   g_bsum[128];
__device__ __align__(16) int4 g_epk[EMAX];   // {src, et, sidx, phi_bits}
// pre-packed weights in mma.sync B-fragment order
__device__ __align__(16) uint4 g_Bpk[3][3][2][2048];

// ---------------- helpers ----------------
__device__ __forceinline__ uint32_t pack_bf16(float a, float b) {
    __nv_bfloat162 t = __floats2bfloat162_rn(a, b);
    return *(uint32_t*)&t;
}

__device__ __forceinline__ void mma16816(float* c,
    uint32_t a0, uint32_t a1, uint32_t a2, uint32_t a3,
    uint32_t b0, uint32_t b1)
{
    asm volatile(
        "mma.sync.aligned.m16n8k16.row.col.f32.bf16.bf16.f32 "
        "{%0,%1,%2,%3}, {%4,%5,%6,%7}, {%8,%9}, {%0,%1,%2,%3};"
        : "+f"(c[0]), "+f"(c[1]), "+f"(c[2]), "+f"(c[3])
        : "r"(a0), "r"(a1), "r"(a2), "r"(a3), "r"(b0), "r"(b1));
}

// ---------------- init: zero degree histogram, counters ----------------
__global__ void k_init(int N) {
    int i = blockIdx.x * blockDim.x + threadIdx.x;
    if (i < N) g_deg[i] = 0;
    if (i < 3) { g_cnt[i] = 0; g_cur[i] = 0; }
}

// ---------------- binning by node type ----------------
__global__ void k_count(const int* __restrict__ ntype, int N) {
    __shared__ int h[3];
    if (threadIdx.x < 3) h[threadIdx.x] = 0;
    __syncthreads();
    int n = blockIdx.x * blockDim.x + threadIdx.x;
    if (n < N) atomicAdd(&h[ntype[n]], 1);
    __syncthreads();
    if (threadIdx.x < 3 && h[threadIdx.x]) atomicAdd(&g_cnt[threadIdx.x], h[threadIdx.x]);
}

__global__ void k_base() {
    int c0 = g_cnt[0], c1 = g_cnt[1];
    g_cur[0] = 0; g_cur[1] = c0; g_cur[2] = c0 + c1;
}

__global__ void k_scatter(const int* __restrict__ ntype, int N) {
    __shared__ int h[3], base[3];
    if (threadIdx.x < 3) h[threadIdx.x] = 0;
    __syncthreads();
    int n = blockIdx.x * blockDim.x + threadIdx.x;
    int t = 0, r = 0;
    if (n < N) { t = ntype[n]; r = atomicAdd(&h[t], 1); }
    __syncthreads();
    if (threadIdx.x < 3 && h[threadIdx.x]) base[threadIdx.x] = atomicAdd(&g_cur[threadIdx.x], h[threadIdx.x]);
    __syncthreads();
    if (n < N) g_perm[base[t] + r] = n;
}

// ---------------- CSR build: histogram, scan, scatter ----------------
__global__ void k_ecount(const int* __restrict__ ei, int E) {
    int e = blockIdx.x * blockDim.x + threadIdx.x;
    if (e < E) atomicAdd(&g_deg[ei[E + e]], 1);
}

__global__ void __launch_bounds__(256) k_scan1(int N) {
    __shared__ int sws[8];
    int tid = threadIdx.x;
    int idx = blockIdx.x * 1024 + tid * 4;
    int d0 = idx + 0 < N ? g_deg[idx + 0] : 0;
    int d1 = idx + 1 < N ? g_deg[idx + 1] : 0;
    int d2 = idx + 2 < N ? g_deg[idx + 2] : 0;
    int d3 = idx + 3 < N ? g_deg[idx + 3] : 0;
    int s = d0 + d1 + d2 + d3;
    int lane = tid & 31, w = tid >> 5;
    int inc = s;
    #pragma unroll
    for (int o = 1; o < 32; o <<= 1) {
        int t = __shfl_up_sync(0xffffffffu, inc, o);
        if (lane >= o) inc += t;
    }
    if (lane == 31) sws[w] = inc;
    __syncthreads();
    if (tid == 0) {
        int run = 0;
        #pragma unroll
        for (int i = 0; i < 8; ++i) { int t = sws[i]; sws[i] = run; run += t; }
        g_bsum[blockIdx.x] = run;
    }
    __syncthreads();
    int ex = inc - s + sws[w];
    if (idx + 0 < N) g_off[idx + 0] = ex;
    if (idx + 1 < N) g_off[idx + 1] = ex + d0;
    if (idx + 2 < N) g_off[idx + 2] = ex + d0 + d1;
    if (idx + 3 < N) g_off[idx + 3] = ex + d0 + d1 + d2;
}

__global__ void __launch_bounds__(128) k_scan2(int NBLK) {
    __shared__ int sws[4];
    int tid = threadIdx.x;
    int v = (tid < NBLK) ? g_bsum[tid] : 0;
    int lane = tid & 31, w = tid >> 5;
    int inc = v;
    #pragma unroll
    for (int o = 1; o < 32; o <<= 1) {
        int t = __shfl_up_sync(0xffffffffu, inc, o);
        if (lane >= o) inc += t;
    }
    if (lane == 31) sws[w] = inc;
    __syncthreads();
    if (tid == 0) {
        int run = 0;
        #pragma unroll
        for (int i = 0; i < 4; ++i) { int t = sws[i]; sws[i] = run; run += t; }
    }
    __syncthreads();
    if (tid < NBLK) g_bsum[tid] = inc - v + sws[w];
}

__global__ void k_scan3(int N) {
    int i = blockIdx.x * blockDim.x + threadIdx.x;
    if (i < N) {
        int o = g_off[i] + g_bsum[i >> 10];
        g_off[i] = o;
        g_cur2[i] = o;
    }
}

__global__ void k_escatter(const int* __restrict__ ei, const int* __restrict__ etype,
                           const int* __restrict__ esign, const float* __restrict__ edist,
                           const float* __restrict__ alphap, const float* __restrict__ taup,
                           int E)
{
    int e = blockIdx.x * blockDim.x + threadIdx.x;
    if (e >= E) return;
    int dst = ei[E + e];
    int src = ei[e];
    int et = etype[e];
    int sg = esign[e];
    int sidx = (sg == -1) ? 0 : ((sg == 1) ? 1 : 2);
    float alpha = __ldg(alphap);
    float itau = 1.f / (__ldg(taup) + 1e-9f);
    float phi = alpha * __expf(-edist[e] * itau);
    int pos = atomicAdd(&g_cur2[dst], 1);
    g_epk[pos] = make_int4(src, et, sidx, __float_as_int(phi));
}

// ---------------- weight pre-pack into B-fragment order ----------------
__global__ void k_wpack(const float* __restrict__ Wq, const float* __restrict__ Wk,
                        const float* __restrict__ Wv) {
    int gid = blockIdx.x * blockDim.x + threadIdx.x;
    if (gid >= 3 * 3 * 2048) return;
    int t = gid / 6144;
    int m = (gid % 6144) / 2048;
    int w = gid % 2048;
    int kt = w >> 8;
    int np = (w >> 5) & 7;
    int lane = w & 31;

    const float* W = (m == 0 ? Wq : (m == 1 ? Wk : Wv)) + (size_t)t * 16384;
    int k0 = kt * 16 + (lane & 3) * 2;
    int n0 = (2 * np) * 8 + (lane >> 2);

    uint4 hi, lo;
    uint32_t* hp = (uint32_t*)&hi;
    uint32_t* lp = (uint32_t*)&lo;
    #pragma unroll
    for (int j = 0; j < 2; ++j) {
        int n = n0 + j * 8;
        #pragma unroll
        for (int g = 0; g < 2; ++g) {
            float v0 = W[(k0 + g * 8) * 128 + n];
            float v1 = W[(k0 + g * 8 + 1) * 128 + n];
            float h0 = __bfloat162float(__float2bfloat16(v0));
            float h1 = __bfloat162float(__float2bfloat16(v1));
            hp[j * 2 + g] = pack_bf16(h0, h1);
            lp[j * 2 + g] = pack_bf16(v0 - h0, v1 - h1);
        }
    }
    g_Bpk[t][m][0][w] = hi;
    g_Bpk[t][m][1][w] = lo;
}

// ---------------- tensor-core QKV via mma.sync, bf16x3 emulated fp32 ----------------
#define SM_AHI 0
#define SM_ALO 32768
#define SM_BHI 65536
#define SM_BLO 98304
#define SM_META 131072
#define SM_TOTAL (131072 + 1024)

__global__ void __launch_bounds__(256) k_qkv_mma(
    const float* __restrict__ x, const int* __restrict__ ntype,
    const float* __restrict__ bq, const float* __restrict__ bk,
    const float* __restrict__ bv, int N)
{
    extern __shared__ __align__(16) unsigned char sm[];
    uint32_t* Ahi = (uint32_t*)(sm + SM_AHI);
    uint32_t* Alo = (uint32_t*)(sm + SM_ALO);
    uint4*    Bhi = (uint4*)(sm + SM_BHI);
    uint4*    Blo = (uint4*)(sm + SM_BLO);
    int* sp = (int*)(sm + SM_META);
    int* st = sp + 128;

    int tid = threadIdx.x;
    int wid = tid >> 5;
    int lane = tid & 31;

    int start = blockIdx.x * 128;
    int count = N - start; if (count > 128) count = 128;

    if (tid < count) {
        int pn = g_perm[start + tid];
        sp[tid] = pn;
        st[tid] = ntype[pn];
    }
    __syncthreads();

    float* raw = (float*)(sm + SM_BHI);
    for (int i = tid; i < count * 32; i += 256) {
        int r = i >> 5, c = i & 31;
        *(float4*)(raw + r * 128 + c * 4) = *(const float4*)(x + (size_t)sp[r] * 128 + c * 4);
    }
    __syncthreads();

    {
        int r = tid >> 1;
        int half = tid & 1;
        int mt = r >> 4, rr = r & 15;
        #pragma unroll 8
        for (int c = half * 32; c < half * 32 + 32; ++c) {
            float v0 = 0.f, v1 = 0.f;
            if (r < count) {
                v0 = raw[r * 128 + 2 * c];
                v1 = raw[r * 128 + 2 * c + 1];
            }
            float h0 = __bfloat162float(__float2bfloat16(v0));
            float h1 = __bfloat162float(__float2bfloat16(v1));
            int kt = c >> 3, cc = c & 7;
            int wl = (rr & 7) * 4 + (cc & 3);
            int slot = (rr >> 3) | ((cc >> 2) << 1);
            int idx = (((kt * 8 + mt) * 32 + wl) << 2) + slot;
            Ahi[idx] = pack_bf16(h0, h1);
            Alo[idx] = pack_bf16(v0 - h0, v1 - h1);
        }
    }
    __syncthreads();

    int tmin = st[0], tmax = st[count - 1];

    for (int t = tmin; t <= tmax; ++t) {
        for (int m = 0; m < 3; ++m) {
            __syncthreads();
            {
                const uint4* srch = g_Bpk[t][m][0];
                const uint4* srcl = g_Bpk[t][m][1];
                #pragma unroll 4
                for (int i = tid; i < 2048; i += 256) {
                    Bhi[i] = srch[i];
                    Blo[i] = srcl[i];
                }
            }
            __syncthreads();

            float acc[16][4];
            #pragma unroll
            for (int i = 0; i < 16; ++i)
                #pragma unroll
                for (int j = 0; j < 4; ++j) acc[i][j] = 0.f;

            #pragma unroll
            for (int kt = 0; kt < 8; ++kt) {
                uint4 ah = *(uint4*)(Ahi + (((kt * 8 + wid) * 32 + lane) << 2));
                uint4 al = *(uint4*)(Alo + (((kt * 8 + wid) * 32 + lane) << 2));
                #pragma unroll
                for (int np = 0; np < 8; ++np) {
                    uint4 bh = Bhi[(kt * 8 + np) * 32 + lane];
                    uint4 bl = Blo[(kt * 8 + np) * 32 + lane];
                    mma16816(acc[2 * np],     ah.x, ah.y, ah.z, ah.w, bh.x, bh.y);
                    mma16816(acc[2 * np + 1], ah.x, ah.y, ah.z, ah.w, bh.z, bh.w);
                    mma16816(acc[2 * np],     al.x, al.y, al.z, al.w, bh.x, bh.y);
                    mma16816(acc[2 * np + 1], al.x, al.y, al.z, al.w, bh.z, bh.w);
                    mma16816(acc[2 * np],     ah.x, ah.y, ah.z, ah.w, bl.x, bl.y);
                    mma16816(acc[2 * np + 1], ah.x, ah.y, ah.z, ah.w, bl.z, bl.w);
                }
            }

            const float* bias = (m == 0 ? bq : (m == 1 ? bk : bv)) + t * 128;
            float* dst = (m == 0 ? g_Q : (m == 1 ? g_K : g_V));
            int row0 = wid * 16 + (lane >> 2);
            int row1 = row0 + 8;
            bool v0ok = (row0 < count) && (st[row0] == t);
            bool v1ok = (row1 < count) && (st[row1] == t);
            float* d0 = v0ok ? (dst + (size_t)sp[row0] * 128) : nullptr;
            float* d1 = v1ok ? (dst + (size_t)sp[row1] * 128) : nullptr;
            int cbase = (lane & 3) * 2;
            #pragma unroll
            for (int nt = 0; nt < 16; ++nt) {
                int c = nt * 8 + cbase;
                float2 b2 = __ldg((const float2*)(bias + c));
                if (v0ok) {
                    float2 o; o.x = acc[nt][0] + b2.x; o.y = acc[nt][1] + b2.y;
                    *(float2*)(d0 + c) = o;
                }
                if (v1ok) {
                    float2 o; o.x = acc[nt][2] + b2.x; o.y = acc[nt][3] + b2.y;
                    *(float2*)(d1 + c) = o;
                }
            }
        }
    }
}

// ---------------- fused gather-attention + residual + LayerNorm ----------------
// One warp per destination node. CSR edges, register accumulation, no atomics.
__global__ void __launch_bounds__(512) k_attn(
    const float* __restrict__ x, const int* __restrict__ ntype,
    const float* __restrict__ rq, const float* __restrict__ rk,
    const float* __restrict__ rv, const float* __restrict__ rb,
    const float* __restrict__ skf, const float* __restrict__ svf,
    const float* __restrict__ skn, const float* __restrict__ svn,
    const float* __restrict__ skip, const float* __restrict__ gamma,
    const float* __restrict__ beta, float* __restrict__ out, int N)
{
    __shared__ __align__(16) float s_rqk[3072];   // [et*3+sidx][128]: rq*rk*sign_k
    __shared__ __align__(16) float s_rvv[3072];   // [et*3+sidx][128]: rv*sign_v
    __shared__ float s_rb[64];

    int tid = threadIdx.x;
    for (int i = tid; i < 3072; i += 512) {
        int c = i >> 7, d = i & 127;
        int et = c / 3, s = c - et * 3;
        float sk = (s < 2) ? skf[s * 128 + d] : skn[d];
        float sv = (s < 2) ? svf[s * 128 + d] : svn[d];
        float rqv = rq[et * 128 + d] * rk[et * 128 + d];
        s_rqk[i] = rqv * sk;
        s_rvv[i] = rv[et * 128 + d] * sv;
    }
    if (tid < 64) s_rb[tid] = rb[tid];
    __syncthreads();

    int wid = tid >> 5, lane = tid & 31;
    int n = blockIdx.x * 16 + wid;
    if (n >= N) return;
    int h = lane >> 2;

    float4 q4 = *(const float4*)(g_Q + (size_t)n * 128 + lane * 4);
    int start = g_off[n];
    int deg = g_deg[n];

    float4 oa = make_float4(0.f, 0.f, 0.f, 0.f);
    float z = 0.f;

    for (int j = 0; j < deg; ++j) {
        int4 p = g_epk[start + j];
        float4 k4 = *(const float4*)(g_K + (size_t)p.x * 128 + lane * 4);
        float4 v4 = *(const float4*)(g_V + (size_t)p.x * 128 + lane * 4);
        int cb = (p.y * 3 + p.z) * 128 + lane * 4;
        float4 rk4 = *(float4*)(s_rqk + cb);
        float4 rv4 = *(float4*)(s_rvv + cb);

        float sc = q4.x * k4.x * rk4.x + q4.y * k4.y * rk4.y
                 + q4.z * k4.z * rk4.z + q4.w * k4.w * rk4.w;
        sc += __shfl_xor_sync(0xffffffffu, sc, 1);
        sc += __shfl_xor_sync(0xffffffffu, sc, 2);

        float es = __expf(sc * 0.25f + s_rb[p.y * 8 + h] + __int_as_float(p.w));
        z += es;
        oa.x += v4.x * rv4.x * es;
        oa.y += v4.y * rv4.y * es;
        oa.z += v4.z * rv4.z * es;
        oa.w += v4.w * rv4.w * es;
    }

    // ---- gated residual + LayerNorm ----
    int t = ntype[n];
    float a = 1.f / (1.f + __expf(-__ldg(skip + t)));
    float b = 1.f - a;
    float r = a / (z + 1e-9f);

    float4 xi = *(const float4*)(x + (size_t)n * 128 + lane * 4);
    float4 xv;
    xv.x = oa.x * r + b * xi.x;
    xv.y = oa.y * r + b * xi.y;
    xv.z = oa.z * r + b * xi.z;
    xv.w = oa.w * r + b * xi.w;

    float s = xv.x + xv.y + xv.z + xv.w;
    #pragma unroll
    for (int o = 16; o; o >>= 1) s += __shfl_xor_sync(0xffffffffu, s, o);
    float mu = s * (1.f / 128.f);

    float dx0 = xv.x - mu, dx1 = xv.y - mu, dx2 = xv.z - mu, dx3 = xv.w - mu;
    float vs = dx0 * dx0 + dx1 * dx1 + dx2 * dx2 + dx3 * dx3;
    #pragma unroll
    for (int o = 16; o; o >>= 1) vs += __shfl_xor_sync(0xffffffffu, vs, o);
    float rs = rsqrtf(vs * (1.f / 128.f) + 1e-5f);

    float4 g4 = *(const float4*)(gamma + t * 128 + lane * 4);
    float4 be4 = *(const float4*)(beta + t * 128 + lane * 4);

    float4 y;
    y.x = dx0 * rs * g4.x + be4.x;
    y.y = dx1 * rs * g4.y + be4.y;
    y.z = dx2 * rs * g4.z + be4.z;
    y.w = dx3 * rs * g4.w + be4.w;

    *(float4*)(out + (size_t)n * 128 + lane * 4) = y;
}

// ---------------- launch ----------------
extern "C" void kernel_launch(void* const* d_in, const int* in_sizes, int n_in,
                              void* d_out, int out_size)
{
    const float* node_inp   = (const float*)d_in[0];
    const int*   node_type  = (const int*)d_in[1];
    const int*   edge_index = (const int*)d_in[2];
    const int*   edge_type  = (const int*)d_in[3];
    const int*   edge_sign  = (const int*)d_in[4];
    const float* edge_dist  = (const float*)d_in[5];
    const float* Wq = (const float*)d_in[6];
    const float* bq = (const float*)d_in[7];
    const float* Wk = (const float*)d_in[8];
    const float* bk = (const float*)d_in[9];
    const float* Wv = (const float*)d_in[10];
    const float* bv = (const float*)d_in[11];
    const float* rel_q   = (const float*)d_in[12];
    const float* rel_k   = (const float*)d_in[13];
    const float* rel_v   = (const float*)d_in[14];
    const float* rel_b   = (const float*)d_in[15];
    const float* skf     = (const float*)d_in[16];
    const float* svf     = (const float*)d_in[17];
    const float* skn     = (const float*)d_in[18];
    const float* svn     = (const float*)d_in[19];
    const float* d_alpha = (const float*)d_in[20];
    const float* d_tau   = (const float*)d_in[21];
    const float* skip    = (const float*)d_in[22];
    const float* ln_g    = (const float*)d_in[23];
    const float* ln_b    = (const float*)d_in[24];

    int N = in_sizes[1];
    int E = in_sizes[3];

    float* out = (float*)d_out;

    cudaFuncSetAttribute(k_qkv_mma, cudaFuncAttributeMaxDynamicSharedMemorySize, SM_TOTAL);

    int nb = (N + 255) / 256;
    int eb = (E + 255) / 256;
    int NBLK = (N + 1023) / 1024;

    k_init<<<nb, 256>>>(N);

    // node-type binning + CSR histogram
    k_count<<<nb, 256>>>(node_type, N);
    k_ecount<<<eb, 256>>>(edge_index, E);
    k_base<<<1, 1>>>();
    k_scatter<<<nb, 256>>>(node_type, N);

    // CSR scan + payload scatter
    k_scan1<<<NBLK, 256>>>(N);
    k_scan2<<<1, 128>>>(NBLK);
    k_scan3<<<nb, 256>>>(N);
    k_escatter<<<eb, 256>>>(edge_index, edge_type, edge_sign, edge_dist,
                            d_alpha, d_tau, E);

    // weight pack + QKV GEMMs
    k_wpack<<<72, 256>>>(Wq, Wk, Wv);
    int qb = (N + 127) / 128;
    k_qkv_mma<<<qb, 256, SM_TOTAL>>>(node_inp, node_type, bq, bk, bv, N);

    // fused attention + residual + LN
    int ab = (N + 15) / 16;
    k_attn<<<ab, 512>>>(node_inp, node_type, rel_q, rel_k, rel_v, rel_b,
                        skf, svf, skn, svn, skip, ln_g, ln_b, out, N);
}

// round 5
// speedup vs baseline: 1.8468x; 1.2628x over previous
#include <cuda_runtime.h>
#include <cuda_bf16.h>
#include <cuda_fp16.h>
#include <cstdint>

#define NMAX 100000
#define EMAX 800000

// -------- scratch (static __device__, no allocation) --------
__device__ float  g_Q[NMAX * 128];
__device__ __half g_Kh[NMAX * 128];
__device__ __half g_Vh[NMAX * 128];
__device__ int   g_perm[NMAX];
__device__ int   g_cnt[3];
__device__ int   g_cur[3];
// CSR by destination
__device__ int   g_deg[NMAX];
__device__ int   g_off[NMAX];
__device__ int   g_cur2[NMAX];
__device__ int   g_bsum[128];
__device__ __align__(16) int4 g_epk[EMAX];   // {src, et, sidx, phi_bits}
// pre-packed weights in mma.sync B-fragment order
__device__ __align__(16) uint4 g_Bpk[3][3][2][2048];
// precomputed rel/sign tables: [et*3+sidx][128]
__device__ __align__(16) float g_tqk[3072];
__device__ __align__(16) float g_tv[3072];

// ---------------- helpers ----------------
__device__ __forceinline__ uint32_t pack_bf16(float a, float b) {
    __nv_bfloat162 t = __floats2bfloat162_rn(a, b);
    return *(uint32_t*)&t;
}

__device__ __forceinline__ void mma16816(float* c,
    uint32_t a0, uint32_t a1, uint32_t a2, uint32_t a3,
    uint32_t b0, uint32_t b1)
{
    asm volatile(
        "mma.sync.aligned.m16n8k16.row.col.f32.bf16.bf16.f32 "
        "{%0,%1,%2,%3}, {%4,%5,%6,%7}, {%8,%9}, {%0,%1,%2,%3};"
        : "+f"(c[0]), "+f"(c[1]), "+f"(c[2]), "+f"(c[3])
        : "r"(a0), "r"(a1), "r"(a2), "r"(a3), "r"(b0), "r"(b1));
}

__device__ __forceinline__ float4 ldhalf4(const __half* p) {
    uint2 r = *(const uint2*)p;
    __half2 h01 = *(__half2*)&r.x;
    __half2 h23 = *(__half2*)&r.y;
    float2 f01 = __half22float2(h01);
    float2 f23 = __half22float2(h23);
    return make_float4(f01.x, f01.y, f23.x, f23.y);
}

// ---------------- init ----------------
__global__ void k_init(int N) {
    int i = blockIdx.x * blockDim.x + threadIdx.x;
    if (i < N) g_deg[i] = 0;
    if (i < 3) { g_cnt[i] = 0; g_cur[i] = 0; }
}

// ---------------- binning by node type ----------------
__global__ void k_count(const int* __restrict__ ntype, int N) {
    __shared__ int h[3];
    if (threadIdx.x < 3) h[threadIdx.x] = 0;
    __syncthreads();
    int n = blockIdx.x * blockDim.x + threadIdx.x;
    if (n < N) atomicAdd(&h[ntype[n]], 1);
    __syncthreads();
    if (threadIdx.x < 3 && h[threadIdx.x]) atomicAdd(&g_cnt[threadIdx.x], h[threadIdx.x]);
}

__global__ void k_base() {
    int c0 = g_cnt[0], c1 = g_cnt[1];
    g_cur[0] = 0; g_cur[1] = c0; g_cur[2] = c0 + c1;
}

__global__ void k_scatter(const int* __restrict__ ntype, int N) {
    __shared__ int h[3], base[3];
    if (threadIdx.x < 3) h[threadIdx.x] = 0;
    __syncthreads();
    int n = blockIdx.x * blockDim.x + threadIdx.x;
    int t = 0, r = 0;
    if (n < N) { t = ntype[n]; r = atomicAdd(&h[t], 1); }
    __syncthreads();
    if (threadIdx.x < 3 && h[threadIdx.x]) base[threadIdx.x] = atomicAdd(&g_cur[threadIdx.x], h[threadIdx.x]);
    __syncthreads();
    if (n < N) g_perm[base[t] + r] = n;
}

// ---------------- CSR build ----------------
__global__ void k_ecount(const int* __restrict__ ei, int E) {
    int e = blockIdx.x * blockDim.x + threadIdx.x;
    if (e < E) atomicAdd(&g_deg[ei[E + e]], 1);
}

__global__ void __launch_bounds__(256) k_scan1(int N) {
    __shared__ int sws[8];
    int tid = threadIdx.x;
    int idx = blockIdx.x * 1024 + tid * 4;
    int d0 = idx + 0 < N ? g_deg[idx + 0] : 0;
    int d1 = idx + 1 < N ? g_deg[idx + 1] : 0;
    int d2 = idx + 2 < N ? g_deg[idx + 2] : 0;
    int d3 = idx + 3 < N ? g_deg[idx + 3] : 0;
    int s = d0 + d1 + d2 + d3;
    int lane = tid & 31, w = tid >> 5;
    int inc = s;
    #pragma unroll
    for (int o = 1; o < 32; o <<= 1) {
        int t = __shfl_up_sync(0xffffffffu, inc, o);
        if (lane >= o) inc += t;
    }
    if (lane == 31) sws[w] = inc;
    __syncthreads();
    if (tid == 0) {
        int run = 0;
        #pragma unroll
        for (int i = 0; i < 8; ++i) { int t = sws[i]; sws[i] = run; run += t; }
        g_bsum[blockIdx.x] = run;
    }
    __syncthreads();
    int ex = inc - s + sws[w];
    if (idx + 0 < N) g_off[idx + 0] = ex;
    if (idx + 1 < N) g_off[idx + 1] = ex + d0;
    if (idx + 2 < N) g_off[idx + 2] = ex + d0 + d1;
    if (idx + 3 < N) g_off[idx + 3] = ex + d0 + d1 + d2;
}

__global__ void __launch_bounds__(128) k_scan2(int NBLK) {
    __shared__ int sws[4];
    int tid = threadIdx.x;
    int v = (tid < NBLK) ? g_bsum[tid] : 0;
    int lane = tid & 31, w = tid >> 5;
    int inc = v;
    #pragma unroll
    for (int o = 1; o < 32; o <<= 1) {
        int t = __shfl_up_sync(0xffffffffu, inc, o);
        if (lane >= o) inc += t;
    }
    if (lane == 31) sws[w] = inc;
    __syncthreads();
    if (tid == 0) {
        int run = 0;
        #pragma unroll
        for (int i = 0; i < 4; ++i) { int t = sws[i]; sws[i] = run; run += t; }
    }
    __syncthreads();
    if (tid < NBLK) g_bsum[tid] = inc - v + sws[w];
}

__global__ void k_scan3(int N) {
    int i = blockIdx.x * blockDim.x + threadIdx.x;
    if (i < N) {
        int o = g_off[i] + g_bsum[i >> 10];
        g_off[i] = o;
        g_cur2[i] = o;
    }
}

__global__ void k_escatter(const int* __restrict__ ei, const int* __restrict__ etype,
                           const int* __restrict__ esign, const float* __restrict__ edist,
                           const float* __restrict__ alphap, const float* __restrict__ taup,
                           int E)
{
    int e = blockIdx.x * blockDim.x + threadIdx.x;
    if (e >= E) return;
    int dst = ei[E + e];
    int src = ei[e];
    int et = etype[e];
    int sg = esign[e];
    int sidx = (sg == -1) ? 0 : ((sg == 1) ? 1 : 2);
    float alpha = __ldg(alphap);
    float itau = 1.f / (__ldg(taup) + 1e-9f);
    float phi = alpha * __expf(-edist[e] * itau);
    int pos = atomicAdd(&g_cur2[dst], 1);
    g_epk[pos] = make_int4(src, et, sidx, __float_as_int(phi));
}

// ---------------- rel/sign tables ----------------
__global__ void k_tab(const float* __restrict__ rq, const float* __restrict__ rk,
                      const float* __restrict__ rv,
                      const float* __restrict__ skf, const float* __restrict__ svf,
                      const float* __restrict__ skn, const float* __restrict__ svn)
{
    int i = blockIdx.x * blockDim.x + threadIdx.x;
    if (i >= 3072) return;
    int c = i >> 7, d = i & 127;
    int et = c / 3, s = c - et * 3;
    float sk = (s < 2) ? skf[s * 128 + d] : skn[d];
    float sv = (s < 2) ? svf[s * 128 + d] : svn[d];
    g_tqk[i] = rq[et * 128 + d] * rk[et * 128 + d] * sk;
    g_tv[i]  = rv[et * 128 + d] * sv;
}

// ---------------- weight pre-pack into B-fragment order ----------------
__global__ void k_wpack(const float* __restrict__ Wq, const float* __restrict__ Wk,
                        const float* __restrict__ Wv) {
    int gid = blockIdx.x * blockDim.x + threadIdx.x;
    if (gid >= 3 * 3 * 2048) return;
    int t = gid / 6144;
    int m = (gid % 6144) / 2048;
    int w = gid % 2048;
    int kt = w >> 8;
    int np = (w >> 5) & 7;
    int lane = w & 31;

    const float* W = (m == 0 ? Wq : (m == 1 ? Wk : Wv)) + (size_t)t * 16384;
    int k0 = kt * 16 + (lane & 3) * 2;
    int n0 = (2 * np) * 8 + (lane >> 2);

    uint4 hi, lo;
    uint32_t* hp = (uint32_t*)&hi;
    uint32_t* lp = (uint32_t*)&lo;
    #pragma unroll
    for (int j = 0; j < 2; ++j) {
        int n = n0 + j * 8;
        #pragma unroll
        for (int g = 0; g < 2; ++g) {
            float v0 = W[(k0 + g * 8) * 128 + n];
            float v1 = W[(k0 + g * 8 + 1) * 128 + n];
            float h0 = __bfloat162float(__float2bfloat16(v0));
            float h1 = __bfloat162float(__float2bfloat16(v1));
            hp[j * 2 + g] = pack_bf16(h0, h1);
            lp[j * 2 + g] = pack_bf16(v0 - h0, v1 - h1);
        }
    }
    g_Bpk[t][m][0][w] = hi;
    g_Bpk[t][m][1][w] = lo;
}

// ---------------- tensor-core QKV via mma.sync, bf16x3 emulated fp32 ----------------
#define SM_AHI 0
#define SM_ALO 32768
#define SM_BHI 65536
#define SM_BLO 98304
#define SM_META 131072
#define SM_TOTAL (131072 + 1024)

__global__ void __launch_bounds__(256) k_qkv_mma(
    const float* __restrict__ x, const int* __restrict__ ntype,
    const float* __restrict__ bq, const float* __restrict__ bk,
    const float* __restrict__ bv, int N)
{
    extern __shared__ __align__(16) unsigned char sm[];
    uint32_t* Ahi = (uint32_t*)(sm + SM_AHI);
    uint32_t* Alo = (uint32_t*)(sm + SM_ALO);
    uint4*    Bhi = (uint4*)(sm + SM_BHI);
    uint4*    Blo = (uint4*)(sm + SM_BLO);
    int* sp = (int*)(sm + SM_META);
    int* st = sp + 128;

    int tid = threadIdx.x;
    int wid = tid >> 5;
    int lane = tid & 31;

    int start = blockIdx.x * 128;
    int count = N - start; if (count > 128) count = 128;

    if (tid < count) {
        int pn = g_perm[start + tid];
        sp[tid] = pn;
        st[tid] = ntype[pn];
    }
    __syncthreads();

    float* raw = (float*)(sm + SM_BHI);
    for (int i = tid; i < count * 32; i += 256) {
        int r = i >> 5, c = i & 31;
        *(float4*)(raw + r * 128 + c * 4) = *(const float4*)(x + (size_t)sp[r] * 128 + c * 4);
    }
    __syncthreads();

    {
        int r = tid >> 1;
        int half = tid & 1;
        int mt = r >> 4, rr = r & 15;
        #pragma unroll 8
        for (int c = half * 32; c < half * 32 + 32; ++c) {
            float v0 = 0.f, v1 = 0.f;
            if (r < count) {
                v0 = raw[r * 128 + 2 * c];
                v1 = raw[r * 128 + 2 * c + 1];
            }
            float h0 = __bfloat162float(__float2bfloat16(v0));
            float h1 = __bfloat162float(__float2bfloat16(v1));
            int kt = c >> 3, cc = c & 7;
            int wl = (rr & 7) * 4 + (cc & 3);
            int slot = (rr >> 3) | ((cc >> 2) << 1);
            int idx = (((kt * 8 + mt) * 32 + wl) << 2) + slot;
            Ahi[idx] = pack_bf16(h0, h1);
            Alo[idx] = pack_bf16(v0 - h0, v1 - h1);
        }
    }
    __syncthreads();

    int tmin = st[0], tmax = st[count - 1];

    for (int t = tmin; t <= tmax; ++t) {
        for (int m = 0; m < 3; ++m) {
            __syncthreads();
            {
                const uint4* srch = g_Bpk[t][m][0];
                const uint4* srcl = g_Bpk[t][m][1];
                #pragma unroll 4
                for (int i = tid; i < 2048; i += 256) {
                    Bhi[i] = srch[i];
                    Blo[i] = srcl[i];
                }
            }
            __syncthreads();

            float acc[16][4];
            #pragma unroll
            for (int i = 0; i < 16; ++i)
                #pragma unroll
                for (int j = 0; j < 4; ++j) acc[i][j] = 0.f;

            #pragma unroll
            for (int kt = 0; kt < 8; ++kt) {
                uint4 ah = *(uint4*)(Ahi + (((kt * 8 + wid) * 32 + lane) << 2));
                uint4 al = *(uint4*)(Alo + (((kt * 8 + wid) * 32 + lane) << 2));
                #pragma unroll
                for (int np = 0; np < 8; ++np) {
                    uint4 bh = Bhi[(kt * 8 + np) * 32 + lane];
                    uint4 bl = Blo[(kt * 8 + np) * 32 + lane];
                    mma16816(acc[2 * np],     ah.x, ah.y, ah.z, ah.w, bh.x, bh.y);
                    mma16816(acc[2 * np + 1], ah.x, ah.y, ah.z, ah.w, bh.z, bh.w);
                    mma16816(acc[2 * np],     al.x, al.y, al.z, al.w, bh.x, bh.y);
                    mma16816(acc[2 * np + 1], al.x, al.y, al.z, al.w, bh.z, bh.w);
                    mma16816(acc[2 * np],     ah.x, ah.y, ah.z, ah.w, bl.x, bl.y);
                    mma16816(acc[2 * np + 1], ah.x, ah.y, ah.z, ah.w, bl.z, bl.w);
                }
            }

            const float* bias = (m == 0 ? bq : (m == 1 ? bk : bv)) + t * 128;
            int row0 = wid * 16 + (lane >> 2);
            int row1 = row0 + 8;
            bool v0ok = (row0 < count) && (st[row0] == t);
            bool v1ok = (row1 < count) && (st[row1] == t);
            int cbase = (lane & 3) * 2;

            if (m == 0) {
                float* d0 = v0ok ? (g_Q + (size_t)sp[row0] * 128) : nullptr;
                float* d1 = v1ok ? (g_Q + (size_t)sp[row1] * 128) : nullptr;
                #pragma unroll
                for (int nt = 0; nt < 16; ++nt) {
                    int c = nt * 8 + cbase;
                    float2 b2 = __ldg((const float2*)(bias + c));
                    if (v0ok) {
                        float2 o; o.x = acc[nt][0] + b2.x; o.y = acc[nt][1] + b2.y;
                        *(float2*)(d0 + c) = o;
                    }
                    if (v1ok) {
                        float2 o; o.x = acc[nt][2] + b2.x; o.y = acc[nt][3] + b2.y;
                        *(float2*)(d1 + c) = o;
                    }
                }
            } else {
                __half* base = (m == 1) ? g_Kh : g_Vh;
                __half* d0 = v0ok ? (base + (size_t)sp[row0] * 128) : nullptr;
                __half* d1 = v1ok ? (base + (size_t)sp[row1] * 128) : nullptr;
                #pragma unroll
                for (int nt = 0; nt < 16; ++nt) {
                    int c = nt * 8 + cbase;
                    float2 b2 = __ldg((const float2*)(bias + c));
                    if (v0ok)
                        *(__half2*)(d0 + c) = __floats2half2_rn(acc[nt][0] + b2.x, acc[nt][1] + b2.y);
                    if (v1ok)
                        *(__half2*)(d1 + c) = __floats2half2_rn(acc[nt][2] + b2.x, acc[nt][3] + b2.y);
                }
            }
        }
    }
}

// ---------------- fused gather-attention + residual + LayerNorm ----------------
// One warp per destination node, fp16 K/V, unroll-2 edge loop.
__global__ void __launch_bounds__(512) k_attn(
    const float* __restrict__ x, const int* __restrict__ ntype,
    const float* __restrict__ rbias,
    const float* __restrict__ skip, const float* __restrict__ gamma,
    const float* __restrict__ beta, float* __restrict__ out, int N)
{
    __shared__ __align__(16) float s_rqk[3072];
    __shared__ __align__(16) float s_rvv[3072];
    __shared__ float s_rb[64];

    int tid = threadIdx.x;
    {
        const uint4* sq = (const uint4*)g_tqk;
        const uint4* sv = (const uint4*)g_tv;
        uint4* dq = (uint4*)s_rqk;
        uint4* dv = (uint4*)s_rvv;
        #pragma unroll 2
        for (int i = tid; i < 768; i += 512) { dq[i] = sq[i]; dv[i] = sv[i]; }
    }
    if (tid < 64) s_rb[tid] = rbias[tid];
    __syncthreads();

    int wid = tid >> 5, lane = tid & 31;
    int n = blockIdx.x * 16 + wid;
    if (n >= N) return;
    int h = lane >> 2;

    float4 q4 = *(const float4*)(g_Q + (size_t)n * 128 + lane * 4);
    int start = g_off[n];
    int deg = g_deg[n];

    float4 oa = make_float4(0.f, 0.f, 0.f, 0.f);
    float z = 0.f;

    int j = 0;
    for (; j + 1 < deg; j += 2) {
        int4 pa = g_epk[start + j];
        int4 pb = g_epk[start + j + 1];
        float4 ka = ldhalf4(g_Kh + (size_t)pa.x * 128 + lane * 4);
        float4 kb = ldhalf4(g_Kh + (size_t)pb.x * 128 + lane * 4);
        float4 va = ldhalf4(g_Vh + (size_t)pa.x * 128 + lane * 4);
        float4 vb = ldhalf4(g_Vh + (size_t)pb.x * 128 + lane * 4);

        int cba = (pa.y * 3 + pa.z) * 128 + lane * 4;
        int cbb = (pb.y * 3 + pb.z) * 128 + lane * 4;
        float4 rka = *(float4*)(s_rqk + cba);
        float4 rkb = *(float4*)(s_rqk + cbb);
        float4 rva = *(float4*)(s_rvv + cba);
        float4 rvb = *(float4*)(s_rvv + cbb);

        float sa = q4.x * ka.x * rka.x + q4.y * ka.y * rka.y
                 + q4.z * ka.z * rka.z + q4.w * ka.w * rka.w;
        float sb = q4.x * kb.x * rkb.x + q4.y * kb.y * rkb.y
                 + q4.z * kb.z * rkb.z + q4.w * kb.w * rkb.w;
        sa += __shfl_xor_sync(0xffffffffu, sa, 1);
        sa += __shfl_xor_sync(0xffffffffu, sa, 2);
        sb += __shfl_xor_sync(0xffffffffu, sb, 1);
        sb += __shfl_xor_sync(0xffffffffu, sb, 2);

        float ea = __expf(sa * 0.25f + s_rb[pa.y * 8 + h] + __int_as_float(pa.w));
        float eb = __expf(sb * 0.25f + s_rb[pb.y * 8 + h] + __int_as_float(pb.w));
        z += ea + eb;
        oa.x += va.x * rva.x * ea + vb.x * rvb.x * eb;
        oa.y += va.y * rva.y * ea + vb.y * rvb.y * eb;
        oa.z += va.z * rva.z * ea + vb.z * rvb.z * eb;
        oa.w += va.w * rva.w * ea + vb.w * rvb.w * eb;
    }
    if (j < deg) {
        int4 p = g_epk[start + j];
        float4 k4 = ldhalf4(g_Kh + (size_t)p.x * 128 + lane * 4);
        float4 v4 = ldhalf4(g_Vh + (size_t)p.x * 128 + lane * 4);
        int cb = (p.y * 3 + p.z) * 128 + lane * 4;
        float4 rk4 = *(float4*)(s_rqk + cb);
        float4 rv4 = *(float4*)(s_rvv + cb);

        float sc = q4.x * k4.x * rk4.x + q4.y * k4.y * rk4.y
                 + q4.z * k4.z * rk4.z + q4.w * k4.w * rk4.w;
        sc += __shfl_xor_sync(0xffffffffu, sc, 1);
        sc += __shfl_xor_sync(0xffffffffu, sc, 2);

        float es = __expf(sc * 0.25f + s_rb[p.y * 8 + h] + __int_as_float(p.w));
        z += es;
        oa.x += v4.x * rv4.x * es;
        oa.y += v4.y * rv4.y * es;
        oa.z += v4.z * rv4.z * es;
        oa.w += v4.w * rv4.w * es;
    }

    // ---- gated residual + LayerNorm ----
    int t = ntype[n];
    float a = 1.f / (1.f + __expf(-__ldg(skip + t)));
    float b = 1.f - a;
    float r = a / (z + 1e-9f);

    float4 xi = *(const float4*)(x + (size_t)n * 128 + lane * 4);
    float4 xv;
    xv.x = oa.x * r + b * xi.x;
    xv.y = oa.y * r + b * xi.y;
    xv.z = oa.z * r + b * xi.z;
    xv.w = oa.w * r + b * xi.w;

    float s = xv.x + xv.y + xv.z + xv.w;
    #pragma unroll
    for (int o = 16; o; o >>= 1) s += __shfl_xor_sync(0xffffffffu, s, o);
    float mu = s * (1.f / 128.f);

    float dx0 = xv.x - mu, dx1 = xv.y - mu, dx2 = xv.z - mu, dx3 = xv.w - mu;
    float vs = dx0 * dx0 + dx1 * dx1 + dx2 * dx2 + dx3 * dx3;
    #pragma unroll
    for (int o = 16; o; o >>= 1) vs += __shfl_xor_sync(0xffffffffu, vs, o);
    float rs = rsqrtf(vs * (1.f / 128.f) + 1e-5f);

    float4 g4 = *(const float4*)(gamma + t * 128 + lane * 4);
    float4 be4 = *(const float4*)(beta + t * 128 + lane * 4);

    float4 y;
    y.x = dx0 * rs * g4.x + be4.x;
    y.y = dx1 * rs * g4.y + be4.y;
    y.z = dx2 * rs * g4.z + be4.z;
    y.w = dx3 * rs * g4.w + be4.w;

    *(float4*)(out + (size_t)n * 128 + lane * 4) = y;
}

// ---------------- launch ----------------
extern "C" void kernel_launch(void* const* d_in, const int* in_sizes, int n_in,
                              void* d_out, int out_size)
{
    const float* node_inp   = (const float*)d_in[0];
    const int*   node_type  = (const int*)d_in[1];
    const int*   edge_index = (const int*)d_in[2];
    const int*   edge_type  = (const int*)d_in[3];
    const int*   edge_sign  = (const int*)d_in[4];
    const float* edge_dist  = (const float*)d_in[5];
    const float* Wq = (const float*)d_in[6];
    const float* bq = (const float*)d_in[7];
    const float* Wk = (const float*)d_in[8];
    const float* bk = (const float*)d_in[9];
    const float* Wv = (const float*)d_in[10];
    const float* bv = (const float*)d_in[11];
    const float* rel_q   = (const float*)d_in[12];
    const float* rel_k   = (const float*)d_in[13];
    const float* rel_v   = (const float*)d_in[14];
    const float* rel_b   = (const float*)d_in[15];
    const float* skf     = (const float*)d_in[16];
    const float* svf     = (const float*)d_in[17];
    const float* skn     = (const float*)d_in[18];
    const float* svn     = (const float*)d_in[19];
    const float* d_alpha = (const float*)d_in[20];
    const float* d_tau   = (const float*)d_in[21];
    const float* skip    = (const float*)d_in[22];
    const float* ln_g    = (const float*)d_in[23];
    const float* ln_b    = (const float*)d_in[24];

    int N = in_sizes[1];
    int E = in_sizes[3];

    float* out = (float*)d_out;

    cudaFuncSetAttribute(k_qkv_mma, cudaFuncAttributeMaxDynamicSharedMemorySize, SM_TOTAL);

    int nb = (N + 255) / 256;
    int eb = (E + 255) / 256;
    int NBLK = (N + 1023) / 1024;

    k_init<<<nb, 256>>>(N);

    k_count<<<nb, 256>>>(node_type, N);
    k_ecount<<<eb, 256>>>(edge_index, E);
    k_base<<<1, 1>>>();
    k_scatter<<<nb, 256>>>(node_type, N);

    k_scan1<<<NBLK, 256>>>(N);
    k_scan2<<<1, 128>>>(NBLK);
    k_scan3<<<nb, 256>>>(N);
    k_escatter<<<eb, 256>>>(edge_index, edge_type, edge_sign, edge_dist,
                            d_alpha, d_tau, E);

    k_tab<<<12, 256>>>(rel_q, rel_k, rel_v, skf, svf, skn, svn);
    k_wpack<<<72, 256>>>(Wq, Wk, Wv);

    int qb = (N + 127) / 128;
    k_qkv_mma<<<qb, 256, SM_TOTAL>>>(node_inp, node_type, bq, bk, bv, N);

    int ab = (N + 15) / 16;
    k_attn<<<ab, 512>>>(node_inp, node_type, rel_b, skip, ln_g, ln_b, out, N);
}

// round 6
// speedup vs baseline: 2.3288x; 1.2610x over previous
#include <cuda_runtime.h>
#include <cuda_bf16.h>
#include <cuda_fp16.h>
#include <cstdint>

#define NMAX 100000
#define EMAX 800000

// -------- scratch (static __device__, no allocation) --------
__device__ float  g_Q[NMAX * 128];
__device__ __half g_Kh[NMAX * 128];
__device__ __half g_Vh[NMAX * 128];
__device__ int   g_perm[NMAX];
__device__ int   g_cnt[3];
__device__ int   g_cur[3];
// CSR by destination
__device__ int   g_deg[NMAX];
__device__ int   g_off[NMAX];
__device__ int   g_cur2[NMAX];
__device__ int   g_bsum[128];
__device__ __align__(16) int4 g_epk[EMAX];   // {src, et, sidx, phi_bits}
// pre-packed weights in mma.sync B-fragment order
__device__ __align__(16) uint4 g_Bpk[3][3][2][2048];
// precomputed rel/sign tables: [et*3+sidx][128]
__device__ __align__(16) float g_tqk[3072];
__device__ __align__(16) float g_tv[3072];

// ---------------- helpers ----------------
__device__ __forceinline__ uint32_t pack_bf16(float a, float b) {
    __nv_bfloat162 t = __floats2bfloat162_rn(a, b);
    return *(uint32_t*)&t;
}

__device__ __forceinline__ void mma16816(float* c,
    uint32_t a0, uint32_t a1, uint32_t a2, uint32_t a3,
    uint32_t b0, uint32_t b1)
{
    asm volatile(
        "mma.sync.aligned.m16n8k16.row.col.f32.bf16.bf16.f32 "
        "{%0,%1,%2,%3}, {%4,%5,%6,%7}, {%8,%9}, {%0,%1,%2,%3};"
        : "+f"(c[0]), "+f"(c[1]), "+f"(c[2]), "+f"(c[3])
        : "r"(a0), "r"(a1), "r"(a2), "r"(a3), "r"(b0), "r"(b1));
}

__device__ __forceinline__ float4 ldhalf4(const __half* p) {
    uint2 r = *(const uint2*)p;
    __half2 h01 = *(__half2*)&r.x;
    __half2 h23 = *(__half2*)&r.y;
    float2 f01 = __half22float2(h01);
    float2 f23 = __half22float2(h23);
    return make_float4(f01.x, f01.y, f23.x, f23.y);
}

__device__ __forceinline__ uint32_t s2u(const void* p) {
    uint32_t a;
    asm("{ .reg .u64 t; cvta.to.shared.u64 t, %1; cvt.u32.u64 %0, t; }" : "=r"(a) : "l"(p));
    return a;
}

__device__ __forceinline__ void cp16(uint32_t s, const void* g) {
    asm volatile("cp.async.cg.shared.global [%0], [%1], 16;" :: "r"(s), "l"(g));
}
__device__ __forceinline__ void cp_commit_wait() {
    asm volatile("cp.async.commit_group;");
    asm volatile("cp.async.wait_group 0;" ::: "memory");
}

// ---------------- K1: init ----------------
__global__ void k_init(int N) {
    int i = blockIdx.x * blockDim.x + threadIdx.x;
    if (i < N) g_deg[i] = 0;
    if (i < 3) { g_cnt[i] = 0; g_cur[i] = 0; }
}

// ---------------- K2: fused type-count + edge-degree histogram ----------------
__global__ void k_hist(const int* __restrict__ ntype, const int* __restrict__ ei,
                       int N, int E) {
    __shared__ int h[3];
    int tid = threadIdx.x;
    if (tid < 3) h[tid] = 0;
    __syncthreads();
    int i = blockIdx.x * blockDim.x + tid;
    if (i < N) atomicAdd(&h[ntype[i]], 1);
    if (i < E) atomicAdd(&g_deg[ei[E + i]], 1);
    __syncthreads();
    if (tid < 3 && h[tid]) atomicAdd(&g_cnt[tid], h[tid]);
}

// ---------------- K3: scan level 1 ----------------
__global__ void __launch_bounds__(256) k_scan1(int N) {
    __shared__ int sws[8];
    int tid = threadIdx.x;
    int idx = blockIdx.x * 1024 + tid * 4;
    int d0 = idx + 0 < N ? g_deg[idx + 0] : 0;
    int d1 = idx + 1 < N ? g_deg[idx + 1] : 0;
    int d2 = idx + 2 < N ? g_deg[idx + 2] : 0;
    int d3 = idx + 3 < N ? g_deg[idx + 3] : 0;
    int s = d0 + d1 + d2 + d3;
    int lane = tid & 31, w = tid >> 5;
    int inc = s;
    #pragma unroll
    for (int o = 1; o < 32; o <<= 1) {
        int t = __shfl_up_sync(0xffffffffu, inc, o);
        if (lane >= o) inc += t;
    }
    if (lane == 31) sws[w] = inc;
    __syncthreads();
    if (tid == 0) {
        int run = 0;
        #pragma unroll
        for (int i = 0; i < 8; ++i) { int t = sws[i]; sws[i] = run; run += t; }
        g_bsum[blockIdx.x] = run;
    }
    __syncthreads();
    int ex = inc - s + sws[w];
    if (idx + 0 < N) g_off[idx + 0] = ex;
    if (idx + 1 < N) g_off[idx + 1] = ex + d0;
    if (idx + 2 < N) g_off[idx + 2] = ex + d0 + d1;
    if (idx + 3 < N) g_off[idx + 3] = ex + d0 + d1 + d2;
}

// ---------------- K4: scan level 2 + type-base ----------------
__global__ void __launch_bounds__(128) k_scan2(int NBLK) {
    __shared__ int sws[4];
    int tid = threadIdx.x;
    int v = (tid < NBLK) ? g_bsum[tid] : 0;
    int lane = tid & 31, w = tid >> 5;
    int inc = v;
    #pragma unroll
    for (int o = 1; o < 32; o <<= 1) {
        int t = __shfl_up_sync(0xffffffffu, inc, o);
        if (lane >= o) inc += t;
    }
    if (lane == 31) sws[w] = inc;
    __syncthreads();
    if (tid == 0) {
        int run = 0;
        #pragma unroll
        for (int i = 0; i < 4; ++i) { int t = sws[i]; sws[i] = run; run += t; }
        int c0 = g_cnt[0], c1 = g_cnt[1];
        g_cur[0] = 0; g_cur[1] = c0; g_cur[2] = c0 + c1;
    }
    __syncthreads();
    if (tid < NBLK) g_bsum[tid] = inc - v + sws[w];
}

// ---------------- K5: scan finalize + type-scatter ----------------
__global__ void k_scan3(const int* __restrict__ ntype, int N) {
    __shared__ int h[3], base[3];
    int tid = threadIdx.x;
    if (tid < 3) h[tid] = 0;
    __syncthreads();
    int i = blockIdx.x * blockDim.x + tid;
    if (i < N) {
        int o = g_off[i] + g_bsum[i >> 10];
        g_off[i] = o;
        g_cur2[i] = o;
    }
    int t = 0, r = 0;
    if (i < N) { t = ntype[i]; r = atomicAdd(&h[t], 1); }
    __syncthreads();
    if (tid < 3 && h[tid]) base[tid] = atomicAdd(&g_cur[tid], h[tid]);
    __syncthreads();
    if (i < N) g_perm[base[t] + r] = i;
}

// ---------------- K6: edge payload scatter ----------------
__global__ void k_escatter(const int* __restrict__ ei, const int* __restrict__ etype,
                           const int* __restrict__ esign, const float* __restrict__ edist,
                           const float* __restrict__ alphap, const float* __restrict__ taup,
                           int E)
{
    int e = blockIdx.x * blockDim.x + threadIdx.x;
    if (e >= E) return;
    int dst = ei[E + e];
    int src = ei[e];
    int et = etype[e];
    int sg = esign[e];
    int sidx = (sg == -1) ? 0 : ((sg == 1) ? 1 : 2);
    float alpha = __ldg(alphap);
    float itau = 1.f / (__ldg(taup) + 1e-9f);
    float phi = alpha * __expf(-edist[e] * itau);
    int pos = atomicAdd(&g_cur2[dst], 1);
    g_epk[pos] = make_int4(src, et, sidx, __float_as_int(phi));
}

// ---------------- K7: weight pack + rel/sign tables (fused) ----------------
__global__ void k_wpack(const float* __restrict__ Wq, const float* __restrict__ Wk,
                        const float* __restrict__ Wv,
                        const float* __restrict__ rq, const float* __restrict__ rk,
                        const float* __restrict__ rv,
                        const float* __restrict__ skf, const float* __restrict__ svf,
                        const float* __restrict__ skn, const float* __restrict__ svn)
{
    int gid = blockIdx.x * blockDim.x + threadIdx.x;
    if (gid < 3072) {
        int c = gid >> 7, d = gid & 127;
        int et = c / 3, s = c - et * 3;
        float sk = (s < 2) ? skf[s * 128 + d] : skn[d];
        float sv = (s < 2) ? svf[s * 128 + d] : svn[d];
        g_tqk[gid] = rq[et * 128 + d] * rk[et * 128 + d] * sk;
        g_tv[gid]  = rv[et * 128 + d] * sv;
    }
    if (gid >= 3 * 3 * 2048) return;
    int t = gid / 6144;
    int m = (gid % 6144) / 2048;
    int w = gid % 2048;
    int kt = w >> 8;
    int np = (w >> 5) & 7;
    int lane = w & 31;

    const float* W = (m == 0 ? Wq : (m == 1 ? Wk : Wv)) + (size_t)t * 16384;
    int k0 = kt * 16 + (lane & 3) * 2;
    int n0 = (2 * np) * 8 + (lane >> 2);

    uint4 hi, lo;
    uint32_t* hp = (uint32_t*)&hi;
    uint32_t* lp = (uint32_t*)&lo;
    #pragma unroll
    for (int j = 0; j < 2; ++j) {
        int n = n0 + j * 8;
        #pragma unroll
        for (int g = 0; g < 2; ++g) {
            float v0 = W[(k0 + g * 8) * 128 + n];
            float v1 = W[(k0 + g * 8 + 1) * 128 + n];
            float h0 = __bfloat162float(__float2bfloat16(v0));
            float h1 = __bfloat162float(__float2bfloat16(v1));
            hp[j * 2 + g] = pack_bf16(h0, h1);
            lp[j * 2 + g] = pack_bf16(v0 - h0, v1 - h1);
        }
    }
    g_Bpk[t][m][0][w] = hi;
    g_Bpk[t][m][1][w] = lo;
}

// ---------------- K8: tensor-core QKV, two-pass B, 97KB smem (2 blocks/SM) ----
#define SM_AHI 0
#define SM_ALO 32768
#define SM_B   65536
#define SM_META 98304
#define SM_TOTAL (98304 + 1024)

__global__ void __launch_bounds__(256) k_qkv_mma(
    const float* __restrict__ x, const int* __restrict__ ntype,
    const float* __restrict__ bq, const float* __restrict__ bk,
    const float* __restrict__ bv, int N)
{
    extern __shared__ __align__(16) unsigned char sm[];
    uint32_t smb = s2u(sm);
    uint32_t* Ahi = (uint32_t*)(sm + SM_AHI);
    uint32_t* Alo = (uint32_t*)(sm + SM_ALO);
    uint4*    Bb  = (uint4*)(sm + SM_B);
    int* sp = (int*)(sm + SM_META);
    int* st = sp + 128;

    int tid = threadIdx.x;
    int wid = tid >> 5;
    int lane = tid & 31;

    int start = blockIdx.x * 128;
    int count = N - start; if (count > 128) count = 128;

    if (tid < count) {
        int pn = g_perm[start + tid];
        sp[tid] = pn;
        st[tid] = ntype[pn];
    }
    __syncthreads();

    // A pack: thread handles row r = tid/2, half = tid&1 (64 floats, contiguous 256B)
    {
        int r = tid >> 1;
        int half = tid & 1;
        int mt = r >> 4, rr = r & 15;
        float4 v[16];
        if (r < count) {
            const float4* xr = (const float4*)(x + (size_t)sp[r] * 128 + half * 64);
            #pragma unroll
            for (int i = 0; i < 16; ++i) v[i] = xr[i];
        } else {
            #pragma unroll
            for (int i = 0; i < 16; ++i) v[i] = make_float4(0.f, 0.f, 0.f, 0.f);
        }
        #pragma unroll
        for (int p = 0; p < 32; ++p) {
            int c = half * 32 + p;
            float v0 = (p & 1) ? v[p >> 1].z : v[p >> 1].x;
            float v1 = (p & 1) ? v[p >> 1].w : v[p >> 1].y;
            float h0 = __bfloat162float(__float2bfloat16(v0));
            float h1 = __bfloat162float(__float2bfloat16(v1));
            int kt = c >> 3, cc = c & 7;
            int wl = (rr & 7) * 4 + (cc & 3);
            int slot = (rr >> 3) | ((cc >> 2) << 1);
            int idx = (((kt * 8 + mt) * 32 + wl) << 2) + slot;
            Ahi[idx] = pack_bf16(h0, h1);
            Alo[idx] = pack_bf16(v0 - h0, v1 - h1);
        }
    }
    __syncthreads();

    int tmin = st[0], tmax = st[count - 1];

    for (int t = tmin; t <= tmax; ++t) {
        for (int m = 0; m < 3; ++m) {
            // ---- pass 1: B_hi ----
            {
                const uint4* srch = g_Bpk[t][m][0];
                #pragma unroll
                for (int i = tid; i < 2048; i += 256)
                    cp16(smb + SM_B + i * 16, srch + i);
                cp_commit_wait();
            }
            __syncthreads();

            float acc[16][4];
            #pragma unroll
            for (int i = 0; i < 16; ++i)
                #pragma unroll
                for (int j = 0; j < 4; ++j) acc[i][j] = 0.f;

            #pragma unroll
            for (int kt = 0; kt < 8; ++kt) {
                uint4 ah = *(uint4*)(Ahi + (((kt * 8 + wid) * 32 + lane) << 2));
                uint4 al = *(uint4*)(Alo + (((kt * 8 + wid) * 32 + lane) << 2));
                #pragma unroll
                for (int np = 0; np < 8; ++np) {
                    uint4 bh = Bb[(kt * 8 + np) * 32 + lane];
                    mma16816(acc[2 * np],     ah.x, ah.y, ah.z, ah.w, bh.x, bh.y);
                    mma16816(acc[2 * np + 1], ah.x, ah.y, ah.z, ah.w, bh.z, bh.w);
                    mma16816(acc[2 * np],     al.x, al.y, al.z, al.w, bh.x, bh.y);
                    mma16816(acc[2 * np + 1], al.x, al.y, al.z, al.w, bh.z, bh.w);
                }
            }
            __syncthreads();

            // ---- pass 2: B_lo ----
            {
                const uint4* srcl = g_Bpk[t][m][1];
                #pragma unroll
                for (int i = tid; i < 2048; i += 256)
                    cp16(smb + SM_B + i * 16, srcl + i);
                cp_commit_wait();
            }
            __syncthreads();

            #pragma unroll
            for (int kt = 0; kt < 8; ++kt) {
                uint4 ah = *(uint4*)(Ahi + (((kt * 8 + wid) * 32 + lane) << 2));
                #pragma unroll
                for (int np = 0; np < 8; ++np) {
                    uint4 bl = Bb[(kt * 8 + np) * 32 + lane];
                    mma16816(acc[2 * np],     ah.x, ah.y, ah.z, ah.w, bl.x, bl.y);
                    mma16816(acc[2 * np + 1], ah.x, ah.y, ah.z, ah.w, bl.z, bl.w);
                }
            }

            // ---- epilogue ----
            const float* bias = (m == 0 ? bq : (m == 1 ? bk : bv)) + t * 128;
            int row0 = wid * 16 + (lane >> 2);
            int row1 = row0 + 8;
            bool v0ok = (row0 < count) && (st[row0] == t);
            bool v1ok = (row1 < count) && (st[row1] == t);
            int cbase = (lane & 3) * 2;

            if (m == 0) {
                float* d0 = v0ok ? (g_Q + (size_t)sp[row0] * 128) : nullptr;
                float* d1 = v1ok ? (g_Q + (size_t)sp[row1] * 128) : nullptr;
                #pragma unroll
                for (int nt = 0; nt < 16; ++nt) {
                    int c = nt * 8 + cbase;
                    float2 b2 = __ldg((const float2*)(bias + c));
                    if (v0ok) {
                        float2 o; o.x = acc[nt][0] + b2.x; o.y = acc[nt][1] + b2.y;
                        *(float2*)(d0 + c) = o;
                    }
                    if (v1ok) {
                        float2 o; o.x = acc[nt][2] + b2.x; o.y = acc[nt][3] + b2.y;
                        *(float2*)(d1 + c) = o;
                    }
                }
            } else {
                __half* base = (m == 1) ? g_Kh : g_Vh;
                __half* d0 = v0ok ? (base + (size_t)sp[row0] * 128) : nullptr;
                __half* d1 = v1ok ? (base + (size_t)sp[row1] * 128) : nullptr;
                #pragma unroll
                for (int nt = 0; nt < 16; ++nt) {
                    int c = nt * 8 + cbase;
                    float2 b2 = __ldg((const float2*)(bias + c));
                    if (v0ok)
                        *(__half2*)(d0 + c) = __floats2half2_rn(acc[nt][0] + b2.x, acc[nt][1] + b2.y);
                    if (v1ok)
                        *(__half2*)(d1 + c) = __floats2half2_rn(acc[nt][2] + b2.x, acc[nt][3] + b2.y);
                }
            }
            __syncthreads();   // everyone done with B before next copy
        }
    }
}

// ---------------- K9: fused gather-attention + residual + LayerNorm ----------
__global__ void __launch_bounds__(512) k_attn(
    const float* __restrict__ x, const int* __restrict__ ntype,
    const float* __restrict__ rbias,
    const float* __restrict__ skip, const float* __restrict__ gamma,
    const float* __restrict__ beta, float* __restrict__ out, int N)
{
    __shared__ __align__(16) float s_rqk[3072];
    __shared__ __align__(16) float s_rvv[3072];
    __shared__ float s_rb[64];

    int tid = threadIdx.x;
    {
        const uint4* sq = (const uint4*)g_tqk;
        const uint4* sv = (const uint4*)g_tv;
        uint4* dq = (uint4*)s_rqk;
        uint4* dv = (uint4*)s_rvv;
        #pragma unroll 2
        for (int i = tid; i < 768; i += 512) { dq[i] = sq[i]; dv[i] = sv[i]; }
    }
    if (tid < 64) s_rb[tid] = rbias[tid];
    __syncthreads();

    int wid = tid >> 5, lane = tid & 31;
    int n = blockIdx.x * 16 + wid;
    if (n >= N) return;
    int h = lane >> 2;

    float4 q4 = *(const float4*)(g_Q + (size_t)n * 128 + lane * 4);
    int start = g_off[n];
    int deg = g_deg[n];

    float4 oa = make_float4(0.f, 0.f, 0.f, 0.f);
    float z = 0.f;

    int j = 0;
    for (; j + 1 < deg; j += 2) {
        int4 pa = g_epk[start + j];
        int4 pb = g_epk[start + j + 1];
        float4 ka = ldhalf4(g_Kh + (size_t)pa.x * 128 + lane * 4);
        float4 kb = ldhalf4(g_Kh + (size_t)pb.x * 128 + lane * 4);
        float4 va = ldhalf4(g_Vh + (size_t)pa.x * 128 + lane * 4);
        float4 vb = ldhalf4(g_Vh + (size_t)pb.x * 128 + lane * 4);

        int cba = (pa.y * 3 + pa.z) * 128 + lane * 4;
        int cbb = (pb.y * 3 + pb.z) * 128 + lane * 4;
        float4 rka = *(float4*)(s_rqk + cba);
        float4 rkb = *(float4*)(s_rqk + cbb);
        float4 rva = *(float4*)(s_rvv + cba);
        float4 rvb = *(float4*)(s_rvv + cbb);

        float sa = q4.x * ka.x * rka.x + q4.y * ka.y * rka.y
                 + q4.z * ka.z * rka.z + q4.w * ka.w * rka.w;
        float sb = q4.x * kb.x * rkb.x + q4.y * kb.y * rkb.y
                 + q4.z * kb.z * rkb.z + q4.w * kb.w * rkb.w;
        sa += __shfl_xor_sync(0xffffffffu, sa, 1);
        sa += __shfl_xor_sync(0xffffffffu, sa, 2);
        sb += __shfl_xor_sync(0xffffffffu, sb, 1);
        sb += __shfl_xor_sync(0xffffffffu, sb, 2);

        float ea = __expf(sa * 0.25f + s_rb[pa.y * 8 + h] + __int_as_float(pa.w));
        float eb = __expf(sb * 0.25f + s_rb[pb.y * 8 + h] + __int_as_float(pb.w));
        z += ea + eb;
        oa.x += va.x * rva.x * ea + vb.x * rvb.x * eb;
        oa.y += va.y * rva.y * ea + vb.y * rvb.y * eb;
        oa.z += va.z * rva.z * ea + vb.z * rvb.z * eb;
        oa.w += va.w * rva.w * ea + vb.w * rvb.w * eb;
    }
    if (j < deg) {
        int4 p = g_epk[start + j];
        float4 k4 = ldhalf4(g_Kh + (size_t)p.x * 128 + lane * 4);
        float4 v4 = ldhalf4(g_Vh + (size_t)p.x * 128 + lane * 4);
        int cb = (p.y * 3 + p.z) * 128 + lane * 4;
        float4 rk4 = *(float4*)(s_rqk + cb);
        float4 rv4 = *(float4*)(s_rvv + cb);

        float sc = q4.x * k4.x * rk4.x + q4.y * k4.y * rk4.y
                 + q4.z * k4.z * rk4.z + q4.w * k4.w * rk4.w;
        sc += __shfl_xor_sync(0xffffffffu, sc, 1);
        sc += __shfl_xor_sync(0xffffffffu, sc, 2);

        float es = __expf(sc * 0.25f + s_rb[p.y * 8 + h] + __int_as_float(p.w));
        z += es;
        oa.x += v4.x * rv4.x * es;
        oa.y += v4.y * rv4.y * es;
        oa.z += v4.z * rv4.z * es;
        oa.w += v4.w * rv4.w * es;
    }

    int t = ntype[n];
    float a = 1.f / (1.f + __expf(-__ldg(skip + t)));
    float b = 1.f - a;
    float r = a / (z + 1e-9f);

    float4 xi = *(const float4*)(x + (size_t)n * 128 + lane * 4);
    float4 xv;
    xv.x = oa.x * r + b * xi.x;
    xv.y = oa.y * r + b * xi.y;
    xv.z = oa.z * r + b * xi.z;
    xv.w = oa.w * r + b * xi.w;

    float s = xv.x + xv.y + xv.z + xv.w;
    #pragma unroll
    for (int o = 16; o; o >>= 1) s += __shfl_xor_sync(0xffffffffu, s, o);
    float mu = s * (1.f / 128.f);

    float dx0 = xv.x - mu, dx1 = xv.y - mu, dx2 = xv.z - mu, dx3 = xv.w - mu;
    float vs = dx0 * dx0 + dx1 * dx1 + dx2 * dx2 + dx3 * dx3;
    #pragma unroll
    for (int o = 16; o; o >>= 1) vs += __shfl_xor_sync(0xffffffffu, vs, o);
    float rs = rsqrtf(vs * (1.f / 128.f) + 1e-5f);

    float4 g4 = *(const float4*)(gamma + t * 128 + lane * 4);
    float4 be4 = *(const float4*)(beta + t * 128 + lane * 4);

    float4 y;
    y.x = dx0 * rs * g4.x + be4.x;
    y.y = dx1 * rs * g4.y + be4.y;
    y.z = dx2 * rs * g4.z + be4.z;
    y.w = dx3 * rs * g4.w + be4.w;

    *(float4*)(out + (size_t)n * 128 + lane * 4) = y;
}

// ---------------- launch ----------------
extern "C" void kernel_launch(void* const* d_in, const int* in_sizes, int n_in,
                              void* d_out, int out_size)
{
    const float* node_inp   = (const float*)d_in[0];
    const int*   node_type  = (const int*)d_in[1];
    const int*   edge_index = (const int*)d_in[2];
    const int*   edge_type  = (const int*)d_in[3];
    const int*   edge_sign  = (const int*)d_in[4];
    const float* edge_dist  = (const float*)d_in[5];
    const float* Wq = (const float*)d_in[6];
    const float* bq = (const float*)d_in[7];
    const float* Wk = (const float*)d_in[8];
    const float* bk = (const float*)d_in[9];
    const float* Wv = (const float*)d_in[10];
    const float* bv = (const float*)d_in[11];
    const float* rel_q   = (const float*)d_in[12];
    const float* rel_k   = (const float*)d_in[13];
    const float* rel_v   = (const float*)d_in[14];
    const float* rel_b   = (const float*)d_in[15];
    const float* skf     = (const float*)d_in[16];
    const float* svf     = (const float*)d_in[17];
    const float* skn     = (const float*)d_in[18];
    const float* svn     = (const float*)d_in[19];
    const float* d_alpha = (const float*)d_in[20];
    const float* d_tau   = (const float*)d_in[21];
    const float* skip    = (const float*)d_in[22];
    const float* ln_g    = (const float*)d_in[23];
    const float* ln_b    = (const float*)d_in[24];

    int N = in_sizes[1];
    int E = in_sizes[3];

    float* out = (float*)d_out;

    cudaFuncSetAttribute(k_qkv_mma, cudaFuncAttributeMaxDynamicSharedMemorySize, SM_TOTAL);

    int nb = (N + 255) / 256;
    int eb = (E + 255) / 256;
    int NBLK = (N + 1023) / 1024;

    k_init<<<nb, 256>>>(N);
    k_hist<<<eb, 256>>>(node_type, edge_index, N, E);
    k_scan1<<<NBLK, 256>>>(N);
    k_scan2<<<1, 128>>>(NBLK);
    k_scan3<<<nb, 256>>>(node_type, N);
    k_escatter<<<eb, 256>>>(edge_index, edge_type, edge_sign, edge_dist,
                            d_alpha, d_tau, E);

    k_wpack<<<72, 256>>>(Wq, Wk, Wv, rel_q, rel_k, rel_v, skf, svf, skn, svn);

    int qb = (N + 127) / 128;
    k_qkv_mma<<<qb, 256, SM_TOTAL>>>(node_inp, node_type, bq, bk, bv, N);

    int ab = (N + 15) / 16;
    k_attn<<<ab, 512>>>(node_inp, node_type, rel_b, skip, ln_g, ln_b, out, N);
}

// round 7
// speedup vs baseline: 2.5071x; 1.0766x over previous
#include <cuda_runtime.h>
#include <cuda_bf16.h>
#include <cuda_fp16.h>
#include <cstdint>

#define NMAX 100000
#define EMAX 800000

// -------- scratch (static __device__, no allocation) --------
__device__ float  g_Q[NMAX * 128];
__device__ __half g_KVh[NMAX * 256];   // interleaved: [k0..3 v0..3 k4..7 v4..7 ...]
__device__ int   g_perm[NMAX];
__device__ int   g_cnt[3];
__device__ int   g_cnt2[3];
__device__ int   g_total;
// CSR by destination
__device__ int   g_deg[NMAX];
__device__ int   g_off[NMAX];
__device__ int   g_cur2[NMAX];
__device__ __align__(16) int4 g_epk[EMAX];   // {src, et, sidx, phi_bits}
// pre-packed weights in mma.sync B-fragment order
__device__ __align__(16) uint4 g_Bpk[3][3][2][2048];
// precomputed rel/sign tables: [et*3+sidx][128]
__device__ __align__(16) float g_tqk[3072];
__device__ __align__(16) float g_tv[3072];

// ---------------- helpers ----------------
__device__ __forceinline__ uint32_t pack_bf16(float a, float b) {
    __nv_bfloat162 t = __floats2bfloat162_rn(a, b);
    return *(uint32_t*)&t;
}

__device__ __forceinline__ void mma16816(float* c,
    uint32_t a0, uint32_t a1, uint32_t a2, uint32_t a3,
    uint32_t b0, uint32_t b1)
{
    asm volatile(
        "mma.sync.aligned.m16n8k16.row.col.f32.bf16.bf16.f32 "
        "{%0,%1,%2,%3}, {%4,%5,%6,%7}, {%8,%9}, {%0,%1,%2,%3};"
        : "+f"(c[0]), "+f"(c[1]), "+f"(c[2]), "+f"(c[3])
        : "r"(a0), "r"(a1), "r"(a2), "r"(a3), "r"(b0), "r"(b1));
}

__device__ __forceinline__ uint32_t s2u(const void* p) {
    uint32_t a;
    asm("{ .reg .u64 t; cvta.to.shared.u64 t, %1; cvt.u32.u64 %0, t; }" : "=r"(a) : "l"(p));
    return a;
}

__device__ __forceinline__ void cp16(uint32_t s, const void* g) {
    asm volatile("cp.async.cg.shared.global [%0], [%1], 16;" :: "r"(s), "l"(g));
}
__device__ __forceinline__ void cp_commit_wait() {
    asm volatile("cp.async.commit_group;");
    asm volatile("cp.async.wait_group 0;" ::: "memory");
}

// ---------------- K1: init ----------------
__global__ void k_init(int N) {
    int i = blockIdx.x * blockDim.x + threadIdx.x;
    if (i < N) g_deg[i] = 0;
    if (i < 3) { g_cnt[i] = 0; g_cnt2[i] = 0; }
    if (i == 3) g_total = 0;
}

// ---------------- K2: fused type-count + edge-degree histogram ----------------
__global__ void k_hist(const int* __restrict__ ntype, const int* __restrict__ ei,
                       int N, int E) {
    __shared__ int h[3];
    int tid = threadIdx.x;
    if (tid < 3) h[tid] = 0;
    __syncthreads();
    int i = blockIdx.x * blockDim.x + tid;
    if (i < N) atomicAdd(&h[ntype[i]], 1);
    if (i < E) atomicAdd(&g_deg[ei[E + i]], 1);
    __syncthreads();
    if (tid < 3 && h[tid]) atomicAdd(&g_cnt[tid], h[tid]);
}

// ---------------- K3: CSR offsets (non-monotonic, block-atomic) + type-scatter --
__global__ void __launch_bounds__(256) k_off(const int* __restrict__ ntype, int N) {
    __shared__ int sws[8];
    __shared__ int sbase;
    __shared__ int h[3], tb[3];

    int tid = threadIdx.x;
    int lane = tid & 31, w = tid >> 5;
    int i = blockIdx.x * 256 + tid;
    int d = (i < N) ? g_deg[i] : 0;

    // block-wide inclusive scan of d
    int inc = d;
    #pragma unroll
    for (int o = 1; o < 32; o <<= 1) {
        int t = __shfl_up_sync(0xffffffffu, inc, o);
        if (lane >= o) inc += t;
    }
    if (lane == 31) sws[w] = inc;
    if (tid < 3) h[tid] = 0;
    __syncthreads();
    if (tid == 0) {
        int run = 0;
        #pragma unroll
        for (int k = 0; k < 8; ++k) { int t = sws[k]; sws[k] = run; run += t; }
        sbase = atomicAdd(&g_total, run);
    }
    __syncthreads();
    int ex = sbase + sws[w] + inc - d;
    if (i < N) { g_off[i] = ex; g_cur2[i] = ex; }

    // type scatter into perm
    int t = 0, r = 0;
    if (i < N) { t = ntype[i]; r = atomicAdd(&h[t], 1); }
    __syncthreads();
    if (tid < 3 && h[tid]) tb[tid] = atomicAdd(&g_cnt2[tid], h[tid]);
    __syncthreads();
    if (i < N) {
        int base = (t == 0) ? 0 : ((t == 1) ? g_cnt[0] : (g_cnt[0] + g_cnt[1]));
        g_perm[base + tb[t] + r] = i;
    }
}

// ---------------- K4: fused edge-payload scatter + weight pack + tables --------
__global__ void k_prep(const int* __restrict__ ei, const int* __restrict__ etype,
                       const int* __restrict__ esign, const float* __restrict__ edist,
                       const float* __restrict__ alphap, const float* __restrict__ taup,
                       const float* __restrict__ Wq, const float* __restrict__ Wk,
                       const float* __restrict__ Wv,
                       const float* __restrict__ rq, const float* __restrict__ rk,
                       const float* __restrict__ rv,
                       const float* __restrict__ skf, const float* __restrict__ svf,
                       const float* __restrict__ skn, const float* __restrict__ svn,
                       int E, int EB)
{
    if ((int)blockIdx.x < EB) {
        int e = blockIdx.x * blockDim.x + threadIdx.x;
        if (e >= E) return;
        int dst = ei[E + e];
        int src = ei[e];
        int et = etype[e];
        int sg = esign[e];
        int sidx = (sg == -1) ? 0 : ((sg == 1) ? 1 : 2);
        float alpha = __ldg(alphap);
        float itau = 1.f / (__ldg(taup) + 1e-9f);
        float phi = alpha * __expf(-edist[e] * itau);
        int pos = atomicAdd(&g_cur2[dst], 1);
        g_epk[pos] = make_int4(src, et, sidx, __float_as_int(phi));
        return;
    }

    int gid = (blockIdx.x - EB) * blockDim.x + threadIdx.x;
    if (gid < 3072) {
        int c = gid >> 7, d = gid & 127;
        int et = c / 3, s = c - et * 3;
        float sk = (s < 2) ? skf[s * 128 + d] : skn[d];
        float sv = (s < 2) ? svf[s * 128 + d] : svn[d];
        g_tqk[gid] = rq[et * 128 + d] * rk[et * 128 + d] * sk;
        g_tv[gid]  = rv[et * 128 + d] * sv;
    }
    if (gid >= 3 * 3 * 2048) return;
    int t = gid / 6144;
    int m = (gid % 6144) / 2048;
    int w = gid % 2048;
    int kt = w >> 8;
    int np = (w >> 5) & 7;
    int lane = w & 31;

    const float* W = (m == 0 ? Wq : (m == 1 ? Wk : Wv)) + (size_t)t * 16384;
    int k0 = kt * 16 + (lane & 3) * 2;
    int n0 = (2 * np) * 8 + (lane >> 2);

    uint4 hi, lo;
    uint32_t* hp = (uint32_t*)&hi;
    uint32_t* lp = (uint32_t*)&lo;
    #pragma unroll
    for (int j = 0; j < 2; ++j) {
        int n = n0 + j * 8;
        #pragma unroll
        for (int g = 0; g < 2; ++g) {
            float v0 = W[(k0 + g * 8) * 128 + n];
            float v1 = W[(k0 + g * 8 + 1) * 128 + n];
            float h0 = __bfloat162float(__float2bfloat16(v0));
            float h1 = __bfloat162float(__float2bfloat16(v1));
            hp[j * 2 + g] = pack_bf16(h0, h1);
            lp[j * 2 + g] = pack_bf16(v0 - h0, v1 - h1);
        }
    }
    g_Bpk[t][m][0][w] = hi;
    g_Bpk[t][m][1][w] = lo;
}

// ---------------- K5: tensor-core QKV, two-pass B, 97KB smem (2 blocks/SM) ----
#define SM_AHI 0
#define SM_ALO 32768
#define SM_B   65536
#define SM_META 98304
#define SM_TOTAL (98304 + 1024)

__global__ void __launch_bounds__(256) k_qkv_mma(
    const float* __restrict__ x, const int* __restrict__ ntype,
    const float* __restrict__ bq, const float* __restrict__ bk,
    const float* __restrict__ bv, int N)
{
    extern __shared__ __align__(16) unsigned char sm[];
    uint32_t smb = s2u(sm);
    uint32_t* Ahi = (uint32_t*)(sm + SM_AHI);
    uint32_t* Alo = (uint32_t*)(sm + SM_ALO);
    uint4*    Bb  = (uint4*)(sm + SM_B);
    int* sp = (int*)(sm + SM_META);
    int* st = sp + 128;

    int tid = threadIdx.x;
    int wid = tid >> 5;
    int lane = tid & 31;

    int start = blockIdx.x * 128;
    int count = N - start; if (count > 128) count = 128;

    if (tid < count) {
        int pn = g_perm[start + tid];
        sp[tid] = pn;
        st[tid] = ntype[pn];
    }
    __syncthreads();

    // A pack: thread handles row r = tid/2, half = tid&1 (64 floats, contiguous 256B)
    {
        int r = tid >> 1;
        int half = tid & 1;
        int mt = r >> 4, rr = r & 15;
        float4 v[16];
        if (r < count) {
            const float4* xr = (const float4*)(x + (size_t)sp[r] * 128 + half * 64);
            #pragma unroll
            for (int i = 0; i < 16; ++i) v[i] = xr[i];
        } else {
            #pragma unroll
            for (int i = 0; i < 16; ++i) v[i] = make_float4(0.f, 0.f, 0.f, 0.f);
        }
        #pragma unroll
        for (int p = 0; p < 32; ++p) {
            int c = half * 32 + p;
            float v0 = (p & 1) ? v[p >> 1].z : v[p >> 1].x;
            float v1 = (p & 1) ? v[p >> 1].w : v[p >> 1].y;
            float h0 = __bfloat162float(__float2bfloat16(v0));
            float h1 = __bfloat162float(__float2bfloat16(v1));
            int kt = c >> 3, cc = c & 7;
            int wl = (rr & 7) * 4 + (cc & 3);
            int slot = (rr >> 3) | ((cc >> 2) << 1);
            int idx = (((kt * 8 + mt) * 32 + wl) << 2) + slot;
            Ahi[idx] = pack_bf16(h0, h1);
            Alo[idx] = pack_bf16(v0 - h0, v1 - h1);
        }
    }
    __syncthreads();

    int tmin = st[0], tmax = st[count - 1];

    for (int t = tmin; t <= tmax; ++t) {
        for (int m = 0; m < 3; ++m) {
            // ---- pass 1: B_hi ----
            {
                const uint4* srch = g_Bpk[t][m][0];
                #pragma unroll
                for (int i = tid; i < 2048; i += 256)
                    cp16(smb + SM_B + i * 16, srch + i);
                cp_commit_wait();
            }
            __syncthreads();

            float acc[16][4];
            #pragma unroll
            for (int i = 0; i < 16; ++i)
                #pragma unroll
                for (int j = 0; j < 4; ++j) acc[i][j] = 0.f;

            #pragma unroll
            for (int kt = 0; kt < 8; ++kt) {
                uint4 ah = *(uint4*)(Ahi + (((kt * 8 + wid) * 32 + lane) << 2));
                uint4 al = *(uint4*)(Alo + (((kt * 8 + wid) * 32 + lane) << 2));
                #pragma unroll
                for (int np = 0; np < 8; ++np) {
                    uint4 bh = Bb[(kt * 8 + np) * 32 + lane];
                    mma16816(acc[2 * np],     ah.x, ah.y, ah.z, ah.w, bh.x, bh.y);
                    mma16816(acc[2 * np + 1], ah.x, ah.y, ah.z, ah.w, bh.z, bh.w);
                    mma16816(acc[2 * np],     al.x, al.y, al.z, al.w, bh.x, bh.y);
                    mma16816(acc[2 * np + 1], al.x, al.y, al.z, al.w, bh.z, bh.w);
                }
            }
            __syncthreads();

            // ---- pass 2: B_lo ----
            {
                const uint4* srcl = g_Bpk[t][m][1];
                #pragma unroll
                for (int i = tid; i < 2048; i += 256)
                    cp16(smb + SM_B + i * 16, srcl + i);
                cp_commit_wait();
            }
            __syncthreads();

            #pragma unroll
            for (int kt = 0; kt < 8; ++kt) {
                uint4 ah = *(uint4*)(Ahi + (((kt * 8 + wid) * 32 + lane) << 2));
                #pragma unroll
                for (int np = 0; np < 8; ++np) {
                    uint4 bl = Bb[(kt * 8 + np) * 32 + lane];
                    mma16816(acc[2 * np],     ah.x, ah.y, ah.z, ah.w, bl.x, bl.y);
                    mma16816(acc[2 * np + 1], ah.x, ah.y, ah.z, ah.w, bl.z, bl.w);
                }
            }

            // ---- epilogue ----
            const float* bias = (m == 0 ? bq : (m == 1 ? bk : bv)) + t * 128;
            int row0 = wid * 16 + (lane >> 2);
            int row1 = row0 + 8;
            bool v0ok = (row0 < count) && (st[row0] == t);
            bool v1ok = (row1 < count) && (st[row1] == t);
            int cbase = (lane & 3) * 2;

            if (m == 0) {
                float* d0 = v0ok ? (g_Q + (size_t)sp[row0] * 128) : nullptr;
                float* d1 = v1ok ? (g_Q + (size_t)sp[row1] * 128) : nullptr;
                #pragma unroll
                for (int nt = 0; nt < 16; ++nt) {
                    int c = nt * 8 + cbase;
                    float2 b2 = __ldg((const float2*)(bias + c));
                    if (v0ok) {
                        float2 o; o.x = acc[nt][0] + b2.x; o.y = acc[nt][1] + b2.y;
                        *(float2*)(d0 + c) = o;
                    }
                    if (v1ok) {
                        float2 o; o.x = acc[nt][2] + b2.x; o.y = acc[nt][3] + b2.y;
                        *(float2*)(d1 + c) = o;
                    }
                }
            } else {
                // interleaved KV layout: element c -> (c>>2)*8 + (m==2?4:0) + (c&3)
                int moff = (m == 2) ? 4 : 0;
                __half* d0 = v0ok ? (g_KVh + (size_t)sp[row0] * 256 + moff) : nullptr;
                __half* d1 = v1ok ? (g_KVh + (size_t)sp[row1] * 256 + moff) : nullptr;
                #pragma unroll
                for (int nt = 0; nt < 16; ++nt) {
                    int c = nt * 8 + cbase;
                    int off = ((c >> 2) << 3) + (c & 3);
                    float2 b2 = __ldg((const float2*)(bias + c));
                    if (v0ok)
                        *(__half2*)(d0 + off) = __floats2half2_rn(acc[nt][0] + b2.x, acc[nt][1] + b2.y);
                    if (v1ok)
                        *(__half2*)(d1 + off) = __floats2half2_rn(acc[nt][2] + b2.x, acc[nt][3] + b2.y);
                }
            }
            __syncthreads();   // everyone done with B before next copy
        }
    }
}

// ---------------- K6: fused gather-attention + residual + LayerNorm ----------
__global__ void __launch_bounds__(512) k_attn(
    const float* __restrict__ x, const int* __restrict__ ntype,
    const float* __restrict__ rbias,
    const float* __restrict__ skip, const float* __restrict__ gamma,
    const float* __restrict__ beta, float* __restrict__ out, int N)
{
    __shared__ __align__(16) float s_rqk[3072];
    __shared__ __align__(16) float s_rvv[3072];
    __shared__ float s_rb[64];

    int tid = threadIdx.x;
    {
        const uint4* sq = (const uint4*)g_tqk;
        const uint4* sv = (const uint4*)g_tv;
        uint4* dq = (uint4*)s_rqk;
        uint4* dv = (uint4*)s_rvv;
        #pragma unroll 2
        for (int i = tid; i < 768; i += 512) { dq[i] = sq[i]; dv[i] = sv[i]; }
    }
    if (tid < 64) s_rb[tid] = rbias[tid];
    __syncthreads();

    int wid = tid >> 5, lane = tid & 31;
    int n = blockIdx.x * 16 + wid;
    if (n >= N) return;
    int h = lane >> 2;

    float4 q4 = *(const float4*)(g_Q + (size_t)n * 128 + lane * 4);
    int start = g_off[n];
    int deg = g_deg[n];

    float4 oa = make_float4(0.f, 0.f, 0.f, 0.f);
    float z = 0.f;

    int j = 0;
    int4 pa, pb;
    if (j + 1 < deg) { pa = g_epk[start]; pb = g_epk[start + 1]; }
    for (; j + 1 < deg; j += 2) {
        // prefetch next pair's payload to break the epk->KV chain
        int4 qa, qb;
        if (j + 3 < deg) { qa = g_epk[start + j + 2]; qb = g_epk[start + j + 3]; }

        uint4 kva = *(const uint4*)(g_KVh + (size_t)pa.x * 256 + lane * 8);
        uint4 kvb = *(const uint4*)(g_KVh + (size_t)pb.x * 256 + lane * 8);

        int cba = (pa.y * 3 + pa.z) * 128 + lane * 4;
        int cbb = (pb.y * 3 + pb.z) * 128 + lane * 4;
        float4 rka = *(float4*)(s_rqk + cba);
        float4 rkb = *(float4*)(s_rqk + cbb);
        float4 rva = *(float4*)(s_rvv + cba);
        float4 rvb = *(float4*)(s_rvv + cbb);

        __half2* ha = (__half2*)&kva;
        __half2* hb = (__half2*)&kvb;
        float2 ka01 = __half22float2(ha[0]), ka23 = __half22float2(ha[1]);
        float2 va01 = __half22float2(ha[2]), va23 = __half22float2(ha[3]);
        float2 kb01 = __half22float2(hb[0]), kb23 = __half22float2(hb[1]);
        float2 vb01 = __half22float2(hb[2]), vb23 = __half22float2(hb[3]);

        float sa = q4.x * ka01.x * rka.x + q4.y * ka01.y * rka.y
                 + q4.z * ka23.x * rka.z + q4.w * ka23.y * rka.w;
        float sb = q4.x * kb01.x * rkb.x + q4.y * kb01.y * rkb.y
                 + q4.z * kb23.x * rkb.z + q4.w * kb23.y * rkb.w;
        sa += __shfl_xor_sync(0xffffffffu, sa, 1);
        sa += __shfl_xor_sync(0xffffffffu, sa, 2);
        sb += __shfl_xor_sync(0xffffffffu, sb, 1);
        sb += __shfl_xor_sync(0xffffffffu, sb, 2);

        float ea = __expf(sa * 0.25f + s_rb[pa.y * 8 + h] + __int_as_float(pa.w));
        float eb = __expf(sb * 0.25f + s_rb[pb.y * 8 + h] + __int_as_float(pb.w));
        z += ea + eb;
        oa.x += va01.x * rva.x * ea + vb01.x * rvb.x * eb;
        oa.y += va01.y * rva.y * ea + vb01.y * rvb.y * eb;
        oa.z += va23.x * rva.z * ea + vb23.x * rvb.z * eb;
        oa.w += va23.y * rva.w * ea + vb23.y * rvb.w * eb;

        pa = qa; pb = qb;
    }
    if (j < deg) {
        int4 p = g_epk[start + j];
        uint4 kv = *(const uint4*)(g_KVh + (size_t)p.x * 256 + lane * 8);
        int cb = (p.y * 3 + p.z) * 128 + lane * 4;
        float4 rk4 = *(float4*)(s_rqk + cb);
        float4 rv4 = *(float4*)(s_rvv + cb);

        __half2* hh = (__half2*)&kv;
        float2 k01 = __half22float2(hh[0]), k23 = __half22float2(hh[1]);
        float2 v01 = __half22float2(hh[2]), v23 = __half22float2(hh[3]);

        float sc = q4.x * k01.x * rk4.x + q4.y * k01.y * rk4.y
                 + q4.z * k23.x * rk4.z + q4.w * k23.y * rk4.w;
        sc += __shfl_xor_sync(0xffffffffu, sc, 1);
        sc += __shfl_xor_sync(0xffffffffu, sc, 2);

        float es = __expf(sc * 0.25f + s_rb[p.y * 8 + h] + __int_as_float(p.w));
        z += es;
        oa.x += v01.x * rv4.x * es;
        oa.y += v01.y * rv4.y * es;
        oa.z += v23.x * rv4.z * es;
        oa.w += v23.y * rv4.w * es;
    }

    int t = ntype[n];
    float a = 1.f / (1.f + __expf(-__ldg(skip + t)));
    float b = 1.f - a;
    float r = a / (z + 1e-9f);

    float4 xi = *(const float4*)(x + (size_t)n * 128 + lane * 4);
    float4 xv;
    xv.x = oa.x * r + b * xi.x;
    xv.y = oa.y * r + b * xi.y;
    xv.z = oa.z * r + b * xi.z;
    xv.w = oa.w * r + b * xi.w;

    float s = xv.x + xv.y + xv.z + xv.w;
    #pragma unroll
    for (int o = 16; o; o >>= 1) s += __shfl_xor_sync(0xffffffffu, s, o);
    float mu = s * (1.f / 128.f);

    float dx0 = xv.x - mu, dx1 = xv.y - mu, dx2 = xv.z - mu, dx3 = xv.w - mu;
    float vs = dx0 * dx0 + dx1 * dx1 + dx2 * dx2 + dx3 * dx3;
    #pragma unroll
    for (int o = 16; o; o >>= 1) vs += __shfl_xor_sync(0xffffffffu, vs, o);
    float rs = rsqrtf(vs * (1.f / 128.f) + 1e-5f);

    float4 g4 = *(const float4*)(gamma + t * 128 + lane * 4);
    float4 be4 = *(const float4*)(beta + t * 128 + lane * 4);

    float4 y;
    y.x = dx0 * rs * g4.x + be4.x;
    y.y = dx1 * rs * g4.y + be4.y;
    y.z = dx2 * rs * g4.z + be4.z;
    y.w = dx3 * rs * g4.w + be4.w;

    *(float4*)(out + (size_t)n * 128 + lane * 4) = y;
}

// ---------------- launch ----------------
extern "C" void kernel_launch(void* const* d_in, const int* in_sizes, int n_in,
                              void* d_out, int out_size)
{
    const float* node_inp   = (const float*)d_in[0];
    const int*   node_type  = (const int*)d_in[1];
    const int*   edge_index = (const int*)d_in[2];
    const int*   edge_type  = (const int*)d_in[3];
    const int*   edge_sign  = (const int*)d_in[4];
    const float* edge_dist  = (const float*)d_in[5];
    const float* Wq = (const float*)d_in[6];
    const float* bq = (const float*)d_in[7];
    const float* Wk = (const float*)d_in[8];
    const float* bk = (const float*)d_in[9];
    const float* Wv = (const float*)d_in[10];
    const float* bv = (const float*)d_in[11];
    const float* rel_q   = (const float*)d_in[12];
    const float* rel_k   = (const float*)d_in[13];
    const float* rel_v   = (const float*)d_in[14];
    const float* rel_b   = (const float*)d_in[15];
    const float* skf     = (const float*)d_in[16];
    const float* svf     = (const float*)d_in[17];
    const float* skn     = (const float*)d_in[18];
    const float* svn     = (const float*)d_in[19];
    const float* d_alpha = (const float*)d_in[20];
    const float* d_tau   = (const float*)d_in[21];
    const float* skip    = (const float*)d_in[22];
    const float* ln_g    = (const float*)d_in[23];
    const float* ln_b    = (const float*)d_in[24];

    int N = in_sizes[1];
    int E = in_sizes[3];

    float* out = (float*)d_out;

    cudaFuncSetAttribute(k_qkv_mma, cudaFuncAttributeMaxDynamicSharedMemorySize, SM_TOTAL);

    int nb = (N + 255) / 256;
    int eb = (E + 255) / 256;

    k_init<<<nb, 256>>>(N);
    k_hist<<<eb, 256>>>(node_type, edge_index, N, E);
    k_off<<<nb, 256>>>(node_type, N);
    k_prep<<<eb + 72, 256>>>(edge_index, edge_type, edge_sign, edge_dist,
                             d_alpha, d_tau, Wq, Wk, Wv,
                             rel_q, rel_k, rel_v, skf, svf, skn, svn, E, eb);

    int qb = (N + 127) / 128;
    k_qkv_mma<<<qb, 256, SM_TOTAL>>>(node_inp, node_type, bq, bk, bv, N);

    int ab = (N + 15) / 16;
    k_attn<<<ab, 512>>>(node_inp, node_type, rel_b, skip, ln_g, ln_b, out, N);
}

// round 8
// speedup vs baseline: 2.5644x; 1.0229x over previous
#include <cuda_runtime.h>
#include <cuda_bf16.h>
#include <cuda_fp16.h>
#include <cstdint>

#define NMAX 100000
#define EMAX 800000

// -------- scratch (static __device__, no allocation) --------
__device__ __half g_Qh[NMAX * 128];
__device__ __half g_KVh[NMAX * 256];   // interleaved: [k0..3 v0..3 k4..7 v4..7 ...]
__device__ int   g_perm[NMAX];
__device__ int   g_cnt[3];
__device__ int   g_cnt2[3];
__device__ int   g_total;
// CSR by destination
__device__ int   g_deg[NMAX];
__device__ int   g_off[NMAX];
__device__ int   g_cur2[NMAX];
__device__ __align__(8) int2 g_epk[EMAX];   // {src|comb<<17|et<<22, phi_bits}
// pre-packed weights in mma.sync B-fragment order
__device__ __align__(16) uint4 g_Bpk[3][3][2][2048];
// precomputed rel/sign tables: [et*3+sidx][128]
__device__ __align__(16) float g_tqk[3072];
__device__ __align__(16) float g_tv[3072];

// ---------------- helpers ----------------
__device__ __forceinline__ uint32_t pack_bf16(float a, float b) {
    __nv_bfloat162 t = __floats2bfloat162_rn(a, b);
    return *(uint32_t*)&t;
}

__device__ __forceinline__ void mma16816(float* c,
    uint32_t a0, uint32_t a1, uint32_t a2, uint32_t a3,
    uint32_t b0, uint32_t b1)
{
    asm volatile(
        "mma.sync.aligned.m16n8k16.row.col.f32.bf16.bf16.f32 "
        "{%0,%1,%2,%3}, {%4,%5,%6,%7}, {%8,%9}, {%0,%1,%2,%3};"
        : "+f"(c[0]), "+f"(c[1]), "+f"(c[2]), "+f"(c[3])
        : "r"(a0), "r"(a1), "r"(a2), "r"(a3), "r"(b0), "r"(b1));
}

__device__ __forceinline__ uint32_t s2u(const void* p) {
    uint32_t a;
    asm("{ .reg .u64 t; cvta.to.shared.u64 t, %1; cvt.u32.u64 %0, t; }" : "=r"(a) : "l"(p));
    return a;
}

__device__ __forceinline__ void cp16(uint32_t s, const void* g) {
    asm volatile("cp.async.cg.shared.global [%0], [%1], 16;" :: "r"(s), "l"(g));
}
__device__ __forceinline__ void cp_commit_wait() {
    asm volatile("cp.async.commit_group;");
    asm volatile("cp.async.wait_group 0;" ::: "memory");
}

// ---------------- K1: init ----------------
__global__ void k_init(int N) {
    int i = blockIdx.x * blockDim.x + threadIdx.x;
    if (i < N) g_deg[i] = 0;
    if (i < 3) { g_cnt[i] = 0; g_cnt2[i] = 0; }
    if (i == 3) g_total = 0;
}

// ---------------- K2: fused type-count + edge-degree histogram ----------------
__global__ void k_hist(const int* __restrict__ ntype, const int* __restrict__ ei,
                       int N, int E) {
    __shared__ int h[3];
    int tid = threadIdx.x;
    if (tid < 3) h[tid] = 0;
    __syncthreads();
    int i = blockIdx.x * blockDim.x + tid;
    if (i < N) atomicAdd(&h[ntype[i]], 1);
    if (i < E) atomicAdd(&g_deg[ei[E + i]], 1);
    __syncthreads();
    if (tid < 3 && h[tid]) atomicAdd(&g_cnt[tid], h[tid]);
}

// ---------------- K3: CSR offsets (non-monotonic, block-atomic) + type-scatter --
__global__ void __launch_bounds__(256) k_off(const int* __restrict__ ntype, int N) {
    __shared__ int sws[8];
    __shared__ int sbase;
    __shared__ int h[3], tb[3];

    int tid = threadIdx.x;
    int lane = tid & 31, w = tid >> 5;
    int i = blockIdx.x * 256 + tid;
    int d = (i < N) ? g_deg[i] : 0;

    int inc = d;
    #pragma unroll
    for (int o = 1; o < 32; o <<= 1) {
        int t = __shfl_up_sync(0xffffffffu, inc, o);
        if (lane >= o) inc += t;
    }
    if (lane == 31) sws[w] = inc;
    if (tid < 3) h[tid] = 0;
    __syncthreads();
    if (tid == 0) {
        int run = 0;
        #pragma unroll
        for (int k = 0; k < 8; ++k) { int t = sws[k]; sws[k] = run; run += t; }
        sbase = atomicAdd(&g_total, run);
    }
    __syncthreads();
    int ex = sbase + sws[w] + inc - d;
    if (i < N) { g_off[i] = ex; g_cur2[i] = ex; }

    int t = 0, r = 0;
    if (i < N) { t = ntype[i]; r = atomicAdd(&h[t], 1); }
    __syncthreads();
    if (tid < 3 && h[tid]) tb[tid] = atomicAdd(&g_cnt2[tid], h[tid]);
    __syncthreads();
    if (i < N) {
        int base = (t == 0) ? 0 : ((t == 1) ? g_cnt[0] : (g_cnt[0] + g_cnt[1]));
        g_perm[base + tb[t] + r] = i;
    }
}

// ---------------- K4: fused edge-payload scatter + weight pack + tables --------
__global__ void k_prep(const int* __restrict__ ei, const int* __restrict__ etype,
                       const int* __restrict__ esign, const float* __restrict__ edist,
                       const float* __restrict__ alphap, const float* __restrict__ taup,
                       const float* __restrict__ Wq, const float* __restrict__ Wk,
                       const float* __restrict__ Wv,
                       const float* __restrict__ rq, const float* __restrict__ rk,
                       const float* __restrict__ rv,
                       const float* __restrict__ skf, const float* __restrict__ svf,
                       const float* __restrict__ skn, const float* __restrict__ svn,
                       int E, int EB)
{
    if ((int)blockIdx.x < EB) {
        int e = blockIdx.x * blockDim.x + threadIdx.x;
        if (e >= E) return;
        int dst = ei[E + e];
        int src = ei[e];
        int et = etype[e];
        int sg = esign[e];
        int sidx = (sg == -1) ? 0 : ((sg == 1) ? 1 : 2);
        float alpha = __ldg(alphap);
        float itau = 1.f / (__ldg(taup) + 1e-9f);
        float phi = alpha * __expf(-edist[e] * itau);
        int pos = atomicAdd(&g_cur2[dst], 1);
        int w = src | ((et * 3 + sidx) << 17) | (et << 22);
        g_epk[pos] = make_int2(w, __float_as_int(phi));
        return;
    }

    int gid = (blockIdx.x - EB) * blockDim.x + threadIdx.x;
    if (gid < 3072) {
        int c = gid >> 7, d = gid & 127;
        int et = c / 3, s = c - et * 3;
        float sk = (s < 2) ? skf[s * 128 + d] : skn[d];
        float sv = (s < 2) ? svf[s * 128 + d] : svn[d];
        g_tqk[gid] = rq[et * 128 + d] * rk[et * 128 + d] * sk;
        g_tv[gid]  = rv[et * 128 + d] * sv;
    }
    if (gid >= 3 * 3 * 2048) return;
    int t = gid / 6144;
    int m = (gid % 6144) / 2048;
    int w = gid % 2048;
    int kt = w >> 8;
    int np = (w >> 5) & 7;
    int lane = w & 31;

    const float* W = (m == 0 ? Wq : (m == 1 ? Wk : Wv)) + (size_t)t * 16384;
    int k0 = kt * 16 + (lane & 3) * 2;
    int n0 = (2 * np) * 8 + (lane >> 2);

    uint4 hi, lo;
    uint32_t* hp = (uint32_t*)&hi;
    uint32_t* lp = (uint32_t*)&lo;
    #pragma unroll
    for (int j = 0; j < 2; ++j) {
        int n = n0 + j * 8;
        #pragma unroll
        for (int g = 0; g < 2; ++g) {
            float v0 = W[(k0 + g * 8) * 128 + n];
            float v1 = W[(k0 + g * 8 + 1) * 128 + n];
            float h0 = __bfloat162float(__float2bfloat16(v0));
            float h1 = __bfloat162float(__float2bfloat16(v1));
            hp[j * 2 + g] = pack_bf16(h0, h1);
            lp[j * 2 + g] = pack_bf16(v0 - h0, v1 - h1);
        }
    }
    g_Bpk[t][m][0][w] = hi;
    g_Bpk[t][m][1][w] = lo;
}

// ---------------- K5: tensor-core QKV, two-pass B, ~98KB smem (2 blocks/SM) ----
#define SM_AHI 0
#define SM_ALO 32768
#define SM_B   65536
#define SM_META (65536 + 33792)
#define SM_TOTAL (SM_META + 1024)

__global__ void __launch_bounds__(256) k_qkv_mma(
    const float* __restrict__ x, const int* __restrict__ ntype,
    const float* __restrict__ bq, const float* __restrict__ bk,
    const float* __restrict__ bv, int N)
{
    extern __shared__ __align__(16) unsigned char sm[];
    uint32_t smb = s2u(sm);
    uint32_t* Ahi = (uint32_t*)(sm + SM_AHI);
    uint32_t* Alo = (uint32_t*)(sm + SM_ALO);
    uint4*    Bb  = (uint4*)(sm + SM_B);
    float*    raw = (float*)(sm + SM_B);     // staging reuses B region (33792 B)
    int* sp = (int*)(sm + SM_META);
    int* st = sp + 128;

    int tid = threadIdx.x;
    int wid = tid >> 5;
    int lane = tid & 31;

    int start = blockIdx.x * 128;
    int count = N - start; if (count > 128) count = 128;

    if (tid < count) {
        int pn = g_perm[start + tid];
        sp[tid] = pn;
        st[tid] = ntype[pn];
    }
    __syncthreads();

    // A pack via staged coalesced loads: 2 chunks of 64 rows
    #pragma unroll
    for (int chunk = 0; chunk < 2; ++chunk) {
        // coalesced gmem -> smem staging (stride 132 floats per row)
        for (int i = tid; i < 2048; i += 256) {
            int row = i >> 5, col = i & 31;
            int gr = chunk * 64 + row;
            float4 v = make_float4(0.f, 0.f, 0.f, 0.f);
            if (gr < count) v = *(const float4*)(x + (size_t)sp[gr] * 128 + col * 4);
            *(float4*)(raw + row * 132 + col * 4) = v;
        }
        __syncthreads();
        // repack to bf16 hi/lo A-fragments (quarter-interleaved: conflict-free)
        {
            int q = tid & 3, row = tid >> 2;
            int gr = chunk * 64 + row;
            int mt = gr >> 4, rr = gr & 15;
            #pragma unroll
            for (int p = 0; p < 16; ++p) {
                int c = q + 4 * p;
                float v0 = raw[row * 132 + 2 * c];
                float v1 = raw[row * 132 + 2 * c + 1];
                float h0 = __bfloat162float(__float2bfloat16(v0));
                float h1 = __bfloat162float(__float2bfloat16(v1));
                int kt = c >> 3, cc = c & 7;
                int wl = (rr & 7) * 4 + (cc & 3);
                int slot = (rr >> 3) | ((cc >> 2) << 1);
                int idx = (((kt * 8 + mt) * 32 + wl) << 2) + slot;
                Ahi[idx] = pack_bf16(h0, h1);
                Alo[idx] = pack_bf16(v0 - h0, v1 - h1);
            }
        }
        __syncthreads();
    }

    int tmin = st[0], tmax = st[count - 1];

    for (int t = tmin; t <= tmax; ++t) {
        for (int m = 0; m < 3; ++m) {
            // ---- pass 1: B_hi ----
            {
                const uint4* srch = g_Bpk[t][m][0];
                #pragma unroll
                for (int i = tid; i < 2048; i += 256)
                    cp16(smb + SM_B + i * 16, srch + i);
                cp_commit_wait();
            }
            __syncthreads();

            float acc[16][4];
            #pragma unroll
            for (int i = 0; i < 16; ++i)
                #pragma unroll
                for (int j = 0; j < 4; ++j) acc[i][j] = 0.f;

            #pragma unroll
            for (int kt = 0; kt < 8; ++kt) {
                uint4 ah = *(uint4*)(Ahi + (((kt * 8 + wid) * 32 + lane) << 2));
                uint4 al = *(uint4*)(Alo + (((kt * 8 + wid) * 32 + lane) << 2));
                #pragma unroll
                for (int np = 0; np < 8; ++np) {
                    uint4 bh = Bb[(kt * 8 + np) * 32 + lane];
                    mma16816(acc[2 * np],     ah.x, ah.y, ah.z, ah.w, bh.x, bh.y);
                    mma16816(acc[2 * np + 1], ah.x, ah.y, ah.z, ah.w, bh.z, bh.w);
                    mma16816(acc[2 * np],     al.x, al.y, al.z, al.w, bh.x, bh.y);
                    mma16816(acc[2 * np + 1], al.x, al.y, al.z, al.w, bh.z, bh.w);
                }
            }
            __syncthreads();

            // ---- pass 2: B_lo ----
            {
                const uint4* srcl = g_Bpk[t][m][1];
                #pragma unroll
                for (int i = tid; i < 2048; i += 256)
                    cp16(smb + SM_B + i * 16, srcl + i);
                cp_commit_wait();
            }
            __syncthreads();

            #pragma unroll
            for (int kt = 0; kt < 8; ++kt) {
                uint4 ah = *(uint4*)(Ahi + (((kt * 8 + wid) * 32 + lane) << 2));
                #pragma unroll
                for (int np = 0; np < 8; ++np) {
                    uint4 bl = Bb[(kt * 8 + np) * 32 + lane];
                    mma16816(acc[2 * np],     ah.x, ah.y, ah.z, ah.w, bl.x, bl.y);
                    mma16816(acc[2 * np + 1], ah.x, ah.y, ah.z, ah.w, bl.z, bl.w);
                }
            }

            // ---- epilogue (all fp16 outputs) ----
            const float* bias = (m == 0 ? bq : (m == 1 ? bk : bv)) + t * 128;
            int row0 = wid * 16 + (lane >> 2);
            int row1 = row0 + 8;
            bool v0ok = (row0 < count) && (st[row0] == t);
            bool v1ok = (row1 < count) && (st[row1] == t);
            int cbase = (lane & 3) * 2;

            __half* d0;
            __half* d1;
            bool interleave;
            if (m == 0) {
                d0 = v0ok ? (g_Qh + (size_t)sp[row0] * 128) : nullptr;
                d1 = v1ok ? (g_Qh + (size_t)sp[row1] * 128) : nullptr;
                interleave = false;
            } else {
                int moff = (m == 2) ? 4 : 0;
                d0 = v0ok ? (g_KVh + (size_t)sp[row0] * 256 + moff) : nullptr;
                d1 = v1ok ? (g_KVh + (size_t)sp[row1] * 256 + moff) : nullptr;
                interleave = true;
            }
            #pragma unroll
            for (int nt = 0; nt < 16; ++nt) {
                int c = nt * 8 + cbase;
                int off = interleave ? (((c >> 2) << 3) + (c & 3)) : c;
                float2 b2 = __ldg((const float2*)(bias + c));
                if (v0ok)
                    *(__half2*)(d0 + off) = __floats2half2_rn(acc[nt][0] + b2.x, acc[nt][1] + b2.y);
                if (v1ok)
                    *(__half2*)(d1 + off) = __floats2half2_rn(acc[nt][2] + b2.x, acc[nt][3] + b2.y);
            }
            __syncthreads();   // everyone done with B before next copy
        }
    }
}

// ---------------- K6: fused gather-attention + residual + LayerNorm ----------
__global__ void __launch_bounds__(512) k_attn(
    const float* __restrict__ x, const int* __restrict__ ntype,
    const float* __restrict__ rbias,
    const float* __restrict__ skip, const float* __restrict__ gamma,
    const float* __restrict__ beta, float* __restrict__ out, int N)
{
    __shared__ __align__(16) float s_rqk[3072];
    __shared__ __align__(16) float s_rvv[3072];
    __shared__ float s_rb[64];

    int tid = threadIdx.x;
    {
        const uint4* sq = (const uint4*)g_tqk;
        const uint4* sv = (const uint4*)g_tv;
        uint4* dq = (uint4*)s_rqk;
        uint4* dv = (uint4*)s_rvv;
        #pragma unroll 2
        for (int i = tid; i < 768; i += 512) { dq[i] = sq[i]; dv[i] = sv[i]; }
    }
    if (tid < 64) s_rb[tid] = rbias[tid];
    __syncthreads();

    int wid = tid >> 5, lane = tid & 31;
    int n = blockIdx.x * 16 + wid;
    if (n >= N) return;
    int h = lane >> 2;

    float4 q4;
    {
        uint2 qr = *(const uint2*)(g_Qh + (size_t)n * 128 + lane * 4);
        __half2* qh = (__half2*)&qr;
        float2 q01 = __half22float2(qh[0]), q23 = __half22float2(qh[1]);
        q4 = make_float4(q01.x, q01.y, q23.x, q23.y);
    }
    int start = g_off[n];
    int deg = g_deg[n];

    float4 oa = make_float4(0.f, 0.f, 0.f, 0.f);
    float z = 0.f;

    int j = 0;
    int2 pa, pb;
    if (j + 1 < deg) { pa = g_epk[start]; pb = g_epk[start + 1]; }
    for (; j + 1 < deg; j += 2) {
        int2 qa, qb;
        if (j + 3 < deg) { qa = g_epk[start + j + 2]; qb = g_epk[start + j + 3]; }

        int sa_i = pa.x & 0x1FFFF;
        int sb_i = pb.x & 0x1FFFF;
        uint4 kva = *(const uint4*)(g_KVh + (size_t)sa_i * 256 + lane * 8);
        uint4 kvb = *(const uint4*)(g_KVh + (size_t)sb_i * 256 + lane * 8);

        int cba = (((pa.x >> 17) & 31) << 7) + lane * 4;
        int cbb = (((pb.x >> 17) & 31) << 7) + lane * 4;
        float4 rka = *(float4*)(s_rqk + cba);
        float4 rkb = *(float4*)(s_rqk + cbb);
        float4 rva = *(float4*)(s_rvv + cba);
        float4 rvb = *(float4*)(s_rvv + cbb);

        __half2* ha = (__half2*)&kva;
        __half2* hb = (__half2*)&kvb;
        float2 ka01 = __half22float2(ha[0]), ka23 = __half22float2(ha[1]);
        float2 va01 = __half22float2(ha[2]), va23 = __half22float2(ha[3]);
        float2 kb01 = __half22float2(hb[0]), kb23 = __half22float2(hb[1]);
        float2 vb01 = __half22float2(hb[2]), vb23 = __half22float2(hb[3]);

        float sa = q4.x * ka01.x * rka.x + q4.y * ka01.y * rka.y
                 + q4.z * ka23.x * rka.z + q4.w * ka23.y * rka.w;
        float sb = q4.x * kb01.x * rkb.x + q4.y * kb01.y * rkb.y
                 + q4.z * kb23.x * rkb.z + q4.w * kb23.y * rkb.w;
        sa += __shfl_xor_sync(0xffffffffu, sa, 1);
        sa += __shfl_xor_sync(0xffffffffu, sa, 2);
        sb += __shfl_xor_sync(0xffffffffu, sb, 1);
        sb += __shfl_xor_sync(0xffffffffu, sb, 2);

        float ea = __expf(sa * 0.25f + s_rb[((pa.x >> 22) & 7) * 8 + h] + __int_as_float(pa.y));
        float eb = __expf(sb * 0.25f + s_rb[((pb.x >> 22) & 7) * 8 + h] + __int_as_float(pb.y));
        z += ea + eb;
        oa.x += va01.x * rva.x * ea + vb01.x * rvb.x * eb;
        oa.y += va01.y * rva.y * ea + vb01.y * rvb.y * eb;
        oa.z += va23.x * rva.z * ea + vb23.x * rvb.z * eb;
        oa.w += va23.y * rva.w * ea + vb23.y * rvb.w * eb;

        pa = qa; pb = qb;
    }
    if (j < deg) {
        int2 p = g_epk[start + j];
        int s_i = p.x & 0x1FFFF;
        uint4 kv = *(const uint4*)(g_KVh + (size_t)s_i * 256 + lane * 8);
        int cb = (((p.x >> 17) & 31) << 7) + lane * 4;
        float4 rk4 = *(float4*)(s_rqk + cb);
        float4 rv4 = *(float4*)(s_rvv + cb);

        __half2* hh = (__half2*)&kv;
        float2 k01 = __half22float2(hh[0]), k23 = __half22float2(hh[1]);
        float2 v01 = __half22float2(hh[2]), v23 = __half22float2(hh[3]);

        float sc = q4.x * k01.x * rk4.x + q4.y * k01.y * rk4.y
                 + q4.z * k23.x * rk4.z + q4.w * k23.y * rk4.w;
        sc += __shfl_xor_sync(0xffffffffu, sc, 1);
        sc += __shfl_xor_sync(0xffffffffu, sc, 2);

        float es = __expf(sc * 0.25f + s_rb[((p.x >> 22) & 7) * 8 + h] + __int_as_float(p.y));
        z += es;
        oa.x += v01.x * rv4.x * es;
        oa.y += v01.y * rv4.y * es;
        oa.z += v23.x * rv4.z * es;
        oa.w += v23.y * rv4.w * es;
    }

    int t = ntype[n];
    float a = 1.f / (1.f + __expf(-__ldg(skip + t)));
    float b = 1.f - a;
    float r = a / (z + 1e-9f);

    float4 xi = *(const float4*)(x + (size_t)n * 128 + lane * 4);
    float4 xv;
    xv.x = oa.x * r + b * xi.x;
    xv.y = oa.y * r + b * xi.y;
    xv.z = oa.z * r + b * xi.z;
    xv.w = oa.w * r + b * xi.w;

    float s = xv.x + xv.y + xv.z + xv.w;
    #pragma unroll
    for (int o = 16; o; o >>= 1) s += __shfl_xor_sync(0xffffffffu, s, o);
    float mu = s * (1.f / 128.f);

    float dx0 = xv.x - mu, dx1 = xv.y - mu, dx2 = xv.z - mu, dx3 = xv.w - mu;
    float vs = dx0 * dx0 + dx1 * dx1 + dx2 * dx2 + dx3 * dx3;
    #pragma unroll
    for (int o = 16; o; o >>= 1) vs += __shfl_xor_sync(0xffffffffu, vs, o);
    float rs = rsqrtf(vs * (1.f / 128.f) + 1e-5f);

    float4 g4 = *(const float4*)(gamma + t * 128 + lane * 4);
    float4 be4 = *(const float4*)(beta + t * 128 + lane * 4);

    float4 y;
    y.x = dx0 * rs * g4.x + be4.x;
    y.y = dx1 * rs * g4.y + be4.y;
    y.z = dx2 * rs * g4.z + be4.z;
    y.w = dx3 * rs * g4.w + be4.w;

    *(float4*)(out + (size_t)n * 128 + lane * 4) = y;
}

// ---------------- launch ----------------
extern "C" void kernel_launch(void* const* d_in, const int* in_sizes, int n_in,
                              void* d_out, int out_size)
{
    const float* node_inp   = (const float*)d_in[0];
    const int*   node_type  = (const int*)d_in[1];
    const int*   edge_index = (const int*)d_in[2];
    const int*   edge_type  = (const int*)d_in[3];
    const int*   edge_sign  = (const int*)d_in[4];
    const float* edge_dist  = (const float*)d_in[5];
    const float* Wq = (const float*)d_in[6];
    const float* bq = (const float*)d_in[7];
    const float* Wk = (const float*)d_in[8];
    const float* bk = (const float*)d_in[9];
    const float* Wv = (const float*)d_in[10];
    const float* bv = (const float*)d_in[11];
    const float* rel_q   = (const float*)d_in[12];
    const float* rel_k   = (const float*)d_in[13];
    const float* rel_v   = (const float*)d_in[14];
    const float* rel_b   = (const float*)d_in[15];
    const float* skf     = (const float*)d_in[16];
    const float* svf     = (const float*)d_in[17];
    const float* skn     = (const float*)d_in[18];
    const float* svn     = (const float*)d_in[19];
    const float* d_alpha = (const float*)d_in[20];
    const float* d_tau   = (const float*)d_in[21];
    const float* skip    = (const float*)d_in[22];
    const float* ln_g    = (const float*)d_in[23];
    const float* ln_b    = (const float*)d_in[24];

    int N = in_sizes[1];
    int E = in_sizes[3];

    float* out = (float*)d_out;

    cudaFuncSetAttribute(k_qkv_mma, cudaFuncAttributeMaxDynamicSharedMemorySize, SM_TOTAL);

    int nb = (N + 255) / 256;
    int eb = (E + 255) / 256;

    k_init<<<nb, 256>>>(N);
    k_hist<<<eb, 256>>>(node_type, edge_index, N, E);
    k_off<<<nb, 256>>>(node_type, N);
    k_prep<<<eb + 72, 256>>>(edge_index, edge_type, edge_sign, edge_dist,
                             d_alpha, d_tau, Wq, Wk, Wv,
                             rel_q, rel_k, rel_v, skf, svf, skn, svn, E, eb);

    int qb = (N + 127) / 128;
    k_qkv_mma<<<qb, 256, SM_TOTAL>>>(node_inp, node_type, bq, bk, bv, N);

    int ab = (N + 15) / 16;
    k_attn<<<ab, 512>>>(node_inp, node_type, rel_b, skip, ln_g, ln_b, out, N);
}

// round 9
// speedup vs baseline: 2.9260x; 1.1410x over previous
#include <cuda_runtime.h>
#include <cuda_fp16.h>
#include <cstdint>

#define NMAX 100000
#define EMAX 800000

// -------- scratch (static __device__, no allocation) --------
__device__ __half g_Qh[NMAX * 128];
__device__ __half g_KVh[NMAX * 256];   // interleaved: [k0..3 v0..3 k4..7 v4..7 ...]
__device__ int   g_perm[NMAX];
__device__ int   g_cnt[3];
__device__ int   g_cnt2[3];
__device__ int   g_total;
// CSR by destination
__device__ int   g_deg[NMAX];
__device__ int   g_off[NMAX];
__device__ int   g_cur2[NMAX];
__device__ __align__(8) int2 g_epk[EMAX];   // {src|comb<<17|et<<22, phi_bits}
// pre-packed fp16 weights in mma.sync B-fragment order
__device__ __align__(16) uint4 g_Bpk[3][3][2048];
// precomputed rel/sign tables: [et*3+sidx][128]
__device__ __align__(16) float g_tqk[3072];
__device__ __align__(16) float g_tv[3072];

// ---------------- helpers ----------------
__device__ __forceinline__ uint32_t pack_half(float a, float b) {
    __half2 t = __floats2half2_rn(a, b);
    return *(uint32_t*)&t;
}

__device__ __forceinline__ void mma16816h(float* c,
    uint32_t a0, uint32_t a1, uint32_t a2, uint32_t a3,
    uint32_t b0, uint32_t b1)
{
    asm volatile(
        "mma.sync.aligned.m16n8k16.row.col.f32.f16.f16.f32 "
        "{%0,%1,%2,%3}, {%4,%5,%6,%7}, {%8,%9}, {%0,%1,%2,%3};"
        : "+f"(c[0]), "+f"(c[1]), "+f"(c[2]), "+f"(c[3])
        : "r"(a0), "r"(a1), "r"(a2), "r"(a3), "r"(b0), "r"(b1));
}

__device__ __forceinline__ uint32_t s2u(const void* p) {
    uint32_t a;
    asm("{ .reg .u64 t; cvta.to.shared.u64 t, %1; cvt.u32.u64 %0, t; }" : "=r"(a) : "l"(p));
    return a;
}

__device__ __forceinline__ void cp16(uint32_t s, const void* g) {
    asm volatile("cp.async.cg.shared.global [%0], [%1], 16;" :: "r"(s), "l"(g));
}
__device__ __forceinline__ void cp_commit_wait() {
    asm volatile("cp.async.commit_group;");
    asm volatile("cp.async.wait_group 0;" ::: "memory");
}

// ---------------- K1: init ----------------
__global__ void k_init(int N) {
    int i = blockIdx.x * blockDim.x + threadIdx.x;
    if (i < N) g_deg[i] = 0;
    if (i < 3) { g_cnt[i] = 0; g_cnt2[i] = 0; }
    if (i == 3) g_total = 0;
}

// ---------------- K2: fused type-count + edge-degree histogram ----------------
__global__ void k_hist(const int* __restrict__ ntype, const int* __restrict__ ei,
                       int N, int E) {
    __shared__ int h[3];
    int tid = threadIdx.x;
    if (tid < 3) h[tid] = 0;
    __syncthreads();
    int i = blockIdx.x * blockDim.x + tid;
    if (i < N) atomicAdd(&h[ntype[i]], 1);
    if (i < E) atomicAdd(&g_deg[ei[E + i]], 1);
    __syncthreads();
    if (tid < 3 && h[tid]) atomicAdd(&g_cnt[tid], h[tid]);
}

// ---------------- K3: CSR offsets (non-monotonic, block-atomic) + type-scatter --
__global__ void __launch_bounds__(256) k_off(const int* __restrict__ ntype, int N) {
    __shared__ int sws[8];
    __shared__ int sbase;
    __shared__ int h[3], tb[3];

    int tid = threadIdx.x;
    int lane = tid & 31, w = tid >> 5;
    int i = blockIdx.x * 256 + tid;
    int d = (i < N) ? g_deg[i] : 0;

    int inc = d;
    #pragma unroll
    for (int o = 1; o < 32; o <<= 1) {
        int t = __shfl_up_sync(0xffffffffu, inc, o);
        if (lane >= o) inc += t;
    }
    if (lane == 31) sws[w] = inc;
    if (tid < 3) h[tid] = 0;
    __syncthreads();
    if (tid == 0) {
        int run = 0;
        #pragma unroll
        for (int k = 0; k < 8; ++k) { int t = sws[k]; sws[k] = run; run += t; }
        sbase = atomicAdd(&g_total, run);
    }
    __syncthreads();
    int ex = sbase + sws[w] + inc - d;
    if (i < N) { g_off[i] = ex; g_cur2[i] = ex; }

    int t = 0, r = 0;
    if (i < N) { t = ntype[i]; r = atomicAdd(&h[t], 1); }
    __syncthreads();
    if (tid < 3 && h[tid]) tb[tid] = atomicAdd(&g_cnt2[tid], h[tid]);
    __syncthreads();
    if (i < N) {
        int base = (t == 0) ? 0 : ((t == 1) ? g_cnt[0] : (g_cnt[0] + g_cnt[1]));
        g_perm[base + tb[t] + r] = i;
    }
}

// ---------------- K4: fused edge-payload scatter + weight pack + tables --------
__global__ void k_prep(const int* __restrict__ ei, const int* __restrict__ etype,
                       const int* __restrict__ esign, const float* __restrict__ edist,
                       const float* __restrict__ alphap, const float* __restrict__ taup,
                       const float* __restrict__ Wq, const float* __restrict__ Wk,
                       const float* __restrict__ Wv,
                       const float* __restrict__ rq, const float* __restrict__ rk,
                       const float* __restrict__ rv,
                       const float* __restrict__ skf, const float* __restrict__ svf,
                       const float* __restrict__ skn, const float* __restrict__ svn,
                       int E, int EB)
{
    if ((int)blockIdx.x < EB) {
        int e = blockIdx.x * blockDim.x + threadIdx.x;
        if (e >= E) return;
        int dst = ei[E + e];
        int src = ei[e];
        int et = etype[e];
        int sg = esign[e];
        int sidx = (sg == -1) ? 0 : ((sg == 1) ? 1 : 2);
        float alpha = __ldg(alphap);
        float itau = 1.f / (__ldg(taup) + 1e-9f);
        float phi = alpha * __expf(-edist[e] * itau);
        int pos = atomicAdd(&g_cur2[dst], 1);
        int w = src | ((et * 3 + sidx) << 17) | (et << 22);
        g_epk[pos] = make_int2(w, __float_as_int(phi));
        return;
    }

    int gid = (blockIdx.x - EB) * blockDim.x + threadIdx.x;
    if (gid < 3072) {
        int c = gid >> 7, d = gid & 127;
        int et = c / 3, s = c - et * 3;
        float sk = (s < 2) ? skf[s * 128 + d] : skn[d];
        float sv = (s < 2) ? svf[s * 128 + d] : svn[d];
        g_tqk[gid] = rq[et * 128 + d] * rk[et * 128 + d] * sk;
        g_tv[gid]  = rv[et * 128 + d] * sv;
    }
    if (gid >= 3 * 3 * 2048) return;
    int t = gid / 6144;
    int m = (gid % 6144) / 2048;
    int w = gid % 2048;
    int kt = w >> 8;
    int np = (w >> 5) & 7;
    int lane = w & 31;

    const float* W = (m == 0 ? Wq : (m == 1 ? Wk : Wv)) + (size_t)t * 16384;
    int k0 = kt * 16 + (lane & 3) * 2;
    int n0 = (2 * np) * 8 + (lane >> 2);

    uint4 hi;
    uint32_t* hp = (uint32_t*)&hi;
    #pragma unroll
    for (int j = 0; j < 2; ++j) {
        int n = n0 + j * 8;
        #pragma unroll
        for (int g = 0; g < 2; ++g) {
            float v0 = W[(k0 + g * 8) * 128 + n];
            float v1 = W[(k0 + g * 8 + 1) * 128 + n];
            hp[j * 2 + g] = pack_half(v0, v1);
        }
    }
    g_Bpk[t][m][w] = hi;
}

// ---------------- K5: tensor-core QKV, single-pass fp16, ~66KB smem ----------
#define SM_A   0
#define SM_B   32768
#define SM_META (32768 + 33792)
#define SM_TOTAL (SM_META + 1024)

__global__ void __launch_bounds__(256) k_qkv_mma(
    const float* __restrict__ x, const int* __restrict__ ntype,
    const float* __restrict__ bq, const float* __restrict__ bk,
    const float* __restrict__ bv, int N)
{
    extern __shared__ __align__(16) unsigned char sm[];
    uint32_t smb = s2u(sm);
    uint32_t* Af  = (uint32_t*)(sm + SM_A);
    uint4*    Bb  = (uint4*)(sm + SM_B);
    float*    raw = (float*)(sm + SM_B);     // staging reuses B region (33792 B)
    int* sp = (int*)(sm + SM_META);
    int* st = sp + 128;

    int tid = threadIdx.x;
    int wid = tid >> 5;
    int lane = tid & 31;

    int start = blockIdx.x * 128;
    int count = N - start; if (count > 128) count = 128;

    if (tid < count) {
        int pn = g_perm[start + tid];
        sp[tid] = pn;
        st[tid] = ntype[pn];
    }
    __syncthreads();

    // A pack via staged coalesced loads: 2 chunks of 64 rows
    #pragma unroll
    for (int chunk = 0; chunk < 2; ++chunk) {
        for (int i = tid; i < 2048; i += 256) {
            int row = i >> 5, col = i & 31;
            int gr = chunk * 64 + row;
            float4 v = make_float4(0.f, 0.f, 0.f, 0.f);
            if (gr < count) v = *(const float4*)(x + (size_t)sp[gr] * 128 + col * 4);
            *(float4*)(raw + row * 132 + col * 4) = v;
        }
        __syncthreads();
        {
            int q = tid & 3, row = tid >> 2;
            int gr = chunk * 64 + row;
            int mt = gr >> 4, rr = gr & 15;
            #pragma unroll
            for (int p = 0; p < 16; ++p) {
                int c = q + 4 * p;
                float v0 = raw[row * 132 + 2 * c];
                float v1 = raw[row * 132 + 2 * c + 1];
                int kt = c >> 3, cc = c & 7;
                int wl = (rr & 7) * 4 + (cc & 3);
                int slot = (rr >> 3) | ((cc >> 2) << 1);
                int idx = (((kt * 8 + mt) * 32 + wl) << 2) + slot;
                Af[idx] = pack_half(v0, v1);
            }
        }
        __syncthreads();
    }

    int tmin = st[0], tmax = st[count - 1];

    for (int t = tmin; t <= tmax; ++t) {
        for (int m = 0; m < 3; ++m) {
            // copy pre-packed fp16 B frags (32KB)
            {
                const uint4* srch = g_Bpk[t][m];
                #pragma unroll
                for (int i = tid; i < 2048; i += 256)
                    cp16(smb + SM_B + i * 16, srch + i);
                cp_commit_wait();
            }
            __syncthreads();

            float acc[16][4];
            #pragma unroll
            for (int i = 0; i < 16; ++i)
                #pragma unroll
                for (int j = 0; j < 4; ++j) acc[i][j] = 0.f;

            #pragma unroll
            for (int kt = 0; kt < 8; ++kt) {
                uint4 ah = *(uint4*)(Af + (((kt * 8 + wid) * 32 + lane) << 2));
                #pragma unroll
                for (int np = 0; np < 8; ++np) {
                    uint4 bh = Bb[(kt * 8 + np) * 32 + lane];
                    mma16816h(acc[2 * np],     ah.x, ah.y, ah.z, ah.w, bh.x, bh.y);
                    mma16816h(acc[2 * np + 1], ah.x, ah.y, ah.z, ah.w, bh.z, bh.w);
                }
            }

            // ---- epilogue (all fp16 outputs) ----
            const float* bias = (m == 0 ? bq : (m == 1 ? bk : bv)) + t * 128;
            int row0 = wid * 16 + (lane >> 2);
            int row1 = row0 + 8;
            bool v0ok = (row0 < count) && (st[row0] == t);
            bool v1ok = (row1 < count) && (st[row1] == t);
            int cbase = (lane & 3) * 2;

            __half* d0;
            __half* d1;
            bool interleave;
            if (m == 0) {
                d0 = v0ok ? (g_Qh + (size_t)sp[row0] * 128) : nullptr;
                d1 = v1ok ? (g_Qh + (size_t)sp[row1] * 128) : nullptr;
                interleave = false;
            } else {
                int moff = (m == 2) ? 4 : 0;
                d0 = v0ok ? (g_KVh + (size_t)sp[row0] * 256 + moff) : nullptr;
                d1 = v1ok ? (g_KVh + (size_t)sp[row1] * 256 + moff) : nullptr;
                interleave = true;
            }
            #pragma unroll
            for (int nt = 0; nt < 16; ++nt) {
                int c = nt * 8 + cbase;
                int off = interleave ? (((c >> 2) << 3) + (c & 3)) : c;
                float2 b2 = __ldg((const float2*)(bias + c));
                if (v0ok)
                    *(__half2*)(d0 + off) = __floats2half2_rn(acc[nt][0] + b2.x, acc[nt][1] + b2.y);
                if (v1ok)
                    *(__half2*)(d1 + off) = __floats2half2_rn(acc[nt][2] + b2.x, acc[nt][3] + b2.y);
            }
            __syncthreads();   // everyone done with B before next copy
        }
    }
}

// ---------------- K6: fused gather-attention + residual + LayerNorm ----------
__global__ void __launch_bounds__(512) k_attn(
    const float* __restrict__ x, const int* __restrict__ ntype,
    const float* __restrict__ rbias,
    const float* __restrict__ skip, const float* __restrict__ gamma,
    const float* __restrict__ beta, float* __restrict__ out, int N)
{
    __shared__ __align__(16) float s_rqk[3072];
    __shared__ __align__(16) float s_rvv[3072];
    __shared__ float s_rb[64];

    int tid = threadIdx.x;
    {
        const uint4* sq = (const uint4*)g_tqk;
        const uint4* sv = (const uint4*)g_tv;
        uint4* dq = (uint4*)s_rqk;
        uint4* dv = (uint4*)s_rvv;
        #pragma unroll 2
        for (int i = tid; i < 768; i += 512) { dq[i] = sq[i]; dv[i] = sv[i]; }
    }
    if (tid < 64) s_rb[tid] = rbias[tid];
    __syncthreads();

    int wid = tid >> 5, lane = tid & 31;
    int n = blockIdx.x * 16 + wid;
    if (n >= N) return;
    int h = lane >> 2;

    float4 q4;
    {
        uint2 qr = *(const uint2*)(g_Qh + (size_t)n * 128 + lane * 4);
        __half2* qh = (__half2*)&qr;
        float2 q01 = __half22float2(qh[0]), q23 = __half22float2(qh[1]);
        q4 = make_float4(q01.x, q01.y, q23.x, q23.y);
    }
    int start = g_off[n];
    int deg = g_deg[n];

    float4 oa = make_float4(0.f, 0.f, 0.f, 0.f);
    float z = 0.f;

    int j = 0;
    int2 pa, pb;
    if (j + 1 < deg) { pa = g_epk[start]; pb = g_epk[start + 1]; }
    for (; j + 1 < deg; j += 2) {
        int2 qa, qb;
        if (j + 3 < deg) { qa = g_epk[start + j + 2]; qb = g_epk[start + j + 3]; }

        int sa_i = pa.x & 0x1FFFF;
        int sb_i = pb.x & 0x1FFFF;
        uint4 kva = *(const uint4*)(g_KVh + (size_t)sa_i * 256 + lane * 8);
        uint4 kvb = *(const uint4*)(g_KVh + (size_t)sb_i * 256 + lane * 8);

        int cba = (((pa.x >> 17) & 31) << 7) + lane * 4;
        int cbb = (((pb.x >> 17) & 31) << 7) + lane * 4;
        float4 rka = *(float4*)(s_rqk + cba);
        float4 rkb = *(float4*)(s_rqk + cbb);
        float4 rva = *(float4*)(s_rvv + cba);
        float4 rvb = *(float4*)(s_rvv + cbb);

        __half2* ha = (__half2*)&kva;
        __half2* hb = (__half2*)&kvb;
        float2 ka01 = __half22float2(ha[0]), ka23 = __half22float2(ha[1]);
        float2 va01 = __half22float2(ha[2]), va23 = __half22float2(ha[3]);
        float2 kb01 = __half22float2(hb[0]), kb23 = __half22float2(hb[1]);
        float2 vb01 = __half22float2(hb[2]), vb23 = __half22float2(hb[3]);

        float sa = q4.x * ka01.x * rka.x + q4.y * ka01.y * rka.y
                 + q4.z * ka23.x * rka.z + q4.w * ka23.y * rka.w;
        float sb = q4.x * kb01.x * rkb.x + q4.y * kb01.y * rkb.y
                 + q4.z * kb23.x * rkb.z + q4.w * kb23.y * rkb.w;
        sa += __shfl_xor_sync(0xffffffffu, sa, 1);
        sa += __shfl_xor_sync(0xffffffffu, sa, 2);
        sb += __shfl_xor_sync(0xffffffffu, sb, 1);
        sb += __shfl_xor_sync(0xffffffffu, sb, 2);

        float ea = __expf(sa * 0.25f + s_rb[((pa.x >> 22) & 7) * 8 + h] + __int_as_float(pa.y));
        float eb = __expf(sb * 0.25f + s_rb[((pb.x >> 22) & 7) * 8 + h] + __int_as_float(pb.y));
        z += ea + eb;
        oa.x += va01.x * rva.x * ea + vb01.x * rvb.x * eb;
        oa.y += va01.y * rva.y * ea + vb01.y * rvb.y * eb;
        oa.z += va23.x * rva.z * ea + vb23.x * rvb.z * eb;
        oa.w += va23.y * rva.w * ea + vb23.y * rvb.w * eb;

        pa = qa; pb = qb;
    }
    if (j < deg) {
        int2 p = g_epk[start + j];
        int s_i = p.x & 0x1FFFF;
        uint4 kv = *(const uint4*)(g_KVh + (size_t)s_i * 256 + lane * 8);
        int cb = (((p.x >> 17) & 31) << 7) + lane * 4;
        float4 rk4 = *(float4*)(s_rqk + cb);
        float4 rv4 = *(float4*)(s_rvv + cb);

        __half2* hh = (__half2*)&kv;
        float2 k01 = __half22float2(hh[0]), k23 = __half22float2(hh[1]);
        float2 v01 = __half22float2(hh[2]), v23 = __half22float2(hh[3]);

        float sc = q4.x * k01.x * rk4.x + q4.y * k01.y * rk4.y
                 + q4.z * k23.x * rk4.z + q4.w * k23.y * rk4.w;
        sc += __shfl_xor_sync(0xffffffffu, sc, 1);
        sc += __shfl_xor_sync(0xffffffffu, sc, 2);

        float es = __expf(sc * 0.25f + s_rb[((p.x >> 22) & 7) * 8 + h] + __int_as_float(p.y));
        z += es;
        oa.x += v01.x * rv4.x * es;
        oa.y += v01.y * rv4.y * es;
        oa.z += v23.x * rv4.z * es;
        oa.w += v23.y * rv4.w * es;
    }

    int t = ntype[n];
    float a = 1.f / (1.f + __expf(-__ldg(skip + t)));
    float b = 1.f - a;
    float r = a / (z + 1e-9f);

    float4 xi = *(const float4*)(x + (size_t)n * 128 + lane * 4);
    float4 xv;
    xv.x = oa.x * r + b * xi.x;
    xv.y = oa.y * r + b * xi.y;
    xv.z = oa.z * r + b * xi.z;
    xv.w = oa.w * r + b * xi.w;

    float s = xv.x + xv.y + xv.z + xv.w;
    #pragma unroll
    for (int o = 16; o; o >>= 1) s += __shfl_xor_sync(0xffffffffu, s, o);
    float mu = s * (1.f / 128.f);

    float dx0 = xv.x - mu, dx1 = xv.y - mu, dx2 = xv.z - mu, dx3 = xv.w - mu;
    float vs = dx0 * dx0 + dx1 * dx1 + dx2 * dx2 + dx3 * dx3;
    #pragma unroll
    for (int o = 16; o; o >>= 1) vs += __shfl_xor_sync(0xffffffffu, vs, o);
    float rs = rsqrtf(vs * (1.f / 128.f) + 1e-5f);

    float4 g4 = *(const float4*)(gamma + t * 128 + lane * 4);
    float4 be4 = *(const float4*)(beta + t * 128 + lane * 4);

    float4 y;
    y.x = dx0 * rs * g4.x + be4.x;
    y.y = dx1 * rs * g4.y + be4.y;
    y.z = dx2 * rs * g4.z + be4.z;
    y.w = dx3 * rs * g4.w + be4.w;

    *(float4*)(out + (size_t)n * 128 + lane * 4) = y;
}

// ---------------- launch ----------------
extern "C" void kernel_launch(void* const* d_in, const int* in_sizes, int n_in,
                              void* d_out, int out_size)
{
    const float* node_inp   = (const float*)d_in[0];
    const int*   node_type  = (const int*)d_in[1];
    const int*   edge_index = (const int*)d_in[2];
    const int*   edge_type  = (const int*)d_in[3];
    const int*   edge_sign  = (const int*)d_in[4];
    const float* edge_dist  = (const float*)d_in[5];
    const float* Wq = (const float*)d_in[6];
    const float* bq = (const float*)d_in[7];
    const float* Wk = (const float*)d_in[8];
    const float* bk = (const float*)d_in[9];
    const float* Wv = (const float*)d_in[10];
    const float* bv = (const float*)d_in[11];
    const float* rel_q   = (const float*)d_in[12];
    const float* rel_k   = (const float*)d_in[13];
    const float* rel_v   = (const float*)d_in[14];
    const float* rel_b   = (const float*)d_in[15];
    const float* skf     = (const float*)d_in[16];
    const float* svf     = (const float*)d_in[17];
    const float* skn     = (const float*)d_in[18];
    const float* svn     = (const float*)d_in[19];
    const float* d_alpha = (const float*)d_in[20];
    const float* d_tau   = (const float*)d_in[21];
    const float* skip    = (const float*)d_in[22];
    const float* ln_g    = (const float*)d_in[23];
    const float* ln_b    = (const float*)d_in[24];

    int N = in_sizes[1];
    int E = in_sizes[3];

    float* out = (float*)d_out;

    cudaFuncSetAttribute(k_qkv_mma, cudaFuncAttributeMaxDynamicSharedMemorySize, SM_TOTAL);

    int nb = (N + 255) / 256;
    int eb = (E + 255) / 256;

    k_init<<<nb, 256>>>(N);
    k_hist<<<eb, 256>>>(node_type, edge_index, N, E);
    k_off<<<nb, 256>>>(node_type, N);
    k_prep<<<eb + 72, 256>>>(edge_index, edge_type, edge_sign, edge_dist,
                             d_alpha, d_tau, Wq, Wk, Wv,
                             rel_q, rel_k, rel_v, skf, svf, skn, svn, E, eb);

    int qb = (N + 127) / 128;
    k_qkv_mma<<<qb, 256, SM_TOTAL>>>(node_inp, node_type, bq, bk, bv, N);

    int ab = (N + 15) / 16;
    k_attn<<<ab, 512>>>(node_inp, node_type, rel_b, skip, ln_g, ln_b, out, N);
}

// round 10
// speedup vs baseline: 2.9546x; 1.0098x over previous
#include <cuda_runtime.h>
#include <cuda_fp16.h>
#include <cstdint>

#define NMAX 100000
#define EMAX 800000

// -------- scratch (static __device__, no allocation) --------
__device__ __half g_Qh[NMAX * 128];
__device__ __half g_KVh[NMAX * 256];   // interleaved: [k0..3 v0..3 k4..7 v4..7 ...]
__device__ int   g_perm[NMAX];
__device__ int   g_cnt[3];
__device__ int   g_cnt2[3];
__device__ int   g_total;
__device__ int   g_wq;                 // dynamic work cursor for attn
// CSR by destination
__device__ int   g_deg[NMAX];
__device__ int   g_off[NMAX];
__device__ int   g_cur2[NMAX];
__device__ __align__(8) int2 g_epk[EMAX];   // {src|comb<<17|et<<22, phi_bits}
// pre-packed fp16 weights in mma.sync B-fragment order
__device__ __align__(16) uint4 g_Bpk[3][3][2048];
// precomputed rel/sign tables: [et*3+sidx][128]
__device__ __align__(16) float g_tqk[3072];
__device__ __align__(16) float g_tv[3072];

// ---------------- helpers ----------------
__device__ __forceinline__ uint32_t pack_half(float a, float b) {
    __half2 t = __floats2half2_rn(a, b);
    return *(uint32_t*)&t;
}

__device__ __forceinline__ void mma16816h(float* c,
    uint32_t a0, uint32_t a1, uint32_t a2, uint32_t a3,
    uint32_t b0, uint32_t b1)
{
    asm volatile(
        "mma.sync.aligned.m16n8k16.row.col.f32.f16.f16.f32 "
        "{%0,%1,%2,%3}, {%4,%5,%6,%7}, {%8,%9}, {%0,%1,%2,%3};"
        : "+f"(c[0]), "+f"(c[1]), "+f"(c[2]), "+f"(c[3])
        : "r"(a0), "r"(a1), "r"(a2), "r"(a3), "r"(b0), "r"(b1));
}

__device__ __forceinline__ uint32_t s2u(const void* p) {
    uint32_t a;
    asm("{ .reg .u64 t; cvta.to.shared.u64 t, %1; cvt.u32.u64 %0, t; }" : "=r"(a) : "l"(p));
    return a;
}

__device__ __forceinline__ void cp16(uint32_t s, const void* g) {
    asm volatile("cp.async.cg.shared.global [%0], [%1], 16;" :: "r"(s), "l"(g));
}
__device__ __forceinline__ void cp_commit_wait() {
    asm volatile("cp.async.commit_group;");
    asm volatile("cp.async.wait_group 0;" ::: "memory");
}

// ---------------- K1: init ----------------
__global__ void k_init(int N) {
    int i = blockIdx.x * blockDim.x + threadIdx.x;
    if (i < N) g_deg[i] = 0;
    if (i < 3) { g_cnt[i] = 0; g_cnt2[i] = 0; }
    if (i == 3) g_total = 0;
    if (i == 4) g_wq = 0;
}

// ---------------- K2: fused type-count + edge-degree histogram ----------------
__global__ void k_hist(const int* __restrict__ ntype, const int* __restrict__ ei,
                       int N, int E) {
    __shared__ int h[3];
    int tid = threadIdx.x;
    if (tid < 3) h[tid] = 0;
    __syncthreads();
    int i = blockIdx.x * blockDim.x + tid;
    if (i < N) atomicAdd(&h[ntype[i]], 1);
    if (i < E) atomicAdd(&g_deg[ei[E + i]], 1);
    __syncthreads();
    if (tid < 3 && h[tid]) atomicAdd(&g_cnt[tid], h[tid]);
}

// ---------------- K3: CSR offsets (non-monotonic, block-atomic) + type-scatter --
__global__ void __launch_bounds__(256) k_off(const int* __restrict__ ntype, int N) {
    __shared__ int sws[8];
    __shared__ int sbase;
    __shared__ int h[3], tb[3];

    int tid = threadIdx.x;
    int lane = tid & 31, w = tid >> 5;
    int i = blockIdx.x * 256 + tid;
    int d = (i < N) ? g_deg[i] : 0;

    int inc = d;
    #pragma unroll
    for (int o = 1; o < 32; o <<= 1) {
        int t = __shfl_up_sync(0xffffffffu, inc, o);
        if (lane >= o) inc += t;
    }
    if (lane == 31) sws[w] = inc;
    if (tid < 3) h[tid] = 0;
    __syncthreads();
    if (tid == 0) {
        int run = 0;
        #pragma unroll
        for (int k = 0; k < 8; ++k) { int t = sws[k]; sws[k] = run; run += t; }
        sbase = atomicAdd(&g_total, run);
    }
    __syncthreads();
    int ex = sbase + sws[w] + inc - d;
    if (i < N) { g_off[i] = ex; g_cur2[i] = ex; }

    int t = 0, r = 0;
    if (i < N) { t = ntype[i]; r = atomicAdd(&h[t], 1); }
    __syncthreads();
    if (tid < 3 && h[tid]) tb[tid] = atomicAdd(&g_cnt2[tid], h[tid]);
    __syncthreads();
    if (i < N) {
        int base = (t == 0) ? 0 : ((t == 1) ? g_cnt[0] : (g_cnt[0] + g_cnt[1]));
        g_perm[base + tb[t] + r] = i;
    }
}

// ---------------- K4: fused edge-payload scatter + weight pack + tables --------
__global__ void k_prep(const int* __restrict__ ei, const int* __restrict__ etype,
                       const int* __restrict__ esign, const float* __restrict__ edist,
                       const float* __restrict__ alphap, const float* __restrict__ taup,
                       const float* __restrict__ Wq, const float* __restrict__ Wk,
                       const float* __restrict__ Wv,
                       const float* __restrict__ rq, const float* __restrict__ rk,
                       const float* __restrict__ rv,
                       const float* __restrict__ skf, const float* __restrict__ svf,
                       const float* __restrict__ skn, const float* __restrict__ svn,
                       int E, int EB)
{
    if ((int)blockIdx.x < EB) {
        int e = blockIdx.x * blockDim.x + threadIdx.x;
        if (e >= E) return;
        int dst = ei[E + e];
        int src = ei[e];
        int et = etype[e];
        int sg = esign[e];
        int sidx = (sg == -1) ? 0 : ((sg == 1) ? 1 : 2);
        float alpha = __ldg(alphap);
        float itau = 1.f / (__ldg(taup) + 1e-9f);
        float phi = alpha * __expf(-edist[e] * itau);
        int pos = atomicAdd(&g_cur2[dst], 1);
        int w = src | ((et * 3 + sidx) << 17) | (et << 22);
        g_epk[pos] = make_int2(w, __float_as_int(phi));
        return;
    }

    int gid = (blockIdx.x - EB) * blockDim.x + threadIdx.x;
    if (gid < 3072) {
        int c = gid >> 7, d = gid & 127;
        int et = c / 3, s = c - et * 3;
        float sk = (s < 2) ? skf[s * 128 + d] : skn[d];
        float sv = (s < 2) ? svf[s * 128 + d] : svn[d];
        g_tqk[gid] = rq[et * 128 + d] * rk[et * 128 + d] * sk;
        g_tv[gid]  = rv[et * 128 + d] * sv;
    }
    if (gid >= 3 * 3 * 2048) return;
    int t = gid / 6144;
    int m = (gid % 6144) / 2048;
    int w = gid % 2048;
    int kt = w >> 8;
    int np = (w >> 5) & 7;
    int lane = w & 31;

    const float* W = (m == 0 ? Wq : (m == 1 ? Wk : Wv)) + (size_t)t * 16384;
    int k0 = kt * 16 + (lane & 3) * 2;
    int n0 = (2 * np) * 8 + (lane >> 2);

    uint4 hi;
    uint32_t* hp = (uint32_t*)&hi;
    #pragma unroll
    for (int j = 0; j < 2; ++j) {
        int n = n0 + j * 8;
        #pragma unroll
        for (int g = 0; g < 2; ++g) {
            float v0 = W[(k0 + g * 8) * 128 + n];
            float v1 = W[(k0 + g * 8 + 1) * 128 + n];
            hp[j * 2 + g] = pack_half(v0, v1);
        }
    }
    g_Bpk[t][m][w] = hi;
}

// ---------------- K5: tensor-core QKV, single-pass fp16, ~66KB smem ----------
#define SM_A   0
#define SM_B   32768
#define SM_META (32768 + 33792)
#define SM_TOTAL (SM_META + 1024)

__global__ void __launch_bounds__(256) k_qkv_mma(
    const float* __restrict__ x, const int* __restrict__ ntype,
    const float* __restrict__ bq, const float* __restrict__ bk,
    const float* __restrict__ bv, int N)
{
    extern __shared__ __align__(16) unsigned char sm[];
    uint32_t smb = s2u(sm);
    uint32_t* Af  = (uint32_t*)(sm + SM_A);
    uint4*    Bb  = (uint4*)(sm + SM_B);
    float*    raw = (float*)(sm + SM_B);     // staging reuses B region (33792 B)
    int* sp = (int*)(sm + SM_META);
    int* st = sp + 128;

    int tid = threadIdx.x;
    int wid = tid >> 5;
    int lane = tid & 31;

    int start = blockIdx.x * 128;
    int count = N - start; if (count > 128) count = 128;

    if (tid < count) {
        int pn = g_perm[start + tid];
        sp[tid] = pn;
        st[tid] = ntype[pn];
    }
    __syncthreads();

    // A pack via staged coalesced loads: 2 chunks of 64 rows
    #pragma unroll
    for (int chunk = 0; chunk < 2; ++chunk) {
        for (int i = tid; i < 2048; i += 256) {
            int row = i >> 5, col = i & 31;
            int gr = chunk * 64 + row;
            float4 v = make_float4(0.f, 0.f, 0.f, 0.f);
            if (gr < count) v = *(const float4*)(x + (size_t)sp[gr] * 128 + col * 4);
            *(float4*)(raw + row * 132 + col * 4) = v;
        }
        __syncthreads();
        {
            int q = tid & 3, row = tid >> 2;
            int gr = chunk * 64 + row;
            int mt = gr >> 4, rr = gr & 15;
            #pragma unroll
            for (int p = 0; p < 16; ++p) {
                int c = q + 4 * p;
                float v0 = raw[row * 132 + 2 * c];
                float v1 = raw[row * 132 + 2 * c + 1];
                int kt = c >> 3, cc = c & 7;
                int wl = (rr & 7) * 4 + (cc & 3);
                int slot = (rr >> 3) | ((cc >> 2) << 1);
                int idx = (((kt * 8 + mt) * 32 + wl) << 2) + slot;
                Af[idx] = pack_half(v0, v1);
            }
        }
        __syncthreads();
    }

    int tmin = st[0], tmax = st[count - 1];

    for (int t = tmin; t <= tmax; ++t) {
        for (int m = 0; m < 3; ++m) {
            {
                const uint4* srch = g_Bpk[t][m];
                #pragma unroll
                for (int i = tid; i < 2048; i += 256)
                    cp16(smb + SM_B + i * 16, srch + i);
                cp_commit_wait();
            }
            __syncthreads();

            float acc[16][4];
            #pragma unroll
            for (int i = 0; i < 16; ++i)
                #pragma unroll
                for (int j = 0; j < 4; ++j) acc[i][j] = 0.f;

            #pragma unroll
            for (int kt = 0; kt < 8; ++kt) {
                uint4 ah = *(uint4*)(Af + (((kt * 8 + wid) * 32 + lane) << 2));
                #pragma unroll
                for (int np = 0; np < 8; ++np) {
                    uint4 bh = Bb[(kt * 8 + np) * 32 + lane];
                    mma16816h(acc[2 * np],     ah.x, ah.y, ah.z, ah.w, bh.x, bh.y);
                    mma16816h(acc[2 * np + 1], ah.x, ah.y, ah.z, ah.w, bh.z, bh.w);
                }
            }

            // ---- epilogue (all fp16 outputs) ----
            const float* bias = (m == 0 ? bq : (m == 1 ? bk : bv)) + t * 128;
            int row0 = wid * 16 + (lane >> 2);
            int row1 = row0 + 8;
            bool v0ok = (row0 < count) && (st[row0] == t);
            bool v1ok = (row1 < count) && (st[row1] == t);
            int cbase = (lane & 3) * 2;

            __half* d0;
            __half* d1;
            bool interleave;
            if (m == 0) {
                d0 = v0ok ? (g_Qh + (size_t)sp[row0] * 128) : nullptr;
                d1 = v1ok ? (g_Qh + (size_t)sp[row1] * 128) : nullptr;
                interleave = false;
            } else {
                int moff = (m == 2) ? 4 : 0;
                d0 = v0ok ? (g_KVh + (size_t)sp[row0] * 256 + moff) : nullptr;
                d1 = v1ok ? (g_KVh + (size_t)sp[row1] * 256 + moff) : nullptr;
                interleave = true;
            }
            #pragma unroll
            for (int nt = 0; nt < 16; ++nt) {
                int c = nt * 8 + cbase;
                int off = interleave ? (((c >> 2) << 3) + (c & 3)) : c;
                float2 b2 = __ldg((const float2*)(bias + c));
                if (v0ok)
                    *(__half2*)(d0 + off) = __floats2half2_rn(acc[nt][0] + b2.x, acc[nt][1] + b2.y);
                if (v1ok)
                    *(__half2*)(d1 + off) = __floats2half2_rn(acc[nt][2] + b2.x, acc[nt][3] + b2.y);
            }
            __syncthreads();
        }
    }
}

// ---------------- K6: fused gather-attention + residual + LN, dynamic work ----
__global__ void __launch_bounds__(256) k_attn(
    const float* __restrict__ x, const int* __restrict__ ntype,
    const float* __restrict__ rbias,
    const float* __restrict__ skip, const float* __restrict__ gamma,
    const float* __restrict__ beta, float* __restrict__ out, int N)
{
    __shared__ __align__(16) float s_rqk[3072];
    __shared__ __align__(16) float s_rvv[3072];
    __shared__ float s_rb[64];

    int tid = threadIdx.x;
    {
        const uint4* sq = (const uint4*)g_tqk;
        const uint4* sv = (const uint4*)g_tv;
        uint4* dq = (uint4*)s_rqk;
        uint4* dv = (uint4*)s_rvv;
        #pragma unroll 3
        for (int i = tid; i < 768; i += 256) { dq[i] = sq[i]; dv[i] = sv[i]; }
    }
    if (tid < 64) s_rb[tid] = rbias[tid];
    __syncthreads();

    int lane = tid & 31;
    int h = lane >> 2;

    for (;;) {
        int base = 0;
        if (lane == 0) base = atomicAdd(&g_wq, 4);
        base = __shfl_sync(0xffffffffu, base, 0);
        if (base >= N) return;
        int stop = base + 4; if (stop > N) stop = N;

        for (int n = base; n < stop; ++n) {
            float4 q4;
            {
                uint2 qr = *(const uint2*)(g_Qh + (size_t)n * 128 + lane * 4);
                __half2* qh = (__half2*)&qr;
                float2 q01 = __half22float2(qh[0]), q23 = __half22float2(qh[1]);
                q4 = make_float4(q01.x, q01.y, q23.x, q23.y);
            }
            int start = g_off[n];
            int deg = g_deg[n];

            float4 oa = make_float4(0.f, 0.f, 0.f, 0.f);
            float z = 0.f;

            int j = 0;
            int2 pa, pb;
            if (j + 1 < deg) { pa = g_epk[start]; pb = g_epk[start + 1]; }
            for (; j + 1 < deg; j += 2) {
                int2 qa, qb;
                if (j + 3 < deg) { qa = g_epk[start + j + 2]; qb = g_epk[start + j + 3]; }

                int sa_i = pa.x & 0x1FFFF;
                int sb_i = pb.x & 0x1FFFF;
                uint4 kva = *(const uint4*)(g_KVh + (size_t)sa_i * 256 + lane * 8);
                uint4 kvb = *(const uint4*)(g_KVh + (size_t)sb_i * 256 + lane * 8);

                int cba = (((pa.x >> 17) & 31) << 7) + lane * 4;
                int cbb = (((pb.x >> 17) & 31) << 7) + lane * 4;
                float4 rka = *(float4*)(s_rqk + cba);
                float4 rkb = *(float4*)(s_rqk + cbb);
                float4 rva = *(float4*)(s_rvv + cba);
                float4 rvb = *(float4*)(s_rvv + cbb);

                __half2* ha = (__half2*)&kva;
                __half2* hb = (__half2*)&kvb;
                float2 ka01 = __half22float2(ha[0]), ka23 = __half22float2(ha[1]);
                float2 va01 = __half22float2(ha[2]), va23 = __half22float2(ha[3]);
                float2 kb01 = __half22float2(hb[0]), kb23 = __half22float2(hb[1]);
                float2 vb01 = __half22float2(hb[2]), vb23 = __half22float2(hb[3]);

                float sa = q4.x * ka01.x * rka.x + q4.y * ka01.y * rka.y
                         + q4.z * ka23.x * rka.z + q4.w * ka23.y * rka.w;
                float sb = q4.x * kb01.x * rkb.x + q4.y * kb01.y * rkb.y
                         + q4.z * kb23.x * rkb.z + q4.w * kb23.y * rkb.w;
                sa += __shfl_xor_sync(0xffffffffu, sa, 1);
                sa += __shfl_xor_sync(0xffffffffu, sa, 2);
                sb += __shfl_xor_sync(0xffffffffu, sb, 1);
                sb += __shfl_xor_sync(0xffffffffu, sb, 2);

                float ea = __expf(sa * 0.25f + s_rb[((pa.x >> 22) & 7) * 8 + h] + __int_as_float(pa.y));
                float eb = __expf(sb * 0.25f + s_rb[((pb.x >> 22) & 7) * 8 + h] + __int_as_float(pb.y));
                z += ea + eb;
                oa.x += va01.x * rva.x * ea + vb01.x * rvb.x * eb;
                oa.y += va01.y * rva.y * ea + vb01.y * rvb.y * eb;
                oa.z += va23.x * rva.z * ea + vb23.x * rvb.z * eb;
                oa.w += va23.y * rva.w * ea + vb23.y * rvb.w * eb;

                pa = qa; pb = qb;
            }
            if (j < deg) {
                int2 p = g_epk[start + j];
                int s_i = p.x & 0x1FFFF;
                uint4 kv = *(const uint4*)(g_KVh + (size_t)s_i * 256 + lane * 8);
                int cb = (((p.x >> 17) & 31) << 7) + lane * 4;
                float4 rk4 = *(float4*)(s_rqk + cb);
                float4 rv4 = *(float4*)(s_rvv + cb);

                __half2* hh = (__half2*)&kv;
                float2 k01 = __half22float2(hh[0]), k23 = __half22float2(hh[1]);
                float2 v01 = __half22float2(hh[2]), v23 = __half22float2(hh[3]);

                float sc = q4.x * k01.x * rk4.x + q4.y * k01.y * rk4.y
                         + q4.z * k23.x * rk4.z + q4.w * k23.y * rk4.w;
                sc += __shfl_xor_sync(0xffffffffu, sc, 1);
                sc += __shfl_xor_sync(0xffffffffu, sc, 2);

                float es = __expf(sc * 0.25f + s_rb[((p.x >> 22) & 7) * 8 + h] + __int_as_float(p.y));
                z += es;
                oa.x += v01.x * rv4.x * es;
                oa.y += v01.y * rv4.y * es;
                oa.z += v23.x * rv4.z * es;
                oa.w += v23.y * rv4.w * es;
            }

            int t = ntype[n];
            float a = 1.f / (1.f + __expf(-__ldg(skip + t)));
            float b = 1.f - a;
            float r = a / (z + 1e-9f);

            float4 xi = *(const float4*)(x + (size_t)n * 128 + lane * 4);
            float4 xv;
            xv.x = oa.x * r + b * xi.x;
            xv.y = oa.y * r + b * xi.y;
            xv.z = oa.z * r + b * xi.z;
            xv.w = oa.w * r + b * xi.w;

            float s = xv.x + xv.y + xv.z + xv.w;
            #pragma unroll
            for (int o = 16; o; o >>= 1) s += __shfl_xor_sync(0xffffffffu, s, o);
            float mu = s * (1.f / 128.f);

            float dx0 = xv.x - mu, dx1 = xv.y - mu, dx2 = xv.z - mu, dx3 = xv.w - mu;
            float vs = dx0 * dx0 + dx1 * dx1 + dx2 * dx2 + dx3 * dx3;
            #pragma unroll
            for (int o = 16; o; o >>= 1) vs += __shfl_xor_sync(0xffffffffu, vs, o);
            float rs = rsqrtf(vs * (1.f / 128.f) + 1e-5f);

            float4 g4 = *(const float4*)(gamma + t * 128 + lane * 4);
            float4 be4 = *(const float4*)(beta + t * 128 + lane * 4);

            float4 y;
            y.x = dx0 * rs * g4.x + be4.x;
            y.y = dx1 * rs * g4.y + be4.y;
            y.z = dx2 * rs * g4.z + be4.z;
            y.w = dx3 * rs * g4.w + be4.w;

            *(float4*)(out + (size_t)n * 128 + lane * 4) = y;
        }
    }
}

// ---------------- launch ----------------
extern "C" void kernel_launch(void* const* d_in, const int* in_sizes, int n_in,
                              void* d_out, int out_size)
{
    const float* node_inp   = (const float*)d_in[0];
    const int*   node_type  = (const int*)d_in[1];
    const int*   edge_index = (const int*)d_in[2];
    const int*   edge_type  = (const int*)d_in[3];
    const int*   edge_sign  = (const int*)d_in[4];
    const float* edge_dist  = (const float*)d_in[5];
    const float* Wq = (const float*)d_in[6];
    const float* bq = (const float*)d_in[7];
    const float* Wk = (const float*)d_in[8];
    const float* bk = (const float*)d_in[9];
    const float* Wv = (const float*)d_in[10];
    const float* bv = (const float*)d_in[11];
    const float* rel_q   = (const float*)d_in[12];
    const float* rel_k   = (const float*)d_in[13];
    const float* rel_v   = (const float*)d_in[14];
    const float* rel_b   = (const float*)d_in[15];
    const float* skf     = (const float*)d_in[16];
    const float* svf     = (const float*)d_in[17];
    const float* skn     = (const float*)d_in[18];
    const float* svn     = (const float*)d_in[19];
    const float* d_alpha = (const float*)d_in[20];
    const float* d_tau   = (const float*)d_in[21];
    const float* skip    = (const float*)d_in[22];
    const float* ln_g    = (const float*)d_in[23];
    const float* ln_b    = (const float*)d_in[24];

    int N = in_sizes[1];
    int E = in_sizes[3];

    float* out = (float*)d_out;

    cudaFuncSetAttribute(k_qkv_mma, cudaFuncAttributeMaxDynamicSharedMemorySize, SM_TOTAL);

    int nb = (N + 255) / 256;
    int eb = (E + 255) / 256;

    k_init<<<nb, 256>>>(N);
    k_hist<<<eb, 256>>>(node_type, edge_index, N, E);
    k_off<<<nb, 256>>>(node_type, N);
    k_prep<<<eb + 72, 256>>>(edge_index, edge_type, edge_sign, edge_dist,
                             d_alpha, d_tau, Wq, Wk, Wv,
                             rel_q, rel_k, rel_v, skf, svf, skn, svn, E, eb);

    int qb = (N + 127) / 128;
    k_qkv_mma<<<qb, 256, SM_TOTAL>>>(node_inp, node_type, bq, bk, bv, N);

    k_attn<<<444, 256>>>(node_inp, node_type, rel_b, skip, ln_g, ln_b, out, N);
}

// round 11
// speedup vs baseline: 3.0993x; 1.0490x over previous
#include <cuda_runtime.h>
#include <cuda_fp16.h>
#include <cstdint>

#define NMAX 100000
#define EMAX 800000

// -------- scratch (static __device__, no allocation) --------
__device__ __half g_Qh[NMAX * 128];
__device__ __half g_KVh[NMAX * 256];   // interleaved: [k0..3 v0..3 k4..7 v4..7 ...]
__device__ int   g_perm[NMAX];
__device__ int   g_cnt[3];
__device__ int   g_cnt2[3];
__device__ int   g_total;
__device__ int   g_wq;                 // dynamic work cursor for attn
// CSR by destination
__device__ int   g_deg[NMAX];
__device__ int   g_off[NMAX];
__device__ int   g_cur2[NMAX];
__device__ __align__(8) int2 g_epk[EMAX];   // {src|comb<<17|et<<22, phi_bits}
// pre-packed fp16 weights in mma.sync B-fragment order
__device__ __align__(16) uint4 g_Bpk[3][3][2048];
// precomputed rel/sign tables: [et*3+sidx][128]
__device__ __align__(16) float g_tqk[3072];
__device__ __align__(16) float g_tv[3072];

// ---------------- helpers ----------------
__device__ __forceinline__ uint32_t pack_half(float a, float b) {
    __half2 t = __floats2half2_rn(a, b);
    return *(uint32_t*)&t;
}

__device__ __forceinline__ void mma16816h(float* c,
    uint32_t a0, uint32_t a1, uint32_t a2, uint32_t a3,
    uint32_t b0, uint32_t b1)
{
    asm volatile(
        "mma.sync.aligned.m16n8k16.row.col.f32.f16.f16.f32 "
        "{%0,%1,%2,%3}, {%4,%5,%6,%7}, {%8,%9}, {%0,%1,%2,%3};"
        : "+f"(c[0]), "+f"(c[1]), "+f"(c[2]), "+f"(c[3])
        : "r"(a0), "r"(a1), "r"(a2), "r"(a3), "r"(b0), "r"(b1));
}

__device__ __forceinline__ uint32_t s2u(const void* p) {
    uint32_t a;
    asm("{ .reg .u64 t; cvta.to.shared.u64 t, %1; cvt.u32.u64 %0, t; }" : "=r"(a) : "l"(p));
    return a;
}

__device__ __forceinline__ void cp16(uint32_t s, const void* g) {
    asm volatile("cp.async.cg.shared.global [%0], [%1], 16;" :: "r"(s), "l"(g));
}

// ---------------- K1: init ----------------
__global__ void k_init(int N) {
    int i = blockIdx.x * blockDim.x + threadIdx.x;
    if (i < N) g_deg[i] = 0;
    if (i < 3) { g_cnt[i] = 0; g_cnt2[i] = 0; }
    if (i == 3) g_total = 0;
    if (i == 4) g_wq = 0;
}

// ---------------- K2: fused histograms + weight pack + tables ----------------
__global__ void k_histpack(const int* __restrict__ ntype, const int* __restrict__ ei,
                           const float* __restrict__ Wq, const float* __restrict__ Wk,
                           const float* __restrict__ Wv,
                           const float* __restrict__ rq, const float* __restrict__ rk,
                           const float* __restrict__ rv,
                           const float* __restrict__ skf, const float* __restrict__ svf,
                           const float* __restrict__ skn, const float* __restrict__ svn,
                           int N, int E, int EB)
{
    int tid = threadIdx.x;
    if ((int)blockIdx.x < EB) {
        __shared__ int h[3];
        if (tid < 3) h[tid] = 0;
        __syncthreads();
        int i = blockIdx.x * blockDim.x + tid;
        if (i < N) atomicAdd(&h[ntype[i]], 1);
        if (i < E) atomicAdd(&g_deg[ei[E + i]], 1);
        __syncthreads();
        if (tid < 3 && h[tid]) atomicAdd(&g_cnt[tid], h[tid]);
        return;
    }

    int gid = (blockIdx.x - EB) * blockDim.x + tid;
    if (gid < 3072) {
        int c = gid >> 7, d = gid & 127;
        int et = c / 3, s = c - et * 3;
        float sk = (s < 2) ? skf[s * 128 + d] : skn[d];
        float sv = (s < 2) ? svf[s * 128 + d] : svn[d];
        g_tqk[gid] = rq[et * 128 + d] * rk[et * 128 + d] * sk;
        g_tv[gid]  = rv[et * 128 + d] * sv;
    }
    if (gid >= 3 * 3 * 2048) return;
    int t = gid / 6144;
    int m = (gid % 6144) / 2048;
    int w = gid % 2048;
    int kt = w >> 8;
    int np = (w >> 5) & 7;
    int lane = w & 31;

    const float* W = (m == 0 ? Wq : (m == 1 ? Wk : Wv)) + (size_t)t * 16384;
    int k0 = kt * 16 + (lane & 3) * 2;
    int n0 = (2 * np) * 8 + (lane >> 2);

    uint4 hi;
    uint32_t* hp = (uint32_t*)&hi;
    #pragma unroll
    for (int j = 0; j < 2; ++j) {
        int n = n0 + j * 8;
        #pragma unroll
        for (int g = 0; g < 2; ++g) {
            float v0 = W[(k0 + g * 8) * 128 + n];
            float v1 = W[(k0 + g * 8 + 1) * 128 + n];
            hp[j * 2 + g] = pack_half(v0, v1);
        }
    }
    g_Bpk[t][m][w] = hi;
}

// ---------------- K3: CSR offsets + type-scatter ----------------
__global__ void __launch_bounds__(256) k_off(const int* __restrict__ ntype, int N) {
    __shared__ int sws[8];
    __shared__ int sbase;
    __shared__ int h[3], tb[3];

    int tid = threadIdx.x;
    int lane = tid & 31, w = tid >> 5;
    int i = blockIdx.x * 256 + tid;
    int d = (i < N) ? g_deg[i] : 0;

    int inc = d;
    #pragma unroll
    for (int o = 1; o < 32; o <<= 1) {
        int t = __shfl_up_sync(0xffffffffu, inc, o);
        if (lane >= o) inc += t;
    }
    if (lane == 31) sws[w] = inc;
    if (tid < 3) h[tid] = 0;
    __syncthreads();
    if (tid == 0) {
        int run = 0;
        #pragma unroll
        for (int k = 0; k < 8; ++k) { int t = sws[k]; sws[k] = run; run += t; }
        sbase = atomicAdd(&g_total, run);
    }
    __syncthreads();
    int ex = sbase + sws[w] + inc - d;
    if (i < N) { g_off[i] = ex; g_cur2[i] = ex; }

    int t = 0, r = 0;
    if (i < N) { t = ntype[i]; r = atomicAdd(&h[t], 1); }
    __syncthreads();
    if (tid < 3 && h[tid]) tb[tid] = atomicAdd(&g_cnt2[tid], h[tid]);
    __syncthreads();
    if (i < N) {
        int base = (t == 0) ? 0 : ((t == 1) ? g_cnt[0] : (g_cnt[0] + g_cnt[1]));
        g_perm[base + tb[t] + r] = i;
    }
}

// ---------------- K4: tensor-core QKV, fp16, double-buffered B ----------
#define SM_A   0
#define SM_B0  32768
#define SM_B1  65536
#define SM_META 98304
#define SM_TOTAL (SM_META + 1024)

__device__ __forceinline__ void copyB(uint32_t dst, const uint4* src, int tid) {
    #pragma unroll
    for (int i = tid; i < 2048; i += 256) cp16(dst + i * 16, src + i);
    asm volatile("cp.async.commit_group;");
}

__global__ void __launch_bounds__(256) k_qkv_mma(
    const float* __restrict__ x, const int* __restrict__ ntype,
    const float* __restrict__ bq, const float* __restrict__ bk,
    const float* __restrict__ bv, int N)
{
    extern __shared__ __align__(16) unsigned char sm[];
    uint32_t smb = s2u(sm);
    uint32_t* Af  = (uint32_t*)(sm + SM_A);
    float*    raw = (float*)(sm + SM_B0);    // staging reuses B region (33792 B)
    int* sp = (int*)(sm + SM_META);
    int* st = sp + 128;

    int tid = threadIdx.x;
    int wid = tid >> 5;
    int lane = tid & 31;

    int start = blockIdx.x * 128;
    int count = N - start; if (count > 128) count = 128;

    if (tid < count) {
        int pn = g_perm[start + tid];
        sp[tid] = pn;
        st[tid] = ntype[pn];
    }
    __syncthreads();

    // A pack via staged coalesced loads: 2 chunks of 64 rows
    #pragma unroll
    for (int chunk = 0; chunk < 2; ++chunk) {
        for (int i = tid; i < 2048; i += 256) {
            int row = i >> 5, col = i & 31;
            int gr = chunk * 64 + row;
            float4 v = make_float4(0.f, 0.f, 0.f, 0.f);
            if (gr < count) v = *(const float4*)(x + (size_t)sp[gr] * 128 + col * 4);
            *(float4*)(raw + row * 132 + col * 4) = v;
        }
        __syncthreads();
        {
            int q = tid & 3, row = tid >> 2;
            int gr = chunk * 64 + row;
            int mt = gr >> 4, rr = gr & 15;
            #pragma unroll
            for (int p = 0; p < 16; ++p) {
                int c = q + 4 * p;
                float v0 = raw[row * 132 + 2 * c];
                float v1 = raw[row * 132 + 2 * c + 1];
                int kt = c >> 3, cc = c & 7;
                int wl = (rr & 7) * 4 + (cc & 3);
                int slot = (rr >> 3) | ((cc >> 2) << 1);
                int idx = (((kt * 8 + mt) * 32 + wl) << 2) + slot;
                Af[idx] = pack_half(v0, v1);
            }
        }
        __syncthreads();
    }

    int tmin = st[0], tmax = st[count - 1];
    int niter = 3 * (tmax - tmin + 1);

    // prefetch first B into buffer 0
    copyB(smb + SM_B0, g_Bpk[tmin][0], tid);

    for (int it = 0; it < niter; ++it) {
        int t = tmin + it / 3;
        int m = it % 3;
        uint4* Bb = (uint4*)(sm + ((it & 1) ? SM_B1 : SM_B0));

        if (it + 1 < niter) {
            int t2 = tmin + (it + 1) / 3;
            int m2 = (it + 1) % 3;
            copyB(smb + ((it & 1) ? SM_B0 : SM_B1), g_Bpk[t2][m2], tid);
            asm volatile("cp.async.wait_group 1;" ::: "memory");
        } else {
            asm volatile("cp.async.wait_group 0;" ::: "memory");
        }
        __syncthreads();

        float acc[16][4];
        #pragma unroll
        for (int i = 0; i < 16; ++i)
            #pragma unroll
            for (int j = 0; j < 4; ++j) acc[i][j] = 0.f;

        #pragma unroll
        for (int kt = 0; kt < 8; ++kt) {
            uint4 ah = *(uint4*)(Af + (((kt * 8 + wid) * 32 + lane) << 2));
            #pragma unroll
            for (int np = 0; np < 8; ++np) {
                uint4 bh = Bb[(kt * 8 + np) * 32 + lane];
                mma16816h(acc[2 * np],     ah.x, ah.y, ah.z, ah.w, bh.x, bh.y);
                mma16816h(acc[2 * np + 1], ah.x, ah.y, ah.z, ah.w, bh.z, bh.w);
            }
        }

        // ---- epilogue (all fp16 outputs) ----
        const float* bias = (m == 0 ? bq : (m == 1 ? bk : bv)) + t * 128;
        int row0 = wid * 16 + (lane >> 2);
        int row1 = row0 + 8;
        bool v0ok = (row0 < count) && (st[row0] == t);
        bool v1ok = (row1 < count) && (st[row1] == t);
        int cbase = (lane & 3) * 2;

        __half* d0;
        __half* d1;
        bool interleave;
        if (m == 0) {
            d0 = v0ok ? (g_Qh + (size_t)sp[row0] * 128) : nullptr;
            d1 = v1ok ? (g_Qh + (size_t)sp[row1] * 128) : nullptr;
            interleave = false;
        } else {
            int moff = (m == 2) ? 4 : 0;
            d0 = v0ok ? (g_KVh + (size_t)sp[row0] * 256 + moff) : nullptr;
            d1 = v1ok ? (g_KVh + (size_t)sp[row1] * 256 + moff) : nullptr;
            interleave = true;
        }
        #pragma unroll
        for (int nt = 0; nt < 16; ++nt) {
            int c = nt * 8 + cbase;
            int off = interleave ? (((c >> 2) << 3) + (c & 3)) : c;
            float2 b2 = __ldg((const float2*)(bias + c));
            if (v0ok)
                *(__half2*)(d0 + off) = __floats2half2_rn(acc[nt][0] + b2.x, acc[nt][1] + b2.y);
            if (v1ok)
                *(__half2*)(d1 + off) = __floats2half2_rn(acc[nt][2] + b2.x, acc[nt][3] + b2.y);
        }
        __syncthreads();   // all warps done with Bb before it gets overwritten
    }
}

// ---------------- K5: edge payload scatter ----------------
__global__ void k_escatter(const int* __restrict__ ei, const int* __restrict__ etype,
                           const int* __restrict__ esign, const float* __restrict__ edist,
                           const float* __restrict__ alphap, const float* __restrict__ taup,
                           int E)
{
    int e = blockIdx.x * blockDim.x + threadIdx.x;
    if (e >= E) return;
    int dst = ei[E + e];
    int src = ei[e];
    int et = etype[e];
    int sg = esign[e];
    int sidx = (sg == -1) ? 0 : ((sg == 1) ? 1 : 2);
    float alpha = __ldg(alphap);
    float itau = 1.f / (__ldg(taup) + 1e-9f);
    float phi = alpha * __expf(-edist[e] * itau);
    int pos = atomicAdd(&g_cur2[dst], 1);
    int w = src | ((et * 3 + sidx) << 17) | (et << 22);
    g_epk[pos] = make_int2(w, __float_as_int(phi));
}

// ---------------- K6: fused gather-attention + residual + LN ----------
__global__ void __launch_bounds__(256) k_attn(
    const float* __restrict__ x, const int* __restrict__ ntype,
    const float* __restrict__ rbias,
    const float* __restrict__ skip, const float* __restrict__ gamma,
    const float* __restrict__ beta, float* __restrict__ out, int N)
{
    __shared__ __align__(16) float s_rqk[3072];
    __shared__ __align__(16) float s_rvv[3072];
    __shared__ float s_rb[64];

    int tid = threadIdx.x;
    {
        const uint4* sq = (const uint4*)g_tqk;
        const uint4* sv = (const uint4*)g_tv;
        uint4* dq = (uint4*)s_rqk;
        uint4* dv = (uint4*)s_rvv;
        #pragma unroll 3
        for (int i = tid; i < 768; i += 256) { dq[i] = sq[i]; dv[i] = sv[i]; }
    }
    if (tid < 64) s_rb[tid] = rbias[tid];
    __syncthreads();

    int lane = tid & 31;
    int h = lane >> 2;

    for (;;) {
        int base = 0;
        if (lane == 0) base = atomicAdd(&g_wq, 4);
        base = __shfl_sync(0xffffffffu, base, 0);
        if (base >= N) return;
        int stop = base + 4; if (stop > N) stop = N;

        for (int n = base; n < stop; ++n) {
            float4 q4;
            {
                uint2 qr = *(const uint2*)(g_Qh + (size_t)n * 128 + lane * 4);
                __half2* qh = (__half2*)&qr;
                float2 q01 = __half22float2(qh[0]), q23 = __half22float2(qh[1]);
                q4 = make_float4(q01.x, q01.y, q23.x, q23.y);
            }
            int start = g_off[n];
            int deg = g_deg[n];

            float4 oa = make_float4(0.f, 0.f, 0.f, 0.f);
            float z = 0.f;

            int j = 0;
            // 4-wide edge loop: 4 independent KV gathers in flight
            for (; j + 3 < deg; j += 4) {
                int2 p0 = g_epk[start + j + 0];
                int2 p1 = g_epk[start + j + 1];
                int2 p2 = g_epk[start + j + 2];
                int2 p3 = g_epk[start + j + 3];

                uint4 kv0 = *(const uint4*)(g_KVh + (size_t)(p0.x & 0x1FFFF) * 256 + lane * 8);
                uint4 kv1 = *(const uint4*)(g_KVh + (size_t)(p1.x & 0x1FFFF) * 256 + lane * 8);
                uint4 kv2 = *(const uint4*)(g_KVh + (size_t)(p2.x & 0x1FFFF) * 256 + lane * 8);
                uint4 kv3 = *(const uint4*)(g_KVh + (size_t)(p3.x & 0x1FFFF) * 256 + lane * 8);

                int cb0 = (((p0.x >> 17) & 31) << 7) + lane * 4;
                int cb1 = (((p1.x >> 17) & 31) << 7) + lane * 4;
                int cb2 = (((p2.x >> 17) & 31) << 7) + lane * 4;
                int cb3 = (((p3.x >> 17) & 31) << 7) + lane * 4;

                float4 rk0 = *(float4*)(s_rqk + cb0);
                float4 rk1 = *(float4*)(s_rqk + cb1);
                float4 rk2 = *(float4*)(s_rqk + cb2);
                float4 rk3 = *(float4*)(s_rqk + cb3);

                __half2* h0 = (__half2*)&kv0;
                __half2* h1 = (__half2*)&kv1;
                __half2* h2 = (__half2*)&kv2;
                __half2* h3 = (__half2*)&kv3;

                float2 k0a = __half22float2(h0[0]), k0b = __half22float2(h0[1]);
                float2 k1a = __half22float2(h1[0]), k1b = __half22float2(h1[1]);
                float2 k2a = __half22float2(h2[0]), k2b = __half22float2(h2[1]);
                float2 k3a = __half22float2(h3[0]), k3b = __half22float2(h3[1]);

                float s0 = q4.x * k0a.x * rk0.x + q4.y * k0a.y * rk0.y
                         + q4.z * k0b.x * rk0.z + q4.w * k0b.y * rk0.w;
                float s1 = q4.x * k1a.x * rk1.x + q4.y * k1a.y * rk1.y
                         + q4.z * k1b.x * rk1.z + q4.w * k1b.y * rk1.w;
                float s2 = q4.x * k2a.x * rk2.x + q4.y * k2a.y * rk2.y
                         + q4.z * k2b.x * rk2.z + q4.w * k2b.y * rk2.w;
                float s3 = q4.x * k3a.x * rk3.x + q4.y * k3a.y * rk3.y
                         + q4.z * k3b.x * rk3.z + q4.w * k3b.y * rk3.w;

                s0 += __shfl_xor_sync(0xffffffffu, s0, 1);
                s1 += __shfl_xor_sync(0xffffffffu, s1, 1);
                s2 += __shfl_xor_sync(0xffffffffu, s2, 1);
                s3 += __shfl_xor_sync(0xffffffffu, s3, 1);
                s0 += __shfl_xor_sync(0xffffffffu, s0, 2);
                s1 += __shfl_xor_sync(0xffffffffu, s1, 2);
                s2 += __shfl_xor_sync(0xffffffffu, s2, 2);
                s3 += __shfl_xor_sync(0xffffffffu, s3, 2);

                float e0 = __expf(s0 * 0.25f + s_rb[((p0.x >> 22) & 7) * 8 + h] + __int_as_float(p0.y));
                float e1 = __expf(s1 * 0.25f + s_rb[((p1.x >> 22) & 7) * 8 + h] + __int_as_float(p1.y));
                float e2 = __expf(s2 * 0.25f + s_rb[((p2.x >> 22) & 7) * 8 + h] + __int_as_float(p2.y));
                float e3 = __expf(s3 * 0.25f + s_rb[((p3.x >> 22) & 7) * 8 + h] + __int_as_float(p3.y));
                z += (e0 + e1) + (e2 + e3);

                float4 rv0 = *(float4*)(s_rvv + cb0);
                float4 rv1 = *(float4*)(s_rvv + cb1);
                float4 rv2 = *(float4*)(s_rvv + cb2);
                float4 rv3 = *(float4*)(s_rvv + cb3);

                float2 v0a = __half22float2(h0[2]), v0b = __half22float2(h0[3]);
                float2 v1a = __half22float2(h1[2]), v1b = __half22float2(h1[3]);
                float2 v2a = __half22float2(h2[2]), v2b = __half22float2(h2[3]);
                float2 v3a = __half22float2(h3[2]), v3b = __half22float2(h3[3]);

                oa.x += v0a.x * rv0.x * e0 + v1a.x * rv1.x * e1
                      + v2a.x * rv2.x * e2 + v3a.x * rv3.x * e3;
                oa.y += v0a.y * rv0.y * e0 + v1a.y * rv1.y * e1
                      + v2a.y * rv2.y * e2 + v3a.y * rv3.y * e3;
                oa.z += v0b.x * rv0.z * e0 + v1b.x * rv1.z * e1
                      + v2b.x * rv2.z * e2 + v3b.x * rv3.z * e3;
                oa.w += v0b.y * rv0.w * e0 + v1b.y * rv1.w * e1
                      + v2b.y * rv2.w * e2 + v3b.y * rv3.w * e3;
            }
            for (; j < deg; ++j) {
                int2 p = g_epk[start + j];
                uint4 kv = *(const uint4*)(g_KVh + (size_t)(p.x & 0x1FFFF) * 256 + lane * 8);
                int cb = (((p.x >> 17) & 31) << 7) + lane * 4;
                float4 rk4 = *(float4*)(s_rqk + cb);
                float4 rv4 = *(float4*)(s_rvv + cb);

                __half2* hh = (__half2*)&kv;
                float2 k01 = __half22float2(hh[0]), k23 = __half22float2(hh[1]);
                float2 v01 = __half22float2(hh[2]), v23 = __half22float2(hh[3]);

                float sc = q4.x * k01.x * rk4.x + q4.y * k01.y * rk4.y
                         + q4.z * k23.x * rk4.z + q4.w * k23.y * rk4.w;
                sc += __shfl_xor_sync(0xffffffffu, sc, 1);
                sc += __shfl_xor_sync(0xffffffffu, sc, 2);

                float es = __expf(sc * 0.25f + s_rb[((p.x >> 22) & 7) * 8 + h] + __int_as_float(p.y));
                z += es;
                oa.x += v01.x * rv4.x * es;
                oa.y += v01.y * rv4.y * es;
                oa.z += v23.x * rv4.z * es;
                oa.w += v23.y * rv4.w * es;
            }

            int t = ntype[n];
            float a = 1.f / (1.f + __expf(-__ldg(skip + t)));
            float b = 1.f - a;
            float r = a / (z + 1e-9f);

            float4 xi = *(const float4*)(x + (size_t)n * 128 + lane * 4);
            float4 xv;
            xv.x = oa.x * r + b * xi.x;
            xv.y = oa.y * r + b * xi.y;
            xv.z = oa.z * r + b * xi.z;
            xv.w = oa.w * r + b * xi.w;

            float s = xv.x + xv.y + xv.z + xv.w;
            #pragma unroll
            for (int o = 16; o; o >>= 1) s += __shfl_xor_sync(0xffffffffu, s, o);
            float mu = s * (1.f / 128.f);

            float dx0 = xv.x - mu, dx1 = xv.y - mu, dx2 = xv.z - mu, dx3 = xv.w - mu;
            float vs = dx0 * dx0 + dx1 * dx1 + dx2 * dx2 + dx3 * dx3;
            #pragma unroll
            for (int o = 16; o; o >>= 1) vs += __shfl_xor_sync(0xffffffffu, vs, o);
            float rs = rsqrtf(vs * (1.f / 128.f) + 1e-5f);

            float4 g4 = *(const float4*)(gamma + t * 128 + lane * 4);
            float4 be4 = *(const float4*)(beta + t * 128 + lane * 4);

            float4 y;
            y.x = dx0 * rs * g4.x + be4.x;
            y.y = dx1 * rs * g4.y + be4.y;
            y.z = dx2 * rs * g4.z + be4.z;
            y.w = dx3 * rs * g4.w + be4.w;

            *(float4*)(out + (size_t)n * 128 + lane * 4) = y;
        }
    }
}

// ---------------- launch ----------------
extern "C" void kernel_launch(void* const* d_in, const int* in_sizes, int n_in,
                              void* d_out, int out_size)
{
    const float* node_inp   = (const float*)d_in[0];
    const int*   node_type  = (const int*)d_in[1];
    const int*   edge_index = (const int*)d_in[2];
    const int*   edge_type  = (const int*)d_in[3];
    const int*   edge_sign  = (const int*)d_in[4];
    const float* edge_dist  = (const float*)d_in[5];
    const float* Wq = (const float*)d_in[6];
    const float* bq = (const float*)d_in[7];
    const float* Wk = (const float*)d_in[8];
    const float* bk = (const float*)d_in[9];
    const float* Wv = (const float*)d_in[10];
    const float* bv = (const float*)d_in[11];
    const float* rel_q   = (const float*)d_in[12];
    const float* rel_k   = (const float*)d_in[13];
    const float* rel_v   = (const float*)d_in[14];
    const float* rel_b   = (const float*)d_in[15];
    const float* skf     = (const float*)d_in[16];
    const float* svf     = (const float*)d_in[17];
    const float* skn     = (const float*)d_in[18];
    const float* svn     = (const float*)d_in[19];
    const float* d_alpha = (const float*)d_in[20];
    const float* d_tau   = (const float*)d_in[21];
    const float* skip    = (const float*)d_in[22];
    const float* ln_g    = (const float*)d_in[23];
    const float* ln_b    = (const float*)d_in[24];

    int N = in_sizes[1];
    int E = in_sizes[3];

    float* out = (float*)d_out;

    cudaFuncSetAttribute(k_qkv_mma, cudaFuncAttributeMaxDynamicSharedMemorySize, SM_TOTAL);

    int nb = (N + 255) / 256;
    int eb = (E + 255) / 256;

    k_init<<<nb, 256>>>(N);
    k_histpack<<<eb + 72, 256>>>(node_type, edge_index, Wq, Wk, Wv,
                                 rel_q, rel_k, rel_v, skf, svf, skn, svn, N, E, eb);
    k_off<<<nb, 256>>>(node_type, N);

    int qb = (N + 127) / 128;
    k_qkv_mma<<<qb, 256, SM_TOTAL>>>(node_inp, node_type, bq, bk, bv, N);

    k_escatter<<<eb, 256>>>(edge_index, edge_type, edge_sign, edge_dist,
                            d_alpha, d_tau, E);

    k_attn<<<444, 256>>>(node_inp, node_type, rel_b, skip, ln_g, ln_b, out, N);
}

// round 12
// speedup vs baseline: 3.1607x; 1.0198x over previous
#include <cuda_runtime.h>
#include <cuda_fp16.h>
#include <cstdint>

#define NMAX 100000
#define EMAX 800000

// -------- scratch (static __device__, no allocation) --------
__device__ __half g_Qh[NMAX * 128];
__device__ __half g_KVh[NMAX * 256];   // interleaved: [k0..3 v0..3 k4..7 v4..7 ...]
__device__ int   g_perm[NMAX];
__device__ int   g_cnt[3];
__device__ int   g_cnt2[3];
__device__ int   g_total;
__device__ int   g_wq;                 // dynamic work cursor for attn
// CSR by destination
__device__ int   g_deg[NMAX];
__device__ int   g_off[NMAX];
__device__ int   g_cur2[NMAX];
__device__ __align__(8) int2 g_epk[EMAX];   // {src|comb<<17|et<<22, phi_bits}
// pre-packed fp16 weights in mma.sync B-fragment order
__device__ __align__(16) uint4 g_Bpk[3][3][2048];
// precomputed rel/sign tables: [et*3+sidx][128]
__device__ __align__(16) float g_tqk[3072];
__device__ __align__(16) float g_tv[3072];

// ---------------- helpers ----------------
__device__ __forceinline__ uint32_t pack_half(float a, float b) {
    __half2 t = __floats2half2_rn(a, b);
    return *(uint32_t*)&t;
}

__device__ __forceinline__ void mma16816h(float* c,
    uint32_t a0, uint32_t a1, uint32_t a2, uint32_t a3,
    uint32_t b0, uint32_t b1)
{
    asm volatile(
        "mma.sync.aligned.m16n8k16.row.col.f32.f16.f16.f32 "
        "{%0,%1,%2,%3}, {%4,%5,%6,%7}, {%8,%9}, {%0,%1,%2,%3};"
        : "+f"(c[0]), "+f"(c[1]), "+f"(c[2]), "+f"(c[3])
        : "r"(a0), "r"(a1), "r"(a2), "r"(a3), "r"(b0), "r"(b1));
}

__device__ __forceinline__ uint32_t s2u(const void* p) {
    uint32_t a;
    asm("{ .reg .u64 t; cvta.to.shared.u64 t, %1; cvt.u32.u64 %0, t; }" : "=r"(a) : "l"(p));
    return a;
}

__device__ __forceinline__ void cp16(uint32_t s, const void* g) {
    asm volatile("cp.async.cg.shared.global [%0], [%1], 16;" :: "r"(s), "l"(g));
}

// ---------------- K1: init ----------------
__global__ void k_init(int N) {
    int i = blockIdx.x * blockDim.x + threadIdx.x;
    if (i < N) g_deg[i] = 0;
    if (i < 3) { g_cnt[i] = 0; g_cnt2[i] = 0; }
    if (i == 3) g_total = 0;
    if (i == 4) g_wq = 0;
}

// ---------------- K2: fused histograms + weight pack + tables ----------------
__global__ void k_histpack(const int* __restrict__ ntype, const int* __restrict__ ei,
                           const float* __restrict__ Wq, const float* __restrict__ Wk,
                           const float* __restrict__ Wv,
                           const float* __restrict__ rq, const float* __restrict__ rk,
                           const float* __restrict__ rv,
                           const float* __restrict__ skf, const float* __restrict__ svf,
                           const float* __restrict__ skn, const float* __restrict__ svn,
                           int N, int E, int EB)
{
    int tid = threadIdx.x;
    if ((int)blockIdx.x < EB) {
        __shared__ int h[3];
        if (tid < 3) h[tid] = 0;
        __syncthreads();
        int i = blockIdx.x * blockDim.x + tid;
        if (i < N) atomicAdd(&h[ntype[i]], 1);
        if (i < E) atomicAdd(&g_deg[ei[E + i]], 1);
        __syncthreads();
        if (tid < 3 && h[tid]) atomicAdd(&g_cnt[tid], h[tid]);
        return;
    }

    int gid = (blockIdx.x - EB) * blockDim.x + tid;
    if (gid < 3072) {
        int c = gid >> 7, d = gid & 127;
        int et = c / 3, s = c - et * 3;
        float sk = (s < 2) ? skf[s * 128 + d] : skn[d];
        float sv = (s < 2) ? svf[s * 128 + d] : svn[d];
        g_tqk[gid] = rq[et * 128 + d] * rk[et * 128 + d] * sk;
        g_tv[gid]  = rv[et * 128 + d] * sv;
    }
    if (gid >= 3 * 3 * 2048) return;
    int t = gid / 6144;
    int m = (gid % 6144) / 2048;
    int w = gid % 2048;
    int kt = w >> 8;
    int np = (w >> 5) & 7;
    int lane = w & 31;

    const float* W = (m == 0 ? Wq : (m == 1 ? Wk : Wv)) + (size_t)t * 16384;
    int k0 = kt * 16 + (lane & 3) * 2;
    int n0 = (2 * np) * 8 + (lane >> 2);

    uint4 hi;
    uint32_t* hp = (uint32_t*)&hi;
    #pragma unroll
    for (int j = 0; j < 2; ++j) {
        int n = n0 + j * 8;
        #pragma unroll
        for (int g = 0; g < 2; ++g) {
            float v0 = W[(k0 + g * 8) * 128 + n];
            float v1 = W[(k0 + g * 8 + 1) * 128 + n];
            hp[j * 2 + g] = pack_half(v0, v1);
        }
    }
    g_Bpk[t][m][w] = hi;
}

// ---------------- K3: CSR offsets + type-scatter ----------------
__global__ void __launch_bounds__(256) k_off(const int* __restrict__ ntype, int N) {
    __shared__ int sws[8];
    __shared__ int sbase;
    __shared__ int h[3], tb[3];

    int tid = threadIdx.x;
    int lane = tid & 31, w = tid >> 5;
    int i = blockIdx.x * 256 + tid;
    int d = (i < N) ? g_deg[i] : 0;

    int inc = d;
    #pragma unroll
    for (int o = 1; o < 32; o <<= 1) {
        int t = __shfl_up_sync(0xffffffffu, inc, o);
        if (lane >= o) inc += t;
    }
    if (lane == 31) sws[w] = inc;
    if (tid < 3) h[tid] = 0;
    __syncthreads();
    if (tid == 0) {
        int run = 0;
        #pragma unroll
        for (int k = 0; k < 8; ++k) { int t = sws[k]; sws[k] = run; run += t; }
        sbase = atomicAdd(&g_total, run);
    }
    __syncthreads();
    int ex = sbase + sws[w] + inc - d;
    if (i < N) { g_off[i] = ex; g_cur2[i] = ex; }

    int t = 0, r = 0;
    if (i < N) { t = ntype[i]; r = atomicAdd(&h[t], 1); }
    __syncthreads();
    if (tid < 3 && h[tid]) tb[tid] = atomicAdd(&g_cnt2[tid], h[tid]);
    __syncthreads();
    if (i < N) {
        int base = (t == 0) ? 0 : ((t == 1) ? g_cnt[0] : (g_cnt[0] + g_cnt[1]));
        g_perm[base + tb[t] + r] = i;
    }
}

// ---------------- K4: tensor-core QKV, A in registers, double-buffered B ------
#define SM_STAGE 0
#define SM_B0 33792
#define SM_B1 (33792 + 32768)
#define SM_META (33792 + 65536)
#define SM_TOTAL (SM_META + 1024)

__device__ __forceinline__ void copyB(uint32_t dst, const uint4* src, int tid) {
    #pragma unroll
    for (int i = tid; i < 2048; i += 256) cp16(dst + i * 16, src + i);
    asm volatile("cp.async.commit_group;");
}

__global__ void __launch_bounds__(256, 2) k_qkv_mma(
    const float* __restrict__ x, const int* __restrict__ ntype,
    const float* __restrict__ bq, const float* __restrict__ bk,
    const float* __restrict__ bv, int N)
{
    extern __shared__ __align__(16) unsigned char sm[];
    uint32_t smb = s2u(sm);
    float* raw = (float*)(sm + SM_STAGE);     // 64 rows x 132 floats
    int* sp = (int*)(sm + SM_META);
    int* st = sp + 128;

    int tid = threadIdx.x;
    int wid = tid >> 5;
    int lane = tid & 31;

    int start = blockIdx.x * 128;
    int count = N - start; if (count > 128) count = 128;

    if (tid < count) {
        int pn = g_perm[start + tid];
        sp[tid] = pn;
        st[tid] = ntype[pn];
    }
    __syncthreads();

    int tmin = st[0], tmax = st[count - 1];
    int niter = 3 * (tmax - tmin + 1);

    // prefetch first B while we stage A
    copyB(smb + SM_B0, g_Bpk[tmin][0], tid);

    // A fragments -> registers, 2 chunks of 64 rows through the staging buffer
    uint4 areg[8];
    #pragma unroll
    for (int chunk = 0; chunk < 2; ++chunk) {
        for (int i = tid; i < 2048; i += 256) {
            int row = i >> 5, col = i & 31;
            int gr = chunk * 64 + row;
            float4 v = make_float4(0.f, 0.f, 0.f, 0.f);
            if (gr < count) v = *(const float4*)(x + (size_t)sp[gr] * 128 + col * 4);
            *(float4*)(raw + row * 132 + col * 4) = v;
        }
        __syncthreads();
        if ((wid >> 2) == chunk) {
            int lr = (wid & 3) * 16 + (lane >> 2);
            int q2 = (lane & 3) * 2;
            #pragma unroll
            for (int kt = 0; kt < 8; ++kt) {
                const float* b0 = raw + lr * 132 + kt * 16 + q2;
                float2 f00 = *(const float2*)(b0);
                float2 f10 = *(const float2*)(b0 + 8 * 132);
                float2 f01 = *(const float2*)(b0 + 8);
                float2 f11 = *(const float2*)(b0 + 8 * 132 + 8);
                areg[kt].x = pack_half(f00.x, f00.y);
                areg[kt].y = pack_half(f10.x, f10.y);
                areg[kt].z = pack_half(f01.x, f01.y);
                areg[kt].w = pack_half(f11.x, f11.y);
            }
        }
        __syncthreads();
    }

    for (int it = 0; it < niter; ++it) {
        int t = tmin + it / 3;
        int m = it % 3;
        uint4* Bb = (uint4*)(sm + ((it & 1) ? SM_B1 : SM_B0));

        if (it + 1 < niter) {
            int t2 = tmin + (it + 1) / 3;
            int m2 = (it + 1) % 3;
            copyB(smb + ((it & 1) ? SM_B0 : SM_B1), g_Bpk[t2][m2], tid);
            asm volatile("cp.async.wait_group 1;" ::: "memory");
        } else {
            asm volatile("cp.async.wait_group 0;" ::: "memory");
        }
        __syncthreads();

        float acc[16][4];
        #pragma unroll
        for (int i = 0; i < 16; ++i)
            #pragma unroll
            for (int j = 0; j < 4; ++j) acc[i][j] = 0.f;

        #pragma unroll
        for (int kt = 0; kt < 8; ++kt) {
            uint4 ah = areg[kt];
            #pragma unroll
            for (int np = 0; np < 8; ++np) {
                uint4 bh = Bb[(kt * 8 + np) * 32 + lane];
                mma16816h(acc[2 * np],     ah.x, ah.y, ah.z, ah.w, bh.x, bh.y);
                mma16816h(acc[2 * np + 1], ah.x, ah.y, ah.z, ah.w, bh.z, bh.w);
            }
        }

        // ---- epilogue (all fp16 outputs) ----
        const float* bias = (m == 0 ? bq : (m == 1 ? bk : bv)) + t * 128;
        int row0 = wid * 16 + (lane >> 2);
        int row1 = row0 + 8;
        bool v0ok = (row0 < count) && (st[row0] == t);
        bool v1ok = (row1 < count) && (st[row1] == t);
        int cbase = (lane & 3) * 2;

        __half* d0;
        __half* d1;
        bool interleave;
        if (m == 0) {
            d0 = v0ok ? (g_Qh + (size_t)sp[row0] * 128) : nullptr;
            d1 = v1ok ? (g_Qh + (size_t)sp[row1] * 128) : nullptr;
            interleave = false;
        } else {
            int moff = (m == 2) ? 4 : 0;
            d0 = v0ok ? (g_KVh + (size_t)sp[row0] * 256 + moff) : nullptr;
            d1 = v1ok ? (g_KVh + (size_t)sp[row1] * 256 + moff) : nullptr;
            interleave = true;
        }
        #pragma unroll
        for (int nt = 0; nt < 16; ++nt) {
            int c = nt * 8 + cbase;
            int off = interleave ? (((c >> 2) << 3) + (c & 3)) : c;
            float2 b2 = __ldg((const float2*)(bias + c));
            if (v0ok)
                *(__half2*)(d0 + off) = __floats2half2_rn(acc[nt][0] + b2.x, acc[nt][1] + b2.y);
            if (v1ok)
                *(__half2*)(d1 + off) = __floats2half2_rn(acc[nt][2] + b2.x, acc[nt][3] + b2.y);
        }
        __syncthreads();   // all warps done with Bb before it gets overwritten
    }
}

// ---------------- K5: edge payload scatter ----------------
__global__ void k_escatter(const int* __restrict__ ei, const int* __restrict__ etype,
                           const int* __restrict__ esign, const float* __restrict__ edist,
                           const float* __restrict__ alphap, const float* __restrict__ taup,
                           int E)
{
    int e = blockIdx.x * blockDim.x + threadIdx.x;
    if (e >= E) return;
    int dst = ei[E + e];
    int src = ei[e];
    int et = etype[e];
    int sg = esign[e];
    int sidx = (sg == -1) ? 0 : ((sg == 1) ? 1 : 2);
    float alpha = __ldg(alphap);
    float itau = 1.f / (__ldg(taup) + 1e-9f);
    float phi = alpha * __expf(-edist[e] * itau);
    int pos = atomicAdd(&g_cur2[dst], 1);
    int w = src | ((et * 3 + sidx) << 17) | (et << 22);
    g_epk[pos] = make_int2(w, __float_as_int(phi));
}

// ---------------- K6: fused gather-attention + residual + LN ----------
__global__ void __launch_bounds__(256) k_attn(
    const float* __restrict__ x, const int* __restrict__ ntype,
    const float* __restrict__ rbias,
    const float* __restrict__ skip, const float* __restrict__ gamma,
    const float* __restrict__ beta, float* __restrict__ out, int N)
{
    __shared__ __align__(16) float s_rqk[3072];
    __shared__ __align__(16) float s_rvv[3072];
    __shared__ float s_rb[64];

    int tid = threadIdx.x;
    {
        const uint4* sq = (const uint4*)g_tqk;
        const uint4* sv = (const uint4*)g_tv;
        uint4* dq = (uint4*)s_rqk;
        uint4* dv = (uint4*)s_rvv;
        #pragma unroll 3
        for (int i = tid; i < 768; i += 256) { dq[i] = sq[i]; dv[i] = sv[i]; }
    }
    if (tid < 64) s_rb[tid] = rbias[tid];
    __syncthreads();

    int lane = tid & 31;
    int h = lane >> 2;

    for (;;) {
        int base = 0;
        if (lane == 0) base = atomicAdd(&g_wq, 4);
        base = __shfl_sync(0xffffffffu, base, 0);
        if (base >= N) return;
        int stop = base + 4; if (stop > N) stop = N;

        for (int n = base; n < stop; ++n) {
            float4 q4;
            {
                uint2 qr = *(const uint2*)(g_Qh + (size_t)n * 128 + lane * 4);
                __half2* qh = (__half2*)&qr;
                float2 q01 = __half22float2(qh[0]), q23 = __half22float2(qh[1]);
                q4 = make_float4(q01.x, q01.y, q23.x, q23.y);
            }
            int start = g_off[n];
            int deg = g_deg[n];

            float4 oa = make_float4(0.f, 0.f, 0.f, 0.f);
            float z = 0.f;

            int j = 0;
            for (; j + 3 < deg; j += 4) {
                int2 p0 = g_epk[start + j + 0];
                int2 p1 = g_epk[start + j + 1];
                int2 p2 = g_epk[start + j + 2];
                int2 p3 = g_epk[start + j + 3];

                uint4 kv0 = *(const uint4*)(g_KVh + (size_t)(p0.x & 0x1FFFF) * 256 + lane * 8);
                uint4 kv1 = *(const uint4*)(g_KVh + (size_t)(p1.x & 0x1FFFF) * 256 + lane * 8);
                uint4 kv2 = *(const uint4*)(g_KVh + (size_t)(p2.x & 0x1FFFF) * 256 + lane * 8);
                uint4 kv3 = *(const uint4*)(g_KVh + (size_t)(p3.x & 0x1FFFF) * 256 + lane * 8);

                int cb0 = (((p0.x >> 17) & 31) << 7) + lane * 4;
                int cb1 = (((p1.x >> 17) & 31) << 7) + lane * 4;
                int cb2 = (((p2.x >> 17) & 31) << 7) + lane * 4;
                int cb3 = (((p3.x >> 17) & 31) << 7) + lane * 4;

                float4 rk0 = *(float4*)(s_rqk + cb0);
                float4 rk1 = *(float4*)(s_rqk + cb1);
                float4 rk2 = *(float4*)(s_rqk + cb2);
                float4 rk3 = *(float4*)(s_rqk + cb3);

                __half2* h0 = (__half2*)&kv0;
                __half2* h1 = (__half2*)&kv1;
                __half2* h2 = (__half2*)&kv2;
                __half2* h3 = (__half2*)&kv3;

                float2 k0a = __half22float2(h0[0]), k0b = __half22float2(h0[1]);
                float2 k1a = __half22float2(h1[0]), k1b = __half22float2(h1[1]);
                float2 k2a = __half22float2(h2[0]), k2b = __half22float2(h2[1]);
                float2 k3a = __half22float2(h3[0]), k3b = __half22float2(h3[1]);

                float s0 = q4.x * k0a.x * rk0.x + q4.y * k0a.y * rk0.y
                         + q4.z * k0b.x * rk0.z + q4.w * k0b.y * rk0.w;
                float s1 = q4.x * k1a.x * rk1.x + q4.y * k1a.y * rk1.y
                         + q4.z * k1b.x * rk1.z + q4.w * k1b.y * rk1.w;
                float s2 = q4.x * k2a.x * rk2.x + q4.y * k2a.y * rk2.y
                         + q4.z * k2b.x * rk2.z + q4.w * k2b.y * rk2.w;
                float s3 = q4.x * k3a.x * rk3.x + q4.y * k3a.y * rk3.y
                         + q4.z * k3b.x * rk3.z + q4.w * k3b.y * rk3.w;

                s0 += __shfl_xor_sync(0xffffffffu, s0, 1);
                s1 += __shfl_xor_sync(0xffffffffu, s1, 1);
                s2 += __shfl_xor_sync(0xffffffffu, s2, 1);
                s3 += __shfl_xor_sync(0xffffffffu, s3, 1);
                s0 += __shfl_xor_sync(0xffffffffu, s0, 2);
                s1 += __shfl_xor_sync(0xffffffffu, s1, 2);
                s2 += __shfl_xor_sync(0xffffffffu, s2, 2);
                s3 += __shfl_xor_sync(0xffffffffu, s3, 2);

                float e0 = __expf(s0 * 0.25f + s_rb[((p0.x >> 22) & 7) * 8 + h] + __int_as_float(p0.y));
                float e1 = __expf(s1 * 0.25f + s_rb[((p1.x >> 22) & 7) * 8 + h] + __int_as_float(p1.y));
                float e2 = __expf(s2 * 0.25f + s_rb[((p2.x >> 22) & 7) * 8 + h] + __int_as_float(p2.y));
                float e3 = __expf(s3 * 0.25f + s_rb[((p3.x >> 22) & 7) * 8 + h] + __int_as_float(p3.y));
                z += (e0 + e1) + (e2 + e3);

                float4 rv0 = *(float4*)(s_rvv + cb0);
                float4 rv1 = *(float4*)(s_rvv + cb1);
                float4 rv2 = *(float4*)(s_rvv + cb2);
                float4 rv3 = *(float4*)(s_rvv + cb3);

                float2 v0a = __half22float2(h0[2]), v0b = __half22float2(h0[3]);
                float2 v1a = __half22float2(h1[2]), v1b = __half22float2(h1[3]);
                float2 v2a = __half22float2(h2[2]), v2b = __half22float2(h2[3]);
                float2 v3a = __half22float2(h3[2]), v3b = __half22float2(h3[3]);

                oa.x += v0a.x * rv0.x * e0 + v1a.x * rv1.x * e1
                      + v2a.x * rv2.x * e2 + v3a.x * rv3.x * e3;
                oa.y += v0a.y * rv0.y * e0 + v1a.y * rv1.y * e1
                      + v2a.y * rv2.y * e2 + v3a.y * rv3.y * e3;
                oa.z += v0b.x * rv0.z * e0 + v1b.x * rv1.z * e1
                      + v2b.x * rv2.z * e2 + v3b.x * rv3.z * e3;
                oa.w += v0b.y * rv0.w * e0 + v1b.y * rv1.w * e1
                      + v2b.y * rv2.w * e2 + v3b.y * rv3.w * e3;
            }
            for (; j < deg; ++j) {
                int2 p = g_epk[start + j];
                uint4 kv = *(const uint4*)(g_KVh + (size_t)(p.x & 0x1FFFF) * 256 + lane * 8);
                int cb = (((p.x >> 17) & 31) << 7) + lane * 4;
                float4 rk4 = *(float4*)(s_rqk + cb);
                float4 rv4 = *(float4*)(s_rvv + cb);

                __half2* hh = (__half2*)&kv;
                float2 k01 = __half22float2(hh[0]), k23 = __half22float2(hh[1]);
                float2 v01 = __half22float2(hh[2]), v23 = __half22float2(hh[3]);

                float sc = q4.x * k01.x * rk4.x + q4.y * k01.y * rk4.y
                         + q4.z * k23.x * rk4.z + q4.w * k23.y * rk4.w;
                sc += __shfl_xor_sync(0xffffffffu, sc, 1);
                sc += __shfl_xor_sync(0xffffffffu, sc, 2);

                float es = __expf(sc * 0.25f + s_rb[((p.x >> 22) & 7) * 8 + h] + __int_as_float(p.y));
                z += es;
                oa.x += v01.x * rv4.x * es;
                oa.y += v01.y * rv4.y * es;
                oa.z += v23.x * rv4.z * es;
                oa.w += v23.y * rv4.w * es;
            }

            int t = ntype[n];
            float a = 1.f / (1.f + __expf(-__ldg(skip + t)));
            float b = 1.f - a;
            float r = a / (z + 1e-9f);

            float4 xi = *(const float4*)(x + (size_t)n * 128 + lane * 4);
            float4 xv;
            xv.x = oa.x * r + b * xi.x;
            xv.y = oa.y * r + b * xi.y;
            xv.z = oa.z * r + b * xi.z;
            xv.w = oa.w * r + b * xi.w;

            float s = xv.x + xv.y + xv.z + xv.w;
            #pragma unroll
            for (int o = 16; o; o >>= 1) s += __shfl_xor_sync(0xffffffffu, s, o);
            float mu = s * (1.f / 128.f);

            float dx0 = xv.x - mu, dx1 = xv.y - mu, dx2 = xv.z - mu, dx3 = xv.w - mu;
            float vs = dx0 * dx0 + dx1 * dx1 + dx2 * dx2 + dx3 * dx3;
            #pragma unroll
            for (int o = 16; o; o >>= 1) vs += __shfl_xor_sync(0xffffffffu, vs, o);
            float rs = rsqrtf(vs * (1.f / 128.f) + 1e-5f);

            float4 g4 = *(const float4*)(gamma + t * 128 + lane * 4);
            float4 be4 = *(const float4*)(beta + t * 128 + lane * 4);

            float4 y;
            y.x = dx0 * rs * g4.x + be4.x;
            y.y = dx1 * rs * g4.y + be4.y;
            y.z = dx2 * rs * g4.z + be4.z;
            y.w = dx3 * rs * g4.w + be4.w;

            *(float4*)(out + (size_t)n * 128 + lane * 4) = y;
        }
    }
}

// ---------------- launch ----------------
extern "C" void kernel_launch(void* const* d_in, const int* in_sizes, int n_in,
                              void* d_out, int out_size)
{
    const float* node_inp   = (const float*)d_in[0];
    const int*   node_type  = (const int*)d_in[1];
    const int*   edge_index = (const int*)d_in[2];
    const int*   edge_type  = (const int*)d_in[3];
    const int*   edge_sign  = (const int*)d_in[4];
    const float* edge_dist  = (const float*)d_in[5];
    const float* Wq = (const float*)d_in[6];
    const float* bq = (const float*)d_in[7];
    const float* Wk = (const float*)d_in[8];
    const float* bk = (const float*)d_in[9];
    const float* Wv = (const float*)d_in[10];
    const float* bv = (const float*)d_in[11];
    const float* rel_q   = (const float*)d_in[12];
    const float* rel_k   = (const float*)d_in[13];
    const float* rel_v   = (const float*)d_in[14];
    const float* rel_b   = (const float*)d_in[15];
    const float* skf     = (const float*)d_in[16];
    const float* svf     = (const float*)d_in[17];
    const float* skn     = (const float*)d_in[18];
    const float* svn     = (const float*)d_in[19];
    const float* d_alpha = (const float*)d_in[20];
    const float* d_tau   = (const float*)d_in[21];
    const float* skip    = (const float*)d_in[22];
    const float* ln_g    = (const float*)d_in[23];
    const float* ln_b    = (const float*)d_in[24];

    int N = in_sizes[1];
    int E = in_sizes[3];

    float* out = (float*)d_out;

    cudaFuncSetAttribute(k_qkv_mma, cudaFuncAttributeMaxDynamicSharedMemorySize, SM_TOTAL);

    int nb = (N + 255) / 256;
    int eb = (E + 255) / 256;

    k_init<<<nb, 256>>>(N);
    k_histpack<<<eb + 72, 256>>>(node_type, edge_index, Wq, Wk, Wv,
                                 rel_q, rel_k, rel_v, skf, svf, skn, svn, N, E, eb);
    k_off<<<nb, 256>>>(node_type, N);

    int qb = (N + 127) / 128;
    k_qkv_mma<<<qb, 256, SM_TOTAL>>>(node_inp, node_type, bq, bk, bv, N);

    k_escatter<<<eb, 256>>>(edge_index, edge_type, edge_sign, edge_dist,
                            d_alpha, d_tau, E);

    k_attn<<<444, 256>>>(node_inp, node_type, rel_b, skip, ln_g, ln_b, out, N);
}